// round 1
// baseline (speedup 1.0000x reference)
#include <cuda_runtime.h>
#include <math.h>

#define Bb   32
#define Ss   512
#define Dd   512
#define Hh   8
#define Ff   2048
#define Ll   4
#define DH   64
#define Mrows (Bb*Ss)   // 16384

// ---------------- scratch (device globals; no runtime allocation) ----------------
__device__ float g_x   [Mrows*Dd];
__device__ float g_q   [Mrows*Dd];
__device__ float g_k   [Mrows*Dd];
__device__ float g_v   [Mrows*Dd];
__device__ float g_ctx [Mrows*Dd];
__device__ float g_attn[Mrows*Dd];
__device__ float g_tmp [Mrows*Dd];
__device__ float g_probs[(size_t)Bb*Hh*Ss*Ss];   // 256 MB
__device__ float g_ffn [(size_t)Mrows*Ff];       // 128 MB

__device__ __forceinline__ float gelu_exact(float x) {
    return 0.5f * x * (1.0f + erff(x * 0.70710678118654752f));
}

// ---------------- main GEMM: C[M,N] = A[M,K] @ W[K,N] + bias (+res) (gelu?) ------
// 128x128 block, BK=8, 256 threads, 8x8 per thread.
template<int ACT, bool HAS_RES>
__global__ void gemm_k(const float* __restrict__ A, const float* __restrict__ W,
                       const float* __restrict__ bias, const float* __restrict__ res,
                       float* __restrict__ C, int N, int K) {
    __shared__ float As[8][128];
    __shared__ float Ws[8][128];
    const int tid  = threadIdx.x;
    const int brow = blockIdx.y * 128;
    const int bcol = blockIdx.x * 128;
    const int tx = tid & 15, ty = tid >> 4;

    float acc[8][8];
    #pragma unroll
    for (int i = 0; i < 8; i++)
        #pragma unroll
        for (int j = 0; j < 8; j++) acc[i][j] = 0.0f;

    const int arow = tid >> 1, ac4 = (tid & 1) * 4;
    const int wrow = tid >> 5, wc4 = (tid & 31) * 4;
    const float* Aptr = A + (size_t)(brow + arow) * K + ac4;
    const float* Wptr = W + (size_t)wrow * N + bcol + wc4;

    for (int kt = 0; kt < K; kt += 8) {
        float4 a = *(const float4*)(Aptr + kt);
        float4 w = *(const float4*)(Wptr + (size_t)kt * N);
        As[ac4+0][arow] = a.x; As[ac4+1][arow] = a.y;
        As[ac4+2][arow] = a.z; As[ac4+3][arow] = a.w;
        *(float4*)&Ws[wrow][wc4] = w;
        __syncthreads();
        #pragma unroll
        for (int k = 0; k < 8; k++) {
            float ra[8], rb[8];
            *(float4*)(ra)   = *(const float4*)&As[k][ty*8];
            *(float4*)(ra+4) = *(const float4*)&As[k][ty*8+4];
            *(float4*)(rb)   = *(const float4*)&Ws[k][tx*8];
            *(float4*)(rb+4) = *(const float4*)&Ws[k][tx*8+4];
            #pragma unroll
            for (int i = 0; i < 8; i++)
                #pragma unroll
                for (int j = 0; j < 8; j++)
                    acc[i][j] += ra[i] * rb[j];
        }
        __syncthreads();
    }

    #pragma unroll
    for (int i = 0; i < 8; i++) {
        size_t r = (size_t)(brow + ty*8 + i);
        #pragma unroll
        for (int jj = 0; jj < 8; jj += 4) {
            int c = bcol + tx*8 + jj;
            float4 bv = *(const float4*)&bias[c];
            float4 o;
            o.x = acc[i][jj+0] + bv.x;
            o.y = acc[i][jj+1] + bv.y;
            o.z = acc[i][jj+2] + bv.z;
            o.w = acc[i][jj+3] + bv.w;
            if (HAS_RES) {
                float4 rv = *(const float4*)&res[r*N + c];
                o.x += rv.x; o.y += rv.y; o.z += rv.z; o.w += rv.w;
            }
            if (ACT == 1) {
                o.x = gelu_exact(o.x); o.y = gelu_exact(o.y);
                o.z = gelu_exact(o.z); o.w = gelu_exact(o.w);
            }
            *(float4*)&C[r*N + c] = o;
        }
    }
}

// ---------------- attention scores: scores[b,h,qi,ki] = (q.k)/scale + pbias ------
// grid (S/64, S/64, B*H), block 256, 4x4 per thread, K=64 fully in smem.
__global__ void scores_k(const float* __restrict__ q, const float* __restrict__ kk,
                         const float* __restrict__ pbias, const long long* __restrict__ ts,
                         float* __restrict__ scores) {
    const int bh = blockIdx.z;
    const int b  = bh / Hh, h = bh % Hh;
    const int qi0 = blockIdx.y * 64, ki0 = blockIdx.x * 64;
    __shared__ float Qs[64][64];
    __shared__ float Ks[64][64];
    const int tid = threadIdx.x;

    #pragma unroll
    for (int i = 0; i < 4; i++) {
        int idx = tid + i*256;
        int r = idx >> 4, c4 = (idx & 15) * 4;
        float4 qv = *(const float4*)&q [((size_t)(b*Ss + qi0 + r))*Dd + h*DH + c4];
        float4 kv = *(const float4*)&kk[((size_t)(b*Ss + ki0 + r))*Dd + h*DH + c4];
        Qs[c4+0][r]=qv.x; Qs[c4+1][r]=qv.y; Qs[c4+2][r]=qv.z; Qs[c4+3][r]=qv.w;
        Ks[c4+0][r]=kv.x; Ks[c4+1][r]=kv.y; Ks[c4+2][r]=kv.z; Ks[c4+3][r]=kv.w;
    }
    __syncthreads();

    const int tx = tid & 15, ty = tid >> 4;
    float acc[4][4];
    #pragma unroll
    for (int i=0;i<4;i++)
        #pragma unroll
        for (int j=0;j<4;j++) acc[i][j]=0.0f;

    #pragma unroll 8
    for (int k = 0; k < 64; k++) {
        float ra[4], rb[4];
        *(float4*)ra = *(const float4*)&Qs[k][ty*4];
        *(float4*)rb = *(const float4*)&Ks[k][tx*4];
        #pragma unroll
        for (int i = 0; i < 4; i++)
            #pragma unroll
            for (int j = 0; j < 4; j++)
                acc[i][j] += ra[i]*rb[j];
    }

    long long tq[4], tk[4];
    #pragma unroll
    for (int i = 0; i < 4; i++) tq[i] = ts[b*Ss + qi0 + ty*4 + i];
    #pragma unroll
    for (int j = 0; j < 4; j++) tk[j] = ts[b*Ss + ki0 + tx*4 + j];

    #pragma unroll
    for (int i = 0; i < 4; i++) {
        int qi = qi0 + ty*4 + i;
        float4 o;
        float* op = &o.x;
        #pragma unroll
        for (int j = 0; j < 4; j++) {
            int ki = ki0 + tx*4 + j;
            float lag = (float)(tq[i] - tk[j]) * (1.0f/60000.0f);
            float scale = 8.0f - 1.0f/(fmaxf(lag, 0.0f) + 1.0f) + 1.0f;
            float pb = pbias[((size_t)(h*Ss + qi))*Ss + ki];
            op[j] = acc[i][j] / scale + pb;
        }
        *(float4*)&scores[((size_t)bh*Ss + qi)*Ss + ki0 + tx*4] = o;
    }
}

// ---------------- softmax in place over last dim (512), one warp per row --------
__global__ void softmax_k(float* __restrict__ p) {
    const size_t row = (size_t)blockIdx.x * 8 + (threadIdx.x >> 5);
    const int lane = threadIdx.x & 31;
    float* pr = p + row * Ss;
    float v[16];
    float m = -1e30f;
    #pragma unroll
    for (int i = 0; i < 16; i++) { v[i] = pr[lane + i*32]; m = fmaxf(m, v[i]); }
    #pragma unroll
    for (int o = 16; o; o >>= 1) m = fmaxf(m, __shfl_xor_sync(0xffffffffu, m, o));
    float s = 0.0f;
    #pragma unroll
    for (int i = 0; i < 16; i++) { v[i] = __expf(v[i] - m); s += v[i]; }
    #pragma unroll
    for (int o = 16; o; o >>= 1) s += __shfl_xor_sync(0xffffffffu, s, o);
    float inv = 1.0f / s;
    #pragma unroll
    for (int i = 0; i < 16; i++) pr[lane + i*32] = v[i] * inv;
}

// ---------------- ctx: ctx[b,qi,h*64+dh] = sum_ki probs * v ---------------------
// grid (S/64, B*H), block 256, 4x4 per thread, K tiles of 16.
__global__ void ctx_k(const float* __restrict__ probs, const float* __restrict__ v,
                      float* __restrict__ ctx) {
    const int bh = blockIdx.y;
    const int b  = bh / Hh, h = bh % Hh;
    const int qi0 = blockIdx.x * 64;
    __shared__ float Ps[16][64];  // [ki][qi]
    __shared__ float Vs[16][64];  // [ki][dh]
    const int tid = threadIdx.x;
    const int tx = tid & 15, ty = tid >> 4;

    float acc[4][4];
    #pragma unroll
    for (int i=0;i<4;i++)
        #pragma unroll
        for (int j=0;j<4;j++) acc[i][j]=0.0f;

    const int pr = tid >> 2, pc4 = (tid & 3) * 4;
    const int vr = tid >> 4, vc4 = (tid & 15) * 4;

    for (int k0 = 0; k0 < Ss; k0 += 16) {
        float4 pv = *(const float4*)&probs[((size_t)bh*Ss + qi0 + pr)*Ss + k0 + pc4];
        Ps[pc4+0][pr]=pv.x; Ps[pc4+1][pr]=pv.y; Ps[pc4+2][pr]=pv.z; Ps[pc4+3][pr]=pv.w;
        *(float4*)&Vs[vr][vc4] = *(const float4*)&v[((size_t)(b*Ss + k0 + vr))*Dd + h*DH + vc4];
        __syncthreads();
        #pragma unroll
        for (int k = 0; k < 16; k++) {
            float ra[4], rb[4];
            *(float4*)ra = *(const float4*)&Ps[k][ty*4];
            *(float4*)rb = *(const float4*)&Vs[k][tx*4];
            #pragma unroll
            for (int i = 0; i < 4; i++)
                #pragma unroll
                for (int j = 0; j < 4; j++)
                    acc[i][j] += ra[i]*rb[j];
        }
        __syncthreads();
    }
    #pragma unroll
    for (int i = 0; i < 4; i++) {
        int qi = qi0 + ty*4 + i;
        *(float4*)&ctx[((size_t)(b*Ss + qi))*Dd + h*DH + tx*4] =
            make_float4(acc[i][0], acc[i][1], acc[i][2], acc[i][3]);
    }
}

// ---------------- LayerNorm over D=512, one block of 128 per row ----------------
__global__ void ln_k(const float* __restrict__ in, const float* __restrict__ g,
                     const float* __restrict__ bt, float* __restrict__ out) {
    const size_t row = blockIdx.x;
    const int tid = threadIdx.x;
    const int lane = tid & 31, wid = tid >> 5;
    __shared__ float red[4];
    float4 v = *(const float4*)&in[row*Dd + tid*4];

    float s = v.x + v.y + v.z + v.w;
    #pragma unroll
    for (int o = 16; o; o >>= 1) s += __shfl_xor_sync(0xffffffffu, s, o);
    if (lane == 0) red[wid] = s;
    __syncthreads();
    float mu = (red[0] + red[1] + red[2] + red[3]) * (1.0f/512.0f);
    __syncthreads();

    float dx = v.x - mu, dy = v.y - mu, dz = v.z - mu, dw = v.w - mu;
    float s2 = dx*dx + dy*dy + dz*dz + dw*dw;
    #pragma unroll
    for (int o = 16; o; o >>= 1) s2 += __shfl_xor_sync(0xffffffffu, s2, o);
    if (lane == 0) red[wid] = s2;
    __syncthreads();
    float var = (red[0] + red[1] + red[2] + red[3]) * (1.0f/512.0f);
    float inv = rsqrtf(var + 1e-12f);

    float4 gv = *(const float4*)&g [tid*4];
    float4 bv = *(const float4*)&bt[tid*4];
    float4 o;
    o.x = dx*inv*gv.x + bv.x;
    o.y = dy*inv*gv.y + bv.y;
    o.z = dz*inv*gv.z + bv.z;
    o.w = dw*inv*gv.w + bv.w;
    *(float4*)&out[row*Dd + tid*4] = o;
}

// --------------------------------- driver ---------------------------------------
extern "C" void kernel_launch(void* const* d_in, const int* in_sizes, int n_in,
                              void* d_out, int out_size) {
    const float*     hidden = (const float*)d_in[0];
    const float*     pbias  = (const float*)d_in[1];
    const long long* ts     = (const long long*)d_in[2];
    const float* Wq = (const float*)d_in[3];
    const float* bq = (const float*)d_in[4];
    const float* Wk = (const float*)d_in[5];
    const float* bk = (const float*)d_in[6];
    const float* Wv = (const float*)d_in[7];
    const float* bv = (const float*)d_in[8];
    const float* Wo = (const float*)d_in[9];
    const float* bo = (const float*)d_in[10];
    const float* l1g = (const float*)d_in[11];
    const float* l1b = (const float*)d_in[12];
    const float* Wi = (const float*)d_in[13];
    const float* bi = (const float*)d_in[14];
    const float* Wf = (const float*)d_in[15];
    const float* bf = (const float*)d_in[16];
    const float* l2g = (const float*)d_in[17];
    const float* l2b = (const float*)d_in[18];

    float *px, *pq, *pk, *pv, *pctx, *pattn, *ptmp, *pprobs, *pffn;
    cudaGetSymbolAddress((void**)&px,    g_x);
    cudaGetSymbolAddress((void**)&pq,    g_q);
    cudaGetSymbolAddress((void**)&pk,    g_k);
    cudaGetSymbolAddress((void**)&pv,    g_v);
    cudaGetSymbolAddress((void**)&pctx,  g_ctx);
    cudaGetSymbolAddress((void**)&pattn, g_attn);
    cudaGetSymbolAddress((void**)&ptmp,  g_tmp);
    cudaGetSymbolAddress((void**)&pprobs,g_probs);
    cudaGetSymbolAddress((void**)&pffn,  g_ffn);

    const dim3 gDD (Dd/128, Mrows/128);   // N=512 GEMMs
    const dim3 gDF (Ff/128, Mrows/128);   // N=2048 GEMM
    const dim3 gSc (Ss/64, Ss/64, Bb*Hh);
    const dim3 gCtx(Ss/64, Bb*Hh);

    const float* X = hidden;
    for (int l = 0; l < Ll; l++) {
        const float* wq = Wq + (size_t)l*Dd*Dd; const float* vbq = bq + l*Dd;
        const float* wk = Wk + (size_t)l*Dd*Dd; const float* vbk = bk + l*Dd;
        const float* wv = Wv + (size_t)l*Dd*Dd; const float* vbv = bv + l*Dd;
        const float* wo = Wo + (size_t)l*Dd*Dd; const float* vbo = bo + l*Dd;
        const float* wi = Wi + (size_t)l*Dd*Ff; const float* vbi = bi + l*Ff;
        const float* wf = Wf + (size_t)l*Ff*Dd; const float* vbf = bf + l*Dd;

        gemm_k<0,false><<<gDD, 256>>>(X, wq, vbq, nullptr, pq, Dd, Dd);
        gemm_k<0,false><<<gDD, 256>>>(X, wk, vbk, nullptr, pk, Dd, Dd);
        gemm_k<0,false><<<gDD, 256>>>(X, wv, vbv, nullptr, pv, Dd, Dd);

        scores_k<<<gSc, 256>>>(pq, pk, pbias, ts, pprobs);
        softmax_k<<<(Bb*Hh*Ss)/8, 256>>>(pprobs);
        ctx_k<<<gCtx, 256>>>(pprobs, pv, pctx);

        gemm_k<0,true><<<gDD, 256>>>(pctx, wo, vbo, X, ptmp, Dd, Dd);
        ln_k<<<Mrows, 128>>>(ptmp, l1g + l*Dd, l1b + l*Dd, pattn);

        gemm_k<1,false><<<gDF, 256>>>(pattn, wi, vbi, nullptr, pffn, Ff, Dd);
        gemm_k<0,true><<<gDD, 256>>>(pffn, wf, vbf, pattn, ptmp, Dd, Ff);
        ln_k<<<Mrows, 128>>>(ptmp, l2g + l*Dd, l2b + l*Dd, px);
        X = px;
    }

    cudaMemcpyAsync(d_out, px, (size_t)Mrows*Dd*sizeof(float),
                    cudaMemcpyDeviceToDevice, 0);
}

// round 2
// speedup vs baseline: 1.0012x; 1.0012x over previous
#include <cuda_runtime.h>
#include <math.h>

#define Bb   32
#define Ss   512
#define Dd   512
#define Hh   8
#define Ff   2048
#define Ll   4
#define DH   64
#define Mrows (Bb*Ss)   // 16384

// ---------------- scratch (device globals; no runtime allocation) ----------------
__device__ float g_x   [Mrows*Dd];
__device__ float g_q   [Mrows*Dd];
__device__ float g_k   [Mrows*Dd];
__device__ float g_v   [Mrows*Dd];
__device__ float g_ctx [Mrows*Dd];
__device__ float g_attn[Mrows*Dd];
__device__ float g_tmp [Mrows*Dd];
__device__ float g_probs[(size_t)Bb*Hh*Ss*Ss];   // 256 MB
__device__ float g_ffn [(size_t)Mrows*Ff];       // 128 MB

__device__ __forceinline__ float gelu_exact(float x) {
    return 0.5f * x * (1.0f + erff(x * 0.70710678118654752f));
}

// ---------------- main GEMM: C[M,N] = A[M,K] @ W[K,N] + bias (+res) (gelu?) ------
// 128x128 block, BK=8, 256 threads, 8x8 per thread.
template<int ACT, bool HAS_RES>
__global__ void gemm_k(const float* __restrict__ A, const float* __restrict__ W,
                       const float* __restrict__ bias, const float* __restrict__ res,
                       float* __restrict__ C, int N, int K) {
    __shared__ float As[8][128];
    __shared__ float Ws[8][128];
    const int tid  = threadIdx.x;
    const int brow = blockIdx.y * 128;
    const int bcol = blockIdx.x * 128;
    const int tx = tid & 15, ty = tid >> 4;

    float acc[8][8];
    #pragma unroll
    for (int i = 0; i < 8; i++)
        #pragma unroll
        for (int j = 0; j < 8; j++) acc[i][j] = 0.0f;

    const int arow = tid >> 1, ac4 = (tid & 1) * 4;
    const int wrow = tid >> 5, wc4 = (tid & 31) * 4;
    const float* Aptr = A + (size_t)(brow + arow) * K + ac4;
    const float* Wptr = W + (size_t)wrow * N + bcol + wc4;

    for (int kt = 0; kt < K; kt += 8) {
        float4 a = *(const float4*)(Aptr + kt);
        float4 w = *(const float4*)(Wptr + (size_t)kt * N);
        As[ac4+0][arow] = a.x; As[ac4+1][arow] = a.y;
        As[ac4+2][arow] = a.z; As[ac4+3][arow] = a.w;
        *(float4*)&Ws[wrow][wc4] = w;
        __syncthreads();
        #pragma unroll
        for (int k = 0; k < 8; k++) {
            float ra[8], rb[8];
            *(float4*)(ra)   = *(const float4*)&As[k][ty*8];
            *(float4*)(ra+4) = *(const float4*)&As[k][ty*8+4];
            *(float4*)(rb)   = *(const float4*)&Ws[k][tx*8];
            *(float4*)(rb+4) = *(const float4*)&Ws[k][tx*8+4];
            #pragma unroll
            for (int i = 0; i < 8; i++)
                #pragma unroll
                for (int j = 0; j < 8; j++)
                    acc[i][j] += ra[i] * rb[j];
        }
        __syncthreads();
    }

    #pragma unroll
    for (int i = 0; i < 8; i++) {
        size_t r = (size_t)(brow + ty*8 + i);
        #pragma unroll
        for (int jj = 0; jj < 8; jj += 4) {
            int c = bcol + tx*8 + jj;
            float4 bv = *(const float4*)&bias[c];
            float4 o;
            o.x = acc[i][jj+0] + bv.x;
            o.y = acc[i][jj+1] + bv.y;
            o.z = acc[i][jj+2] + bv.z;
            o.w = acc[i][jj+3] + bv.w;
            if (HAS_RES) {
                float4 rv = *(const float4*)&res[r*N + c];
                o.x += rv.x; o.y += rv.y; o.z += rv.z; o.w += rv.w;
            }
            if (ACT == 1) {
                o.x = gelu_exact(o.x); o.y = gelu_exact(o.y);
                o.z = gelu_exact(o.z); o.w = gelu_exact(o.w);
            }
            *(float4*)&C[r*N + c] = o;
        }
    }
}

// ---------------- attention scores: scores[b,h,qi,ki] = (q.k)/scale + pbias ------
// grid (S/64, S/64, B*H), block 256, 4x4 per thread, K=64 fully in smem.
__global__ void scores_k(const float* __restrict__ q, const float* __restrict__ kk,
                         const float* __restrict__ pbias, const long long* __restrict__ ts,
                         float* __restrict__ scores) {
    const int bh = blockIdx.z;
    const int b  = bh / Hh, h = bh % Hh;
    const int qi0 = blockIdx.y * 64, ki0 = blockIdx.x * 64;
    __shared__ float Qs[64][64];
    __shared__ float Ks[64][64];
    const int tid = threadIdx.x;

    #pragma unroll
    for (int i = 0; i < 4; i++) {
        int idx = tid + i*256;
        int r = idx >> 4, c4 = (idx & 15) * 4;
        float4 qv = *(const float4*)&q [((size_t)(b*Ss + qi0 + r))*Dd + h*DH + c4];
        float4 kv = *(const float4*)&kk[((size_t)(b*Ss + ki0 + r))*Dd + h*DH + c4];
        Qs[c4+0][r]=qv.x; Qs[c4+1][r]=qv.y; Qs[c4+2][r]=qv.z; Qs[c4+3][r]=qv.w;
        Ks[c4+0][r]=kv.x; Ks[c4+1][r]=kv.y; Ks[c4+2][r]=kv.z; Ks[c4+3][r]=kv.w;
    }
    __syncthreads();

    const int tx = tid & 15, ty = tid >> 4;
    float acc[4][4];
    #pragma unroll
    for (int i=0;i<4;i++)
        #pragma unroll
        for (int j=0;j<4;j++) acc[i][j]=0.0f;

    #pragma unroll 8
    for (int k = 0; k < 64; k++) {
        float ra[4], rb[4];
        *(float4*)ra = *(const float4*)&Qs[k][ty*4];
        *(float4*)rb = *(const float4*)&Ks[k][tx*4];
        #pragma unroll
        for (int i = 0; i < 4; i++)
            #pragma unroll
            for (int j = 0; j < 4; j++)
                acc[i][j] += ra[i]*rb[j];
    }

    long long tq[4], tk[4];
    #pragma unroll
    for (int i = 0; i < 4; i++) tq[i] = ts[b*Ss + qi0 + ty*4 + i];
    #pragma unroll
    for (int j = 0; j < 4; j++) tk[j] = ts[b*Ss + ki0 + tx*4 + j];

    #pragma unroll
    for (int i = 0; i < 4; i++) {
        int qi = qi0 + ty*4 + i;
        float4 o;
        float* op = &o.x;
        #pragma unroll
        for (int j = 0; j < 4; j++) {
            int ki = ki0 + tx*4 + j;
            float lag = (float)(tq[i] - tk[j]) * (1.0f/60000.0f);
            float scale = 8.0f - 1.0f/(fmaxf(lag, 0.0f) + 1.0f) + 1.0f;
            float pb = pbias[((size_t)(h*Ss + qi))*Ss + ki];
            op[j] = acc[i][j] / scale + pb;
        }
        *(float4*)&scores[((size_t)bh*Ss + qi)*Ss + ki0 + tx*4] = o;
    }
}

// ---------------- softmax in place over last dim (512), one warp per row --------
__global__ void softmax_k(float* __restrict__ p) {
    const size_t row = (size_t)blockIdx.x * 8 + (threadIdx.x >> 5);
    const int lane = threadIdx.x & 31;
    float* pr = p + row * Ss;
    float v[16];
    float m = -1e30f;
    #pragma unroll
    for (int i = 0; i < 16; i++) { v[i] = pr[lane + i*32]; m = fmaxf(m, v[i]); }
    #pragma unroll
    for (int o = 16; o; o >>= 1) m = fmaxf(m, __shfl_xor_sync(0xffffffffu, m, o));
    float s = 0.0f;
    #pragma unroll
    for (int i = 0; i < 16; i++) { v[i] = __expf(v[i] - m); s += v[i]; }
    #pragma unroll
    for (int o = 16; o; o >>= 1) s += __shfl_xor_sync(0xffffffffu, s, o);
    float inv = 1.0f / s;
    #pragma unroll
    for (int i = 0; i < 16; i++) pr[lane + i*32] = v[i] * inv;
}

// ---------------- ctx: ctx[b,qi,h*64+dh] = sum_ki probs * v ---------------------
// grid (S/64, B*H), block 256, 4x4 per thread, K tiles of 16.
__global__ void ctx_k(const float* __restrict__ probs, const float* __restrict__ v,
                      float* __restrict__ ctx) {
    const int bh = blockIdx.y;
    const int b  = bh / Hh, h = bh % Hh;
    const int qi0 = blockIdx.x * 64;
    __shared__ float Ps[16][64];  // [ki][qi]
    __shared__ float Vs[16][64];  // [ki][dh]
    const int tid = threadIdx.x;
    const int tx = tid & 15, ty = tid >> 4;

    float acc[4][4];
    #pragma unroll
    for (int i=0;i<4;i++)
        #pragma unroll
        for (int j=0;j<4;j++) acc[i][j]=0.0f;

    const int pr = tid >> 2, pc4 = (tid & 3) * 4;
    const int vr = tid >> 4, vc4 = (tid & 15) * 4;

    for (int k0 = 0; k0 < Ss; k0 += 16) {
        float4 pv = *(const float4*)&probs[((size_t)bh*Ss + qi0 + pr)*Ss + k0 + pc4];
        Ps[pc4+0][pr]=pv.x; Ps[pc4+1][pr]=pv.y; Ps[pc4+2][pr]=pv.z; Ps[pc4+3][pr]=pv.w;
        *(float4*)&Vs[vr][vc4] = *(const float4*)&v[((size_t)(b*Ss + k0 + vr))*Dd + h*DH + vc4];
        __syncthreads();
        #pragma unroll
        for (int k = 0; k < 16; k++) {
            float ra[4], rb[4];
            *(float4*)ra = *(const float4*)&Ps[k][ty*4];
            *(float4*)rb = *(const float4*)&Vs[k][tx*4];
            #pragma unroll
            for (int i = 0; i < 4; i++)
                #pragma unroll
                for (int j = 0; j < 4; j++)
                    acc[i][j] += ra[i]*rb[j];
        }
        __syncthreads();
    }
    #pragma unroll
    for (int i = 0; i < 4; i++) {
        int qi = qi0 + ty*4 + i;
        *(float4*)&ctx[((size_t)(b*Ss + qi))*Dd + h*DH + tx*4] =
            make_float4(acc[i][0], acc[i][1], acc[i][2], acc[i][3]);
    }
}

// ---------------- LayerNorm over D=512, one block of 128 per row ----------------
__global__ void ln_k(const float* __restrict__ in, const float* __restrict__ g,
                     const float* __restrict__ bt, float* __restrict__ out) {
    const size_t row = blockIdx.x;
    const int tid = threadIdx.x;
    const int lane = tid & 31, wid = tid >> 5;
    __shared__ float red[4];
    float4 v = *(const float4*)&in[row*Dd + tid*4];

    float s = v.x + v.y + v.z + v.w;
    #pragma unroll
    for (int o = 16; o; o >>= 1) s += __shfl_xor_sync(0xffffffffu, s, o);
    if (lane == 0) red[wid] = s;
    __syncthreads();
    float mu = (red[0] + red[1] + red[2] + red[3]) * (1.0f/512.0f);
    __syncthreads();

    float dx = v.x - mu, dy = v.y - mu, dz = v.z - mu, dw = v.w - mu;
    float s2 = dx*dx + dy*dy + dz*dz + dw*dw;
    #pragma unroll
    for (int o = 16; o; o >>= 1) s2 += __shfl_xor_sync(0xffffffffu, s2, o);
    if (lane == 0) red[wid] = s2;
    __syncthreads();
    float var = (red[0] + red[1] + red[2] + red[3]) * (1.0f/512.0f);
    float inv = rsqrtf(var + 1e-12f);

    float4 gv = *(const float4*)&g [tid*4];
    float4 bv = *(const float4*)&bt[tid*4];
    float4 o;
    o.x = dx*inv*gv.x + bv.x;
    o.y = dy*inv*gv.y + bv.y;
    o.z = dz*inv*gv.z + bv.z;
    o.w = dw*inv*gv.w + bv.w;
    *(float4*)&out[row*Dd + tid*4] = o;
}

// --------------------------------- driver ---------------------------------------
extern "C" void kernel_launch(void* const* d_in, const int* in_sizes, int n_in,
                              void* d_out, int out_size) {
    const float*     hidden = (const float*)d_in[0];
    const float*     pbias  = (const float*)d_in[1];
    const long long* ts     = (const long long*)d_in[2];
    const float* Wq = (const float*)d_in[3];
    const float* bq = (const float*)d_in[4];
    const float* Wk = (const float*)d_in[5];
    const float* bk = (const float*)d_in[6];
    const float* Wv = (const float*)d_in[7];
    const float* bv = (const float*)d_in[8];
    const float* Wo = (const float*)d_in[9];
    const float* bo = (const float*)d_in[10];
    const float* l1g = (const float*)d_in[11];
    const float* l1b = (const float*)d_in[12];
    const float* Wi = (const float*)d_in[13];
    const float* bi = (const float*)d_in[14];
    const float* Wf = (const float*)d_in[15];
    const float* bf = (const float*)d_in[16];
    const float* l2g = (const float*)d_in[17];
    const float* l2b = (const float*)d_in[18];

    float *px, *pq, *pk, *pv, *pctx, *pattn, *ptmp, *pprobs, *pffn;
    cudaGetSymbolAddress((void**)&px,    g_x);
    cudaGetSymbolAddress((void**)&pq,    g_q);
    cudaGetSymbolAddress((void**)&pk,    g_k);
    cudaGetSymbolAddress((void**)&pv,    g_v);
    cudaGetSymbolAddress((void**)&pctx,  g_ctx);
    cudaGetSymbolAddress((void**)&pattn, g_attn);
    cudaGetSymbolAddress((void**)&ptmp,  g_tmp);
    cudaGetSymbolAddress((void**)&pprobs,g_probs);
    cudaGetSymbolAddress((void**)&pffn,  g_ffn);

    const dim3 gDD (Dd/128, Mrows/128);   // N=512 GEMMs
    const dim3 gDF (Ff/128, Mrows/128);   // N=2048 GEMM
    const dim3 gSc (Ss/64, Ss/64, Bb*Hh);
    const dim3 gCtx(Ss/64, Bb*Hh);

    const float* X = hidden;
    for (int l = 0; l < Ll; l++) {
        const float* wq = Wq + (size_t)l*Dd*Dd; const float* vbq = bq + l*Dd;
        const float* wk = Wk + (size_t)l*Dd*Dd; const float* vbk = bk + l*Dd;
        const float* wv = Wv + (size_t)l*Dd*Dd; const float* vbv = bv + l*Dd;
        const float* wo = Wo + (size_t)l*Dd*Dd; const float* vbo = bo + l*Dd;
        const float* wi = Wi + (size_t)l*Dd*Ff; const float* vbi = bi + l*Ff;
        const float* wf = Wf + (size_t)l*Ff*Dd; const float* vbf = bf + l*Dd;

        gemm_k<0,false><<<gDD, 256>>>(X, wq, vbq, nullptr, pq, Dd, Dd);
        gemm_k<0,false><<<gDD, 256>>>(X, wk, vbk, nullptr, pk, Dd, Dd);
        gemm_k<0,false><<<gDD, 256>>>(X, wv, vbv, nullptr, pv, Dd, Dd);

        scores_k<<<gSc, 256>>>(pq, pk, pbias, ts, pprobs);
        softmax_k<<<(Bb*Hh*Ss)/8, 256>>>(pprobs);
        ctx_k<<<gCtx, 256>>>(pprobs, pv, pctx);

        gemm_k<0,true><<<gDD, 256>>>(pctx, wo, vbo, X, ptmp, Dd, Dd);
        ln_k<<<Mrows, 128>>>(ptmp, l1g + l*Dd, l1b + l*Dd, pattn);

        gemm_k<1,false><<<gDF, 256>>>(pattn, wi, vbi, nullptr, pffn, Ff, Dd);
        gemm_k<0,true><<<gDD, 256>>>(pffn, wf, vbf, pattn, ptmp, Dd, Ff);
        ln_k<<<Mrows, 128>>>(ptmp, l2g + l*Dd, l2b + l*Dd, px);
        X = px;
    }

    cudaMemcpyAsync(d_out, px, (size_t)Mrows*Dd*sizeof(float),
                    cudaMemcpyDeviceToDevice, 0);
}

// round 4
// speedup vs baseline: 1.6855x; 1.6834x over previous
#include <cuda_runtime.h>
#include <cuda_bf16.h>
#include <math.h>
#include <stdint.h>

#define Bb 32
#define Ss 512
#define Dd 512
#define Hh 8
#define Ff 2048
#define Ll 4
#define DH 64
#define Mrows (Bb*Ss)

__device__ float g_x[Mrows*Dd];
__device__ float g_q[Mrows*Dd];
__device__ float g_k[Mrows*Dd];
__device__ float g_v[Mrows*Dd];
__device__ float g_ctx[Mrows*Dd];
__device__ float g_attn[Mrows*Dd];
__device__ float g_tmp[Mrows*Dd];
__device__ float g_probs[(size_t)Bb*Hh*Ss*Ss];
__device__ float g_ffn[(size_t)Mrows*Ff];
__device__ __nv_bfloat16 g_ahi[(size_t)Mrows*Ff];
__device__ __nv_bfloat16 g_alo[(size_t)Mrows*Ff];
__device__ __nv_bfloat16 g_wh[(size_t)Ll*(4*Dd*Dd + 2*Dd*Ff)];
__device__ __nv_bfloat16 g_wl[(size_t)Ll*(4*Dd*Dd + 2*Dd*Ff)];

__device__ __forceinline__ float gelu_e(float x){return 0.5f*x*(1.0f+erff(x*0.70710678118654752f));}

__device__ __forceinline__ void cp16(uint32_t d, const void* s){
    asm volatile("cp.async.cg.shared.global [%0], [%1], 16;"::"r"(d),"l"(s));
}
#define CPC() asm volatile("cp.async.commit_group;":::"memory")
#define LDSM4(r0,r1,r2,r3,a) asm volatile("ldmatrix.sync.aligned.m8n8.x4.shared.b16 {%0,%1,%2,%3},[%4];":"=r"(r0),"=r"(r1),"=r"(r2),"=r"(r3):"r"(a))
#define MMA(d,a,b0,b1) asm volatile( \
    "mma.sync.aligned.m16n8k16.row.col.f32.bf16.bf16.f32 {%0,%1,%2,%3},{%4,%5,%6,%7},{%8,%9},{%0,%1,%2,%3};" \
    :"+f"((d)[0]),"+f"((d)[1]),"+f"((d)[2]),"+f"((d)[3]) \
    :"r"((a)[0]),"r"((a)[1]),"r"((a)[2]),"r"((a)[3]),"r"(b0),"r"(b1))

// ---- bf16x2-split tensor GEMM: C[M,N]=(Ahi+Alo)@Bt^T + bias (+res)(gelu) ----
// Bt=[N,K] K-contig. CTA 128x128, BK=32, 256 thr (8 warps: 2M x 4N, warp 64x32).
#define STB2 32768
#define GSMEM (2*STB2)

__device__ __forceinline__ void load_stage(uint32_t st,int tid,
    const __nv_bfloat16* Ah,const __nv_bfloat16* Al,
    const __nv_bfloat16* Bh,const __nv_bfloat16* Bl,
    int m0,int n0,int k0,int K){
    #pragma unroll
    for(int i=0;i<8;i++){
        int id=i*256+tid;
        int reg=id>>9, rid=id&511, row=rid>>2, c=rid&3;
        const __nv_bfloat16* src;
        if(reg==0)      src=Ah+(size_t)(m0+row)*K+k0+c*8;
        else if(reg==1) src=Al+(size_t)(m0+row)*K+k0+c*8;
        else if(reg==2) src=Bh+(size_t)(n0+row)*K+k0+c*8;
        else            src=Bl+(size_t)(n0+row)*K+k0+c*8;
        uint32_t dst=st+reg*8192+row*64+((c^((row>>1)&3))*16);
        cp16(dst,src);
    }
    CPC();
}

template<int ACT, bool RES>
__global__ void __launch_bounds__(256,1)
gemm_mma(const __nv_bfloat16* __restrict__ Ah,const __nv_bfloat16* __restrict__ Al,
         const __nv_bfloat16* __restrict__ Bh,const __nv_bfloat16* __restrict__ Bl,
         const float* __restrict__ bias,const float* __restrict__ res,
         float* __restrict__ C,int N,int K){
    extern __shared__ char sm[];
    uint32_t sb=(uint32_t)__cvta_generic_to_shared(sm);
    const int tid=threadIdx.x, wid=tid>>5, lane=tid&31;
    const int n0=blockIdx.x*128, m0=blockIdx.y*128;
    const int wm=(wid>>2)*64, wn=(wid&3)*32;
    const int chunks=K>>5;

    float acc[4][4][4];
    #pragma unroll
    for(int i=0;i<4;i++)
        #pragma unroll
        for(int j=0;j<4;j++)
            #pragma unroll
            for(int t=0;t<4;t++)acc[i][j][t]=0.0f;

    load_stage(sb,      tid,Ah,Al,Bh,Bl,m0,n0,0, K);
    load_stage(sb+STB2, tid,Ah,Al,Bh,Bl,m0,n0,32,K);

    // per-lane ldmatrix row/halves
    const int arow=lane&15, ah8=lane>>4;     // A/B x4: rows 0..15, 16B-half
    for(int c=0;c<chunks;c++){
        uint32_t st=sb+(c&1)*STB2;
        if(c+2<chunks) asm volatile("cp.async.wait_group 1;":::"memory");
        else           asm volatile("cp.async.wait_group 0;":::"memory");
        __syncthreads();

        #pragma unroll
        for(int s=0;s<2;s++){
            uint32_t ahf[4][4], alf[4][4], bhf[2][4], blf[2][4];
            #pragma unroll
            for(int mi=0;mi<4;mi++){
                int row=wm+mi*16+arow;
                uint32_t co=((s*2+ah8)^((row>>1)&3))*16;
                uint32_t ad=st+row*64+co;
                LDSM4(ahf[mi][0],ahf[mi][1],ahf[mi][2],ahf[mi][3],ad);
                LDSM4(alf[mi][0],alf[mi][1],alf[mi][2],alf[mi][3],ad+8192);
            }
            #pragma unroll
            for(int nq=0;nq<2;nq++){
                int row=wn+nq*16+arow;
                uint32_t co=((s*2+ah8)^((row>>1)&3))*16;
                uint32_t ad=st+16384+row*64+co;
                LDSM4(bhf[nq][0],bhf[nq][1],bhf[nq][2],bhf[nq][3],ad);
                LDSM4(blf[nq][0],blf[nq][1],blf[nq][2],blf[nq][3],ad+8192);
            }
            #pragma unroll
            for(int mi=0;mi<4;mi++)
                #pragma unroll
                for(int nq=0;nq<2;nq++)
                    #pragma unroll
                    for(int p=0;p<2;p++){
                        int nt=nq*2+p;
                        MMA(acc[mi][nt],ahf[mi],bhf[nq][p],bhf[nq][p+2]);
                        MMA(acc[mi][nt],ahf[mi],blf[nq][p],blf[nq][p+2]);
                        MMA(acc[mi][nt],alf[mi],bhf[nq][p],bhf[nq][p+2]);
                    }
        }
        __syncthreads();
        if(c+2<chunks)
            load_stage(sb+(c&1)*STB2,tid,Ah,Al,Bh,Bl,m0,n0,(c+2)*32,K);
    }

    // epilogue
    const int r4=lane>>2, c2=(lane&3)*2;
    #pragma unroll
    for(int mi=0;mi<4;mi++){
        #pragma unroll
        for(int nt=0;nt<4;nt++){
            int col=n0+wn+nt*8+c2;
            float2 bv=*(const float2*)&bias[col];
            #pragma unroll
            for(int hrow=0;hrow<2;hrow++){
                int row=m0+wm+mi*16+r4+hrow*8;
                float2 o;
                o.x=acc[mi][nt][hrow*2+0]+bv.x;
                o.y=acc[mi][nt][hrow*2+1]+bv.y;
                if(RES){
                    float2 rv=*(const float2*)&res[(size_t)row*N+col];
                    o.x+=rv.x;o.y+=rv.y;
                }
                if(ACT==1){o.x=gelu_e(o.x);o.y=gelu_e(o.y);}
                *(float2*)&C[(size_t)row*N+col]=o;
            }
        }
    }
}

__global__ void split_k(const float* __restrict__ s,__nv_bfloat16* __restrict__ hi,
                        __nv_bfloat16* __restrict__ lo,int n4){
    int i=blockIdx.x*256+threadIdx.x;
    if(i>=n4)return;
    float4 v=((const float4*)s)[i];
    __nv_bfloat16 h0=__float2bfloat16(v.x),h1=__float2bfloat16(v.y),h2=__float2bfloat16(v.z),h3=__float2bfloat16(v.w);
    ((__nv_bfloat162*)hi)[i*2+0]=__halves2bfloat162(h0,h1);
    ((__nv_bfloat162*)hi)[i*2+1]=__halves2bfloat162(h2,h3);
    ((__nv_bfloat162*)lo)[i*2+0]=__halves2bfloat162(__float2bfloat16(v.x-__bfloat162float(h0)),__float2bfloat16(v.y-__bfloat162float(h1)));
    ((__nv_bfloat162*)lo)[i*2+1]=__halves2bfloat162(__float2bfloat16(v.z-__bfloat162float(h2)),__float2bfloat16(v.w-__bfloat162float(h3)));
}

__global__ void tsplit_k(const float* __restrict__ W,__nv_bfloat16* __restrict__ hi,
                         __nv_bfloat16* __restrict__ lo,int K,int N){
    __shared__ float t[32][33];
    int n=blockIdx.x*32+threadIdx.x, k0=blockIdx.y*32;
    for(int j=threadIdx.y;j<32;j+=8) t[j][threadIdx.x]=W[(size_t)(k0+j)*N+n];
    __syncthreads();
    int k=k0+threadIdx.x, n0=blockIdx.x*32;
    for(int j=threadIdx.y;j<32;j+=8){
        float v=t[threadIdx.x][j];
        __nv_bfloat16 h=__float2bfloat16(v);
        hi[(size_t)(n0+j)*K+k]=h;
        lo[(size_t)(n0+j)*K+k]=__float2bfloat16(v-__bfloat162float(h));
    }
}

__global__ void scores_k(const float* __restrict__ q,const float* __restrict__ kk,
                         const float* __restrict__ pbias,const long long* __restrict__ ts,
                         float* __restrict__ scores){
    const int bh=blockIdx.z, b=bh/Hh, h=bh%Hh;
    const int qi0=blockIdx.y*64, ki0=blockIdx.x*64;
    __shared__ float Qs[64][64], Ks[64][64];
    const int tid=threadIdx.x;
    #pragma unroll
    for(int i=0;i<4;i++){
        int idx=tid+i*256, r=idx>>4, c4=(idx&15)*4;
        float4 qv=*(const float4*)&q [((size_t)(b*Ss+qi0+r))*Dd+h*DH+c4];
        float4 kv=*(const float4*)&kk[((size_t)(b*Ss+ki0+r))*Dd+h*DH+c4];
        Qs[c4+0][r]=qv.x;Qs[c4+1][r]=qv.y;Qs[c4+2][r]=qv.z;Qs[c4+3][r]=qv.w;
        Ks[c4+0][r]=kv.x;Ks[c4+1][r]=kv.y;Ks[c4+2][r]=kv.z;Ks[c4+3][r]=kv.w;
    }
    __syncthreads();
    const int tx=tid&15, ty=tid>>4;
    float acc[4][4];
    #pragma unroll
    for(int i=0;i<4;i++)
        #pragma unroll
        for(int j=0;j<4;j++)acc[i][j]=0.0f;
    #pragma unroll 8
    for(int k=0;k<64;k++){
        float ra[4],rb[4];
        *(float4*)ra=*(const float4*)&Qs[k][ty*4];
        *(float4*)rb=*(const float4*)&Ks[k][tx*4];
        #pragma unroll
        for(int i=0;i<4;i++)
            #pragma unroll
            for(int j=0;j<4;j++)acc[i][j]+=ra[i]*rb[j];
    }
    long long tq[4],tk[4];
    #pragma unroll
    for(int i=0;i<4;i++)tq[i]=ts[b*Ss+qi0+ty*4+i];
    #pragma unroll
    for(int j=0;j<4;j++)tk[j]=ts[b*Ss+ki0+tx*4+j];
    #pragma unroll
    for(int i=0;i<4;i++){
        int qi=qi0+ty*4+i;
        float4 o; float* op=&o.x;
        #pragma unroll
        for(int j=0;j<4;j++){
            float lag=(float)(tq[i]-tk[j])*(1.0f/60000.0f);
            float scale=9.0f-1.0f/(fmaxf(lag,0.0f)+1.0f);
            op[j]=acc[i][j]/scale+pbias[((size_t)(h*Ss+qi))*Ss+ki0+tx*4+j];
        }
        *(float4*)&scores[((size_t)bh*Ss+qi)*Ss+ki0+tx*4]=o;
    }
}

__global__ void softmax_k(float* __restrict__ p){
    const size_t row=(size_t)blockIdx.x*8+(threadIdx.x>>5);
    const int lane=threadIdx.x&31;
    float* pr=p+row*Ss;
    float v[16], m=-1e30f;
    #pragma unroll
    for(int i=0;i<16;i++){v[i]=pr[lane+i*32];m=fmaxf(m,v[i]);}
    #pragma unroll
    for(int o=16;o;o>>=1)m=fmaxf(m,__shfl_xor_sync(0xffffffffu,m,o));
    float s=0.0f;
    #pragma unroll
    for(int i=0;i<16;i++){v[i]=__expf(v[i]-m);s+=v[i];}
    #pragma unroll
    for(int o=16;o;o>>=1)s+=__shfl_xor_sync(0xffffffffu,s,o);
    float inv=1.0f/s;
    #pragma unroll
    for(int i=0;i<16;i++)pr[lane+i*32]=v[i]*inv;
}

__global__ void ctx_k(const float* __restrict__ probs,const float* __restrict__ v,
                      float* __restrict__ ctx){
    const int bh=blockIdx.y, b=bh/Hh, h=bh%Hh;
    const int qi0=blockIdx.x*64;
    __shared__ float Ps[16][64], Vs[16][64];
    const int tid=threadIdx.x, tx=tid&15, ty=tid>>4;
    float acc[4][4];
    #pragma unroll
    for(int i=0;i<4;i++)
        #pragma unroll
        for(int j=0;j<4;j++)acc[i][j]=0.0f;
    const int pr=tid>>2, pc4=(tid&3)*4, vr=tid>>4, vc4=(tid&15)*4;
    for(int k0=0;k0<Ss;k0+=16){
        float4 pv=*(const float4*)&probs[((size_t)bh*Ss+qi0+pr)*Ss+k0+pc4];
        Ps[pc4+0][pr]=pv.x;Ps[pc4+1][pr]=pv.y;Ps[pc4+2][pr]=pv.z;Ps[pc4+3][pr]=pv.w;
        *(float4*)&Vs[vr][vc4]=*(const float4*)&v[((size_t)(b*Ss+k0+vr))*Dd+h*DH+vc4];
        __syncthreads();
        #pragma unroll
        for(int k=0;k<16;k++){
            float ra[4],rb[4];
            *(float4*)ra=*(const float4*)&Ps[k][ty*4];
            *(float4*)rb=*(const float4*)&Vs[k][tx*4];
            #pragma unroll
            for(int i=0;i<4;i++)
                #pragma unroll
                for(int j=0;j<4;j++)acc[i][j]+=ra[i]*rb[j];
        }
        __syncthreads();
    }
    #pragma unroll
    for(int i=0;i<4;i++){
        int qi=qi0+ty*4+i;
        *(float4*)&ctx[((size_t)(b*Ss+qi))*Dd+h*DH+tx*4]=
            make_float4(acc[i][0],acc[i][1],acc[i][2],acc[i][3]);
    }
}

__global__ void ln_k(const float* __restrict__ in,const float* __restrict__ g,
                     const float* __restrict__ bt,float* __restrict__ out){
    const size_t row=blockIdx.x;
    const int tid=threadIdx.x, lane=tid&31, wid=tid>>5;
    __shared__ float red[4];
    float4 v=*(const float4*)&in[row*Dd+tid*4];
    float s=v.x+v.y+v.z+v.w;
    #pragma unroll
    for(int o=16;o;o>>=1)s+=__shfl_xor_sync(0xffffffffu,s,o);
    if(lane==0)red[wid]=s;
    __syncthreads();
    float mu=(red[0]+red[1]+red[2]+red[3])*(1.0f/512.0f);
    __syncthreads();
    float dx=v.x-mu,dy=v.y-mu,dz=v.z-mu,dw=v.w-mu;
    float s2=dx*dx+dy*dy+dz*dz+dw*dw;
    #pragma unroll
    for(int o=16;o;o>>=1)s2+=__shfl_xor_sync(0xffffffffu,s2,o);
    if(lane==0)red[wid]=s2;
    __syncthreads();
    float var=(red[0]+red[1]+red[2]+red[3])*(1.0f/512.0f);
    float inv=rsqrtf(var+1e-12f);
    float4 gv=*(const float4*)&g[tid*4];
    float4 bv=*(const float4*)&bt[tid*4];
    float4 o;
    o.x=dx*inv*gv.x+bv.x; o.y=dy*inv*gv.y+bv.y;
    o.z=dz*inv*gv.z+bv.z; o.w=dw*inv*gv.w+bv.w;
    *(float4*)&out[row*Dd+tid*4]=o;
}

extern "C" void kernel_launch(void* const* d_in, const int* in_sizes, int n_in,
                              void* d_out, int out_size){
    const float* hidden=(const float*)d_in[0];
    const float* pbias=(const float*)d_in[1];
    const long long* ts=(const long long*)d_in[2];
    const float* Wq=(const float*)d_in[3];  const float* bq=(const float*)d_in[4];
    const float* Wk=(const float*)d_in[5];  const float* bk=(const float*)d_in[6];
    const float* Wv=(const float*)d_in[7];  const float* bv=(const float*)d_in[8];
    const float* Wo=(const float*)d_in[9];  const float* bo=(const float*)d_in[10];
    const float* l1g=(const float*)d_in[11];const float* l1b=(const float*)d_in[12];
    const float* Wi=(const float*)d_in[13]; const float* bi=(const float*)d_in[14];
    const float* Wf=(const float*)d_in[15]; const float* bfp=(const float*)d_in[16];
    const float* l2g=(const float*)d_in[17];const float* l2b=(const float*)d_in[18];

    float *px,*pq,*pk,*pv,*pctx,*pattn,*ptmp,*pprobs,*pffn;
    cudaGetSymbolAddress((void**)&px,g_x);     cudaGetSymbolAddress((void**)&pq,g_q);
    cudaGetSymbolAddress((void**)&pk,g_k);     cudaGetSymbolAddress((void**)&pv,g_v);
    cudaGetSymbolAddress((void**)&pctx,g_ctx); cudaGetSymbolAddress((void**)&pattn,g_attn);
    cudaGetSymbolAddress((void**)&ptmp,g_tmp); cudaGetSymbolAddress((void**)&pprobs,g_probs);
    cudaGetSymbolAddress((void**)&pffn,g_ffn);
    __nv_bfloat16 *ahi,*alo,*wh,*wl;
    cudaGetSymbolAddress((void**)&ahi,g_ahi);  cudaGetSymbolAddress((void**)&alo,g_alo);
    cudaGetSymbolAddress((void**)&wh,g_wh);    cudaGetSymbolAddress((void**)&wl,g_wl);

    cudaFuncSetAttribute(gemm_mma<0,false>,cudaFuncAttributeMaxDynamicSharedMemorySize,GSMEM);
    cudaFuncSetAttribute(gemm_mma<0,true>, cudaFuncAttributeMaxDynamicSharedMemorySize,GSMEM);
    cudaFuncSetAttribute(gemm_mma<1,false>,cudaFuncAttributeMaxDynamicSharedMemorySize,GSMEM);

    const size_t LW=(size_t)(4*Dd*Dd+2*Dd*Ff);
    for(int l=0;l<Ll;l++){
        __nv_bfloat16* bh_=wh+l*LW; __nv_bfloat16* bl_=wl+l*LW;
        dim3 tb(32,8);
        tsplit_k<<<dim3(Dd/32,Dd/32),tb>>>(Wq+(size_t)l*Dd*Dd,bh_,         bl_,         Dd,Dd);
        tsplit_k<<<dim3(Dd/32,Dd/32),tb>>>(Wk+(size_t)l*Dd*Dd,bh_+Dd*Dd,   bl_+Dd*Dd,   Dd,Dd);
        tsplit_k<<<dim3(Dd/32,Dd/32),tb>>>(Wv+(size_t)l*Dd*Dd,bh_+2*Dd*Dd, bl_+2*Dd*Dd, Dd,Dd);
        tsplit_k<<<dim3(Dd/32,Dd/32),tb>>>(Wo+(size_t)l*Dd*Dd,bh_+3*Dd*Dd, bl_+3*Dd*Dd, Dd,Dd);
        tsplit_k<<<dim3(Ff/32,Dd/32),tb>>>(Wi+(size_t)l*Dd*Ff,bh_+4*Dd*Dd, bl_+4*Dd*Dd, Dd,Ff);
        tsplit_k<<<dim3(Dd/32,Ff/32),tb>>>(Wf+(size_t)l*Ff*Dd,bh_+4*Dd*Dd+(size_t)Dd*Ff,bl_+4*Dd*Dd+(size_t)Dd*Ff,Ff,Dd);
    }

    const dim3 gDD(Dd/128,Mrows/128), gDF(Ff/128,Mrows/128);
    const dim3 gSc(Ss/64,Ss/64,Bb*Hh), gCtx(Ss/64,Bb*Hh);
    const int nD4=Mrows*Dd/4, nF4=Mrows*Ff/4;

    const float* X=hidden;
    for(int l=0;l<Ll;l++){
        __nv_bfloat16* bh_=wh+l*LW; __nv_bfloat16* bl_=wl+l*LW;
        __nv_bfloat16* wih=bh_+4*Dd*Dd; __nv_bfloat16* wil=bl_+4*Dd*Dd;
        __nv_bfloat16* wfh=wih+(size_t)Dd*Ff; __nv_bfloat16* wfl=wil+(size_t)Dd*Ff;

        split_k<<<(nD4+255)/256,256>>>(X,ahi,alo,nD4);
        gemm_mma<0,false><<<gDD,256,GSMEM>>>(ahi,alo,bh_,         bl_,         bq+l*Dd,nullptr,pq,Dd,Dd);
        gemm_mma<0,false><<<gDD,256,GSMEM>>>(ahi,alo,bh_+Dd*Dd,   bl_+Dd*Dd,   bk+l*Dd,nullptr,pk,Dd,Dd);
        gemm_mma<0,false><<<gDD,256,GSMEM>>>(ahi,alo,bh_+2*Dd*Dd, bl_+2*Dd*Dd, bv+l*Dd,nullptr,pv,Dd,Dd);

        scores_k<<<gSc,256>>>(pq,pk,pbias,ts,pprobs);
        softmax_k<<<(Bb*Hh*Ss)/8,256>>>(pprobs);
        ctx_k<<<gCtx,256>>>(pprobs,pv,pctx);

        split_k<<<(nD4+255)/256,256>>>(pctx,ahi,alo,nD4);
        gemm_mma<0,true><<<gDD,256,GSMEM>>>(ahi,alo,bh_+3*Dd*Dd,bl_+3*Dd*Dd,bo+l*Dd,X,ptmp,Dd,Dd);
        ln_k<<<Mrows,128>>>(ptmp,l1g+l*Dd,l1b+l*Dd,pattn);

        split_k<<<(nD4+255)/256,256>>>(pattn,ahi,alo,nD4);
        gemm_mma<1,false><<<gDF,256,GSMEM>>>(ahi,alo,wih,wil,bi+l*Ff,nullptr,pffn,Ff,Dd);

        split_k<<<(nF4+255)/256,256>>>(pffn,ahi,alo,nF4);
        gemm_mma<0,true><<<gDD,256,GSMEM>>>(ahi,alo,wfh,wfl,bfp+l*Dd,pattn,ptmp,Dd,Ff);
        ln_k<<<Mrows,128>>>(ptmp,l2g+l*Dd,l2b+l*Dd,px);
        X=px;
    }
    cudaMemcpyAsync(d_out,px,(size_t)Mrows*Dd*sizeof(float),cudaMemcpyDeviceToDevice,0);
}

// round 5
// speedup vs baseline: 1.8971x; 1.1256x over previous
#include <cuda_runtime.h>
#include <cuda_bf16.h>
#include <math.h>
#include <stdint.h>

#define Bb 32
#define Ss 512
#define Dd 512
#define Hh 8
#define Ff 2048
#define Ll 4
#define DH 64
#define Mrows (Bb*Ss)
#define BHSS ((size_t)Bb*Hh*Ss*Ss)

typedef __nv_bfloat16 bf16;
typedef __nv_bfloat162 bf162;

__device__ float g_x[Mrows*Dd];
__device__ float g_attn[Mrows*Dd];
__device__ float g_tmp[Mrows*Dd];
__device__ float g_probs[BHSS];
__device__ bf16 g_xh[Mrows*Dd], g_xl[Mrows*Dd];
__device__ bf16 g_qh[Mrows*Dd], g_ql[Mrows*Dd];
__device__ bf16 g_kh[Mrows*Dd], g_kl[Mrows*Dd];
__device__ bf16 g_vth[Mrows*Dd], g_vtl[Mrows*Dd];
__device__ bf16 g_ch[Mrows*Dd], g_cl[Mrows*Dd];
__device__ bf16 g_ah[Mrows*Dd], g_al[Mrows*Dd];
__device__ bf16 g_fh[(size_t)Mrows*Ff], g_fl[(size_t)Mrows*Ff];
__device__ bf16 g_ph[BHSS], g_pl[BHSS];
__device__ bf16 g_wh[(size_t)Ll*(4*Dd*Dd+2*Dd*Ff)];
__device__ bf16 g_wl[(size_t)Ll*(4*Dd*Dd+2*Dd*Ff)];

__device__ __forceinline__ float gelu_e(float x){return 0.5f*x*(1.0f+erff(x*0.70710678118654752f));}
__device__ __forceinline__ void cp16(uint32_t d,const void* s){
    asm volatile("cp.async.cg.shared.global [%0], [%1], 16;"::"r"(d),"l"(s));
}
#define CPC() asm volatile("cp.async.commit_group;":::"memory")
#define LDSM4(r0,r1,r2,r3,a) asm volatile("ldmatrix.sync.aligned.m8n8.x4.shared.b16 {%0,%1,%2,%3},[%4];":"=r"(r0),"=r"(r1),"=r"(r2),"=r"(r3):"r"(a))
#define MMA(d,a,b0,b1) asm volatile( \
    "mma.sync.aligned.m16n8k16.row.col.f32.bf16.bf16.f32 {%0,%1,%2,%3},{%4,%5,%6,%7},{%8,%9},{%0,%1,%2,%3};" \
    :"+f"((d)[0]),"+f"((d)[1]),"+f"((d)[2]),"+f"((d)[3]) \
    :"r"((a)[0]),"r"((a)[1]),"r"((a)[2]),"r"((a)[3]),"r"(b0),"r"(b1))

__device__ __forceinline__ void wsplit(float v, bf16& h, bf16& l){
    h=__float2bfloat16(v); l=__float2bfloat16(v-__bfloat162float(h));
}

// ======================= projection/FFN GEMM (proven R4 core) ====================
#define STB2 32768
#define GSMEM (2*STB2)
__device__ __forceinline__ void load_stage(uint32_t st,int tid,
    const bf16* Ah,const bf16* Al,const bf16* Bh,const bf16* Bl,
    int m0,int n0,int k0,int K){
    #pragma unroll
    for(int i=0;i<8;i++){
        int id=i*256+tid;
        int reg=id>>9, rid=id&511, row=rid>>2, c=rid&3;
        const bf16* src;
        if(reg==0)      src=Ah+(size_t)(m0+row)*K+k0+c*8;
        else if(reg==1) src=Al+(size_t)(m0+row)*K+k0+c*8;
        else if(reg==2) src=Bh+(size_t)(n0+row)*K+k0+c*8;
        else            src=Bl+(size_t)(n0+row)*K+k0+c*8;
        cp16(st+reg*8192+row*64+((c^((row>>1)&3))*16),src);
    }
    CPC();
}

// OUT: 0=fp32 C, 1=bf16 hi/lo same layout, 2=bf16 hi/lo transposed-per-head (V)
template<int ACT, bool RES, int OUT>
__global__ void __launch_bounds__(256,1)
gemm_mma(const bf16* __restrict__ Ah,const bf16* __restrict__ Al,
         const bf16* __restrict__ Bh,const bf16* __restrict__ Bl,
         const float* __restrict__ bias,const float* __restrict__ res,
         float* __restrict__ C,bf16* __restrict__ Ch,bf16* __restrict__ Cl,
         int N,int K){
    extern __shared__ char sm[];
    uint32_t sb=(uint32_t)__cvta_generic_to_shared(sm);
    const int tid=threadIdx.x, wid=tid>>5, lane=tid&31;
    const int n0=blockIdx.x*128, m0=blockIdx.y*128;
    const int wm=(wid>>2)*64, wn=(wid&3)*32;
    const int chunks=K>>5;
    float acc[4][4][4];
    #pragma unroll
    for(int i=0;i<4;i++)
        #pragma unroll
        for(int j=0;j<4;j++){acc[i][j][0]=0;acc[i][j][1]=0;acc[i][j][2]=0;acc[i][j][3]=0;}
    load_stage(sb,tid,Ah,Al,Bh,Bl,m0,n0,0,K);
    load_stage(sb+STB2,tid,Ah,Al,Bh,Bl,m0,n0,32,K);
    const int arow=lane&15, ah8=lane>>4;
    for(int c=0;c<chunks;c++){
        uint32_t st=sb+(c&1)*STB2;
        if(c+2<chunks) asm volatile("cp.async.wait_group 1;":::"memory");
        else           asm volatile("cp.async.wait_group 0;":::"memory");
        __syncthreads();
        #pragma unroll
        for(int s=0;s<2;s++){
            uint32_t ahf[4][4],alf[4][4],bhf[2][4],blf[2][4];
            #pragma unroll
            for(int mi=0;mi<4;mi++){
                int row=wm+mi*16+arow;
                uint32_t ad=st+row*64+(((s*2+ah8)^((row>>1)&3))*16);
                LDSM4(ahf[mi][0],ahf[mi][1],ahf[mi][2],ahf[mi][3],ad);
                LDSM4(alf[mi][0],alf[mi][1],alf[mi][2],alf[mi][3],ad+8192);
            }
            #pragma unroll
            for(int nq=0;nq<2;nq++){
                int row=wn+nq*16+arow;
                uint32_t ad=st+16384+row*64+(((s*2+ah8)^((row>>1)&3))*16);
                LDSM4(bhf[nq][0],bhf[nq][1],bhf[nq][2],bhf[nq][3],ad);
                LDSM4(blf[nq][0],blf[nq][1],blf[nq][2],blf[nq][3],ad+8192);
            }
            #pragma unroll
            for(int mi=0;mi<4;mi++)
                #pragma unroll
                for(int nq=0;nq<2;nq++)
                    #pragma unroll
                    for(int p=0;p<2;p++){
                        int nt=nq*2+p;
                        MMA(acc[mi][nt],ahf[mi],bhf[nq][p],bhf[nq][p+2]);
                        MMA(acc[mi][nt],ahf[mi],blf[nq][p],blf[nq][p+2]);
                        MMA(acc[mi][nt],alf[mi],bhf[nq][p],bhf[nq][p+2]);
                    }
        }
        __syncthreads();
        if(c+2<chunks) load_stage(sb+(c&1)*STB2,tid,Ah,Al,Bh,Bl,m0,n0,(c+2)*32,K);
    }
    const int r4=lane>>2, c2=(lane&3)*2;
    #pragma unroll
    for(int mi=0;mi<4;mi++)
        #pragma unroll
        for(int nt=0;nt<4;nt++){
            int col=n0+wn+nt*8+c2;
            float2 bv=*(const float2*)&bias[col];
            #pragma unroll
            for(int hr=0;hr<2;hr++){
                int row=m0+wm+mi*16+r4+hr*8;
                float2 o;
                o.x=acc[mi][nt][hr*2+0]+bv.x;
                o.y=acc[mi][nt][hr*2+1]+bv.y;
                if(RES){float2 rv=*(const float2*)&res[(size_t)row*N+col]; o.x+=rv.x;o.y+=rv.y;}
                if(ACT==1){o.x=gelu_e(o.x);o.y=gelu_e(o.y);}
                if(OUT==0){
                    *(float2*)&C[(size_t)row*N+col]=o;
                }else if(OUT==1){
                    bf16 h0,l0,h1,l1; wsplit(o.x,h0,l0); wsplit(o.y,h1,l1);
                    *(bf162*)&Ch[(size_t)row*N+col]=__halves2bfloat162(h0,h1);
                    *(bf162*)&Cl[(size_t)row*N+col]=__halves2bfloat162(l0,l1);
                }else{
                    bf16 h0,l0,h1,l1; wsplit(o.x,h0,l0); wsplit(o.y,h1,l1);
                    int bb=row>>9, sl=row&511, hh=col>>6, dh=col&63;
                    size_t base=((size_t)((bb*Hh+hh)*64+dh))*512+sl;
                    Ch[base]=h0; Cl[base]=l0; Ch[base+512]=h1; Cl[base+512]=l1;
                }
            }
        }
}

// ================= scores: S = Q@K^T /scale + pbias (per b,h) ====================
// CTA 128q x 128k, K=64 resident. smem 64KB. Same warp layout as gemm_mma.
#define SCSM 65536
__global__ void __launch_bounds__(256,1)
scores_mma(const bf16* __restrict__ Qh,const bf16* __restrict__ Ql,
           const bf16* __restrict__ Kh,const bf16* __restrict__ Kl,
           const float* __restrict__ pbias,const long long* __restrict__ ts,
           float* __restrict__ scores){
    extern __shared__ char sm[];
    uint32_t sb=(uint32_t)__cvta_generic_to_shared(sm);
    const int tid=threadIdx.x, wid=tid>>5, lane=tid&31;
    const int bh=blockIdx.z, b=bh>>3, h=bh&7;
    const int m0=blockIdx.y*128, n0=blockIdx.x*128;
    const int wm=(wid>>2)*64, wn=(wid&3)*32;
    // load Qh/Ql/Kh/Kl tiles: 4 arrays x 128 rows x 128B
    #pragma unroll
    for(int i=0;i<16;i++){
        int id=i*256+tid;
        int reg=id>>10, rid=id&1023, row=rid>>3, c=rid&7;
        const bf16* base=(reg==0)?Qh:(reg==1)?Ql:(reg==2)?Kh:Kl;
        int r0=(reg<2)?m0:n0;
        cp16(sb+reg*16384+row*128+((c^(row&7))*16),
             base+((size_t)(b*Ss+r0+row))*Dd+h*DH+c*8);
    }
    CPC();
    asm volatile("cp.async.wait_group 0;":::"memory");
    __syncthreads();

    float acc[4][4][4];
    #pragma unroll
    for(int i=0;i<4;i++)
        #pragma unroll
        for(int j=0;j<4;j++){acc[i][j][0]=0;acc[i][j][1]=0;acc[i][j][2]=0;acc[i][j][3]=0;}
    const int arow=lane&15, ah8=lane>>4;
    #pragma unroll
    for(int s=0;s<4;s++){
        uint32_t ahf[4][4],alf[4][4],bhf[2][4],blf[2][4];
        #pragma unroll
        for(int mi=0;mi<4;mi++){
            int row=wm+mi*16+arow;
            uint32_t ad=sb+row*128+((((s*2+ah8))^(row&7))*16);
            LDSM4(ahf[mi][0],ahf[mi][1],ahf[mi][2],ahf[mi][3],ad);
            LDSM4(alf[mi][0],alf[mi][1],alf[mi][2],alf[mi][3],ad+16384);
        }
        #pragma unroll
        for(int nq=0;nq<2;nq++){
            int row=wn+nq*16+arow;
            uint32_t ad=sb+32768+row*128+((((s*2+ah8))^(row&7))*16);
            LDSM4(bhf[nq][0],bhf[nq][1],bhf[nq][2],bhf[nq][3],ad);
            LDSM4(blf[nq][0],blf[nq][1],blf[nq][2],blf[nq][3],ad+16384);
        }
        #pragma unroll
        for(int mi=0;mi<4;mi++)
            #pragma unroll
            for(int nq=0;nq<2;nq++)
                #pragma unroll
                for(int p=0;p<2;p++){
                    int nt=nq*2+p;
                    MMA(acc[mi][nt],ahf[mi],bhf[nq][p],bhf[nq][p+2]);
                    MMA(acc[mi][nt],ahf[mi],blf[nq][p],blf[nq][p+2]);
                    MMA(acc[mi][nt],alf[mi],bhf[nq][p],bhf[nq][p+2]);
                }
    }
    const int r4=lane>>2, c2=(lane&3)*2;
    #pragma unroll
    for(int mi=0;mi<4;mi++)
        #pragma unroll
        for(int nt=0;nt<4;nt++){
            int kc=n0+wn+nt*8+c2;
            long long tk0=ts[b*Ss+kc], tk1=ts[b*Ss+kc+1];
            #pragma unroll
            for(int hr=0;hr<2;hr++){
                int qi=m0+wm+mi*16+r4+hr*8;
                long long tq=ts[b*Ss+qi];
                float2 pb=*(const float2*)&pbias[((size_t)(h*Ss+qi))*Ss+kc];
                float l0=(float)(tq-tk0)*(1.0f/60000.0f);
                float l1=(float)(tq-tk1)*(1.0f/60000.0f);
                float s0=9.0f-1.0f/(fmaxf(l0,0.0f)+1.0f);
                float s1=9.0f-1.0f/(fmaxf(l1,0.0f)+1.0f);
                float2 o;
                o.x=acc[mi][nt][hr*2+0]/s0+pb.x;
                o.y=acc[mi][nt][hr*2+1]/s1+pb.y;
                *(float2*)&scores[((size_t)bh*Ss+qi)*Ss+kc]=o;
            }
        }
}

// ============== softmax: fp32 in -> bf16 hi/lo out =============================
__global__ void softmax_k(const float* __restrict__ p, bf16* __restrict__ ph,
                          bf16* __restrict__ pl){
    const size_t row=(size_t)blockIdx.x*8+(threadIdx.x>>5);
    const int lane=threadIdx.x&31;
    const float* pr=p+row*Ss;
    float v[16], m=-1e30f;
    #pragma unroll
    for(int i=0;i<16;i++){v[i]=pr[lane*16+i];m=fmaxf(m,v[i]);}
    #pragma unroll
    for(int o=16;o;o>>=1)m=fmaxf(m,__shfl_xor_sync(0xffffffffu,m,o));
    float s=0.0f;
    #pragma unroll
    for(int i=0;i<16;i++){v[i]=__expf(v[i]-m);s+=v[i];}
    #pragma unroll
    for(int o=16;o;o>>=1)s+=__shfl_xor_sync(0xffffffffu,s,o);
    float inv=1.0f/s;
    bf16 hb[16], lb[16];
    #pragma unroll
    for(int i=0;i<16;i++){float pv=v[i]*inv; wsplit(pv,hb[i],lb[i]);}
    #pragma unroll
    for(int i=0;i<8;i++){
        ((bf162*)(ph+row*Ss+lane*16))[i]=__halves2bfloat162(hb[2*i],hb[2*i+1]);
        ((bf162*)(pl+row*Ss+lane*16))[i]=__halves2bfloat162(lb[2*i],lb[2*i+1]);
    }
}

// ================= ctx: C = P@V (per b,h), out bf16 hi/lo [s,d] ==================
// CTA 128q x 64dh, BK=32, 2-stage. smem 48KB. 8 warps: 4M x 2N (warp 32x32).
#define CTST 24576
#define CTSM (2*CTST)
__global__ void __launch_bounds__(256,1)
ctx_mma(const bf16* __restrict__ Ph,const bf16* __restrict__ Pl,
        const bf16* __restrict__ Vh,const bf16* __restrict__ Vl,
        bf16* __restrict__ Ch,bf16* __restrict__ Cl){
    extern __shared__ char sm[];
    uint32_t sb=(uint32_t)__cvta_generic_to_shared(sm);
    const int tid=threadIdx.x, wid=tid>>5, lane=tid&31;
    const int bh=blockIdx.y, b=bh>>3, h=bh&7;
    const int m0=blockIdx.x*128;
    const int wm=(wid>>1)*32, wn=(wid&1)*32;
    float acc[2][4][4];
    #pragma unroll
    for(int i=0;i<2;i++)
        #pragma unroll
        for(int j=0;j<4;j++){acc[i][j][0]=0;acc[i][j][1]=0;acc[i][j][2]=0;acc[i][j][3]=0;}

    auto load=[&](uint32_t st,int k0){
        #pragma unroll
        for(int i=0;i<6;i++){
            int id=i*256+tid;
            const bf16* src; uint32_t off; int row,c;
            if(id<1024){
                int reg=id>>9; row=(id&511)>>2; c=id&3;
                src=(reg?Pl:Ph)+((size_t)(bh*Ss+m0+row))*Ss+k0+c*8;
                off=reg*8192;
            }else{
                int id2=id-1024; int reg=id2>>8; row=(id2&255)>>2; c=id2&3;
                src=(reg?Vl:Vh)+((size_t)(bh*64+row))*Ss+k0+c*8;
                off=16384+reg*4096;
            }
            cp16(st+off+row*64+((c^((row>>1)&3))*16),src);
        }
        CPC();
    };
    load(sb,0); load(sb+CTST,32);
    const int arow=lane&15, ah8=lane>>4;
    for(int c=0;c<16;c++){
        uint32_t st=sb+(c&1)*CTST;
        if(c+2<16) asm volatile("cp.async.wait_group 1;":::"memory");
        else       asm volatile("cp.async.wait_group 0;":::"memory");
        __syncthreads();
        #pragma unroll
        for(int s=0;s<2;s++){
            uint32_t ahf[2][4],alf[2][4],bhf[2][4],blf[2][4];
            #pragma unroll
            for(int mi=0;mi<2;mi++){
                int row=wm+mi*16+arow;
                uint32_t ad=st+row*64+(((s*2+ah8)^((row>>1)&3))*16);
                LDSM4(ahf[mi][0],ahf[mi][1],ahf[mi][2],ahf[mi][3],ad);
                LDSM4(alf[mi][0],alf[mi][1],alf[mi][2],alf[mi][3],ad+8192);
            }
            #pragma unroll
            for(int nq=0;nq<2;nq++){
                int row=wn+nq*16+arow;
                uint32_t ad=st+16384+row*64+(((s*2+ah8)^((row>>1)&3))*16);
                LDSM4(bhf[nq][0],bhf[nq][1],bhf[nq][2],bhf[nq][3],ad);
                LDSM4(blf[nq][0],blf[nq][1],blf[nq][2],blf[nq][3],ad+4096);
            }
            #pragma unroll
            for(int mi=0;mi<2;mi++)
                #pragma unroll
                for(int nq=0;nq<2;nq++)
                    #pragma unroll
                    for(int p=0;p<2;p++){
                        int nt=nq*2+p;
                        MMA(acc[mi][nt],ahf[mi],bhf[nq][p],bhf[nq][p+2]);
                        MMA(acc[mi][nt],ahf[mi],blf[nq][p],blf[nq][p+2]);
                        MMA(acc[mi][nt],alf[mi],bhf[nq][p],bhf[nq][p+2]);
                    }
        }
        __syncthreads();
        if(c+2<16) load(sb+(c&1)*CTST,(c+2)*32);
    }
    const int r4=lane>>2, c2=(lane&3)*2;
    #pragma unroll
    for(int mi=0;mi<2;mi++)
        #pragma unroll
        for(int nt=0;nt<4;nt++){
            int dh=wn+nt*8+c2;
            #pragma unroll
            for(int hr=0;hr<2;hr++){
                int si=m0+wm+mi*16+r4+hr*8;
                float ox=acc[mi][nt][hr*2+0], oy=acc[mi][nt][hr*2+1];
                bf16 h0,l0,h1,l1; wsplit(ox,h0,l0); wsplit(oy,h1,l1);
                size_t idx=((size_t)(b*Ss+si))*Dd+h*DH+dh;
                *(bf162*)&Ch[idx]=__halves2bfloat162(h0,h1);
                *(bf162*)&Cl[idx]=__halves2bfloat162(l0,l1);
            }
        }
}

// ================= LayerNorm: fp32 out + bf16 hi/lo out ========================
__global__ void ln_k(const float* __restrict__ in,const float* __restrict__ g,
                     const float* __restrict__ bt,float* __restrict__ out,
                     bf16* __restrict__ oh,bf16* __restrict__ ol){
    const size_t row=blockIdx.x;
    const int tid=threadIdx.x, lane=tid&31, wid=tid>>5;
    __shared__ float red[4];
    float4 v=*(const float4*)&in[row*Dd+tid*4];
    float s=v.x+v.y+v.z+v.w;
    #pragma unroll
    for(int o=16;o;o>>=1)s+=__shfl_xor_sync(0xffffffffu,s,o);
    if(lane==0)red[wid]=s;
    __syncthreads();
    float mu=(red[0]+red[1]+red[2]+red[3])*(1.0f/512.0f);
    __syncthreads();
    float dx=v.x-mu,dy=v.y-mu,dz=v.z-mu,dw=v.w-mu;
    float s2=dx*dx+dy*dy+dz*dz+dw*dw;
    #pragma unroll
    for(int o=16;o;o>>=1)s2+=__shfl_xor_sync(0xffffffffu,s2,o);
    if(lane==0)red[wid]=s2;
    __syncthreads();
    float var=(red[0]+red[1]+red[2]+red[3])*(1.0f/512.0f);
    float inv=rsqrtf(var+1e-12f);
    float4 gv=*(const float4*)&g[tid*4];
    float4 bv=*(const float4*)&bt[tid*4];
    float4 o;
    o.x=dx*inv*gv.x+bv.x; o.y=dy*inv*gv.y+bv.y;
    o.z=dz*inv*gv.z+bv.z; o.w=dw*inv*gv.w+bv.w;
    *(float4*)&out[row*Dd+tid*4]=o;
    bf16 h0,l0,h1,l1,h2,l2,h3,l3;
    wsplit(o.x,h0,l0);wsplit(o.y,h1,l1);wsplit(o.z,h2,l2);wsplit(o.w,h3,l3);
    ((bf162*)(oh+row*Dd+tid*4))[0]=__halves2bfloat162(h0,h1);
    ((bf162*)(oh+row*Dd+tid*4))[1]=__halves2bfloat162(h2,h3);
    ((bf162*)(ol+row*Dd+tid*4))[0]=__halves2bfloat162(l0,l1);
    ((bf162*)(ol+row*Dd+tid*4))[1]=__halves2bfloat162(l2,l3);
}

__global__ void split_k(const float* __restrict__ s,bf16* __restrict__ hi,
                        bf16* __restrict__ lo,int n4){
    int i=blockIdx.x*256+threadIdx.x;
    if(i>=n4)return;
    float4 v=((const float4*)s)[i];
    bf16 h0,l0,h1,l1,h2,l2,h3,l3;
    wsplit(v.x,h0,l0);wsplit(v.y,h1,l1);wsplit(v.z,h2,l2);wsplit(v.w,h3,l3);
    ((bf162*)hi)[i*2+0]=__halves2bfloat162(h0,h1);
    ((bf162*)hi)[i*2+1]=__halves2bfloat162(h2,h3);
    ((bf162*)lo)[i*2+0]=__halves2bfloat162(l0,l1);
    ((bf162*)lo)[i*2+1]=__halves2bfloat162(l2,l3);
}

__global__ void tsplit_k(const float* __restrict__ W,bf16* __restrict__ hi,
                         bf16* __restrict__ lo,int K,int N){
    __shared__ float t[32][33];
    int n=blockIdx.x*32+threadIdx.x, k0=blockIdx.y*32;
    for(int j=threadIdx.y;j<32;j+=8) t[j][threadIdx.x]=W[(size_t)(k0+j)*N+n];
    __syncthreads();
    int k=k0+threadIdx.x, n0=blockIdx.x*32;
    for(int j=threadIdx.y;j<32;j+=8){
        float v=t[threadIdx.x][j];
        bf16 h,l; wsplit(v,h,l);
        hi[(size_t)(n0+j)*K+k]=h;
        lo[(size_t)(n0+j)*K+k]=l;
    }
}

extern "C" void kernel_launch(void* const* d_in, const int* in_sizes, int n_in,
                              void* d_out, int out_size){
    const float* hidden=(const float*)d_in[0];
    const float* pbias=(const float*)d_in[1];
    const long long* ts=(const long long*)d_in[2];
    const float* Wq=(const float*)d_in[3];  const float* bq=(const float*)d_in[4];
    const float* Wk=(const float*)d_in[5];  const float* bk=(const float*)d_in[6];
    const float* Wv=(const float*)d_in[7];  const float* bv=(const float*)d_in[8];
    const float* Wo=(const float*)d_in[9];  const float* bo=(const float*)d_in[10];
    const float* l1g=(const float*)d_in[11];const float* l1b=(const float*)d_in[12];
    const float* Wi=(const float*)d_in[13]; const float* bi=(const float*)d_in[14];
    const float* Wf=(const float*)d_in[15]; const float* bfp=(const float*)d_in[16];
    const float* l2g=(const float*)d_in[17];const float* l2b=(const float*)d_in[18];

    float *px,*pattn,*ptmp,*pprobs;
    cudaGetSymbolAddress((void**)&px,g_x);       cudaGetSymbolAddress((void**)&pattn,g_attn);
    cudaGetSymbolAddress((void**)&ptmp,g_tmp);   cudaGetSymbolAddress((void**)&pprobs,g_probs);
    bf16 *xh,*xl,*qh,*ql,*kh,*kl,*vth,*vtl,*ch,*cl,*ah,*al,*fh,*fl,*ph,*pl,*wh,*wl;
    cudaGetSymbolAddress((void**)&xh,g_xh);   cudaGetSymbolAddress((void**)&xl,g_xl);
    cudaGetSymbolAddress((void**)&qh,g_qh);   cudaGetSymbolAddress((void**)&ql,g_ql);
    cudaGetSymbolAddress((void**)&kh,g_kh);   cudaGetSymbolAddress((void**)&kl,g_kl);
    cudaGetSymbolAddress((void**)&vth,g_vth); cudaGetSymbolAddress((void**)&vtl,g_vtl);
    cudaGetSymbolAddress((void**)&ch,g_ch);   cudaGetSymbolAddress((void**)&cl,g_cl);
    cudaGetSymbolAddress((void**)&ah,g_ah);   cudaGetSymbolAddress((void**)&al,g_al);
    cudaGetSymbolAddress((void**)&fh,g_fh);   cudaGetSymbolAddress((void**)&fl,g_fl);
    cudaGetSymbolAddress((void**)&ph,g_ph);   cudaGetSymbolAddress((void**)&pl,g_pl);
    cudaGetSymbolAddress((void**)&wh,g_wh);   cudaGetSymbolAddress((void**)&wl,g_wl);

    cudaFuncSetAttribute(gemm_mma<0,false,1>,cudaFuncAttributeMaxDynamicSharedMemorySize,GSMEM);
    cudaFuncSetAttribute(gemm_mma<0,false,2>,cudaFuncAttributeMaxDynamicSharedMemorySize,GSMEM);
    cudaFuncSetAttribute(gemm_mma<0,true,0>, cudaFuncAttributeMaxDynamicSharedMemorySize,GSMEM);
    cudaFuncSetAttribute(gemm_mma<1,false,1>,cudaFuncAttributeMaxDynamicSharedMemorySize,GSMEM);
    cudaFuncSetAttribute(scores_mma,cudaFuncAttributeMaxDynamicSharedMemorySize,SCSM);
    cudaFuncSetAttribute(ctx_mma,cudaFuncAttributeMaxDynamicSharedMemorySize,CTSM);

    const size_t LW=(size_t)(4*Dd*Dd+2*Dd*Ff);
    for(int l=0;l<Ll;l++){
        bf16* bh_=wh+l*LW; bf16* bl_=wl+l*LW;
        dim3 tb(32,8);
        tsplit_k<<<dim3(Dd/32,Dd/32),tb>>>(Wq+(size_t)l*Dd*Dd,bh_,         bl_,         Dd,Dd);
        tsplit_k<<<dim3(Dd/32,Dd/32),tb>>>(Wk+(size_t)l*Dd*Dd,bh_+Dd*Dd,   bl_+Dd*Dd,   Dd,Dd);
        tsplit_k<<<dim3(Dd/32,Dd/32),tb>>>(Wv+(size_t)l*Dd*Dd,bh_+2*Dd*Dd, bl_+2*Dd*Dd, Dd,Dd);
        tsplit_k<<<dim3(Dd/32,Dd/32),tb>>>(Wo+(size_t)l*Dd*Dd,bh_+3*Dd*Dd, bl_+3*Dd*Dd, Dd,Dd);
        tsplit_k<<<dim3(Ff/32,Dd/32),tb>>>(Wi+(size_t)l*Dd*Ff,bh_+4*Dd*Dd, bl_+4*Dd*Dd, Dd,Ff);
        tsplit_k<<<dim3(Dd/32,Ff/32),tb>>>(Wf+(size_t)l*Ff*Dd,bh_+4*Dd*Dd+(size_t)Dd*Ff,bl_+4*Dd*Dd+(size_t)Dd*Ff,Ff,Dd);
    }

    const dim3 gDD(Dd/128,Mrows/128), gDF(Ff/128,Mrows/128);
    const int nD4=Mrows*Dd/4;
    split_k<<<(nD4+255)/256,256>>>(hidden,xh,xl,nD4);

    const float* X=hidden;
    for(int l=0;l<Ll;l++){
        bf16* bh_=wh+l*LW; bf16* bl_=wl+l*LW;
        bf16* wih=bh_+4*Dd*Dd; bf16* wil=bl_+4*Dd*Dd;
        bf16* wfh=wih+(size_t)Dd*Ff; bf16* wfl=wil+(size_t)Dd*Ff;

        gemm_mma<0,false,1><<<gDD,256,GSMEM>>>(xh,xl,bh_,        bl_,        bq+l*Dd,nullptr,nullptr,qh,ql,Dd,Dd);
        gemm_mma<0,false,1><<<gDD,256,GSMEM>>>(xh,xl,bh_+Dd*Dd,  bl_+Dd*Dd,  bk+l*Dd,nullptr,nullptr,kh,kl,Dd,Dd);
        gemm_mma<0,false,2><<<gDD,256,GSMEM>>>(xh,xl,bh_+2*Dd*Dd,bl_+2*Dd*Dd,bv+l*Dd,nullptr,nullptr,vth,vtl,Dd,Dd);

        scores_mma<<<dim3(4,4,Bb*Hh),256,SCSM>>>(qh,ql,kh,kl,pbias,ts,pprobs);
        softmax_k<<<(Bb*Hh*Ss)/8,256>>>(pprobs,ph,pl);
        ctx_mma<<<dim3(4,Bb*Hh),256,CTSM>>>(ph,pl,vth,vtl,ch,cl);

        gemm_mma<0,true,0><<<gDD,256,GSMEM>>>(ch,cl,bh_+3*Dd*Dd,bl_+3*Dd*Dd,bo+l*Dd,X,ptmp,nullptr,nullptr,Dd,Dd);
        ln_k<<<Mrows,128>>>(ptmp,l1g+l*Dd,l1b+l*Dd,pattn,ah,al);

        gemm_mma<1,false,1><<<gDF,256,GSMEM>>>(ah,al,wih,wil,bi+l*Ff,nullptr,nullptr,fh,fl,Ff,Dd);
        gemm_mma<0,true,0><<<gDD,256,GSMEM>>>(fh,fl,wfh,wfl,bfp+l*Dd,pattn,ptmp,nullptr,nullptr,Dd,Ff);
        ln_k<<<Mrows,128>>>(ptmp,l2g+l*Dd,l2b+l*Dd,px,xh,xl);
        X=px;
    }
    cudaMemcpyAsync(d_out,px,(size_t)Mrows*Dd*sizeof(float),cudaMemcpyDeviceToDevice,0);
}

// round 6
// speedup vs baseline: 2.0267x; 1.0683x over previous
#include <cuda_runtime.h>
#include <cuda_bf16.h>
#include <math.h>
#include <stdint.h>

#define Bb 32
#define Ss 512
#define Dd 512
#define Hh 8
#define Ff 2048
#define Ll 4
#define DH 64
#define Mrows (Bb*Ss)
#define BHSS ((size_t)Bb*Hh*Ss*Ss)

typedef __nv_bfloat16 bf16;
typedef __nv_bfloat162 bf162;

__device__ float g_x[Mrows*Dd];
__device__ float g_attn[Mrows*Dd];
__device__ float g_tmp[Mrows*Dd];
__device__ float g_probs[BHSS];
__device__ bf16 g_xh[Mrows*Dd], g_xl[Mrows*Dd];
__device__ bf16 g_qh[Mrows*Dd], g_ql[Mrows*Dd];
__device__ bf16 g_kh[Mrows*Dd], g_kl[Mrows*Dd];
__device__ bf16 g_vrh[Mrows*Dd], g_vrl[Mrows*Dd];    // V raw [s,d]
__device__ bf16 g_vth[Mrows*Dd], g_vtl[Mrows*Dd];    // V transposed [d,s] per head
__device__ bf16 g_ch[Mrows*Dd], g_cl[Mrows*Dd];
__device__ bf16 g_ah[Mrows*Dd], g_al[Mrows*Dd];
__device__ bf16 g_fh[(size_t)Mrows*Ff], g_fl[(size_t)Mrows*Ff];
__device__ bf16 g_ph[BHSS], g_pl[BHSS];
__device__ bf16 g_wh[(size_t)Ll*(4*Dd*Dd+2*Dd*Ff)];
__device__ bf16 g_wl[(size_t)Ll*(4*Dd*Dd+2*Dd*Ff)];

__device__ __forceinline__ float gelu_e(float x){return 0.5f*x*(1.0f+erff(x*0.70710678118654752f));}
__device__ __forceinline__ void cp16(uint32_t d,const void* s){
    asm volatile("cp.async.cg.shared.global [%0], [%1], 16;"::"r"(d),"l"(s));
}
#define CPC() asm volatile("cp.async.commit_group;":::"memory")
#define LDSM4(r0,r1,r2,r3,a) asm volatile("ldmatrix.sync.aligned.m8n8.x4.shared.b16 {%0,%1,%2,%3},[%4];":"=r"(r0),"=r"(r1),"=r"(r2),"=r"(r3):"r"(a))
#define MMA(d,a,b0,b1) asm volatile( \
    "mma.sync.aligned.m16n8k16.row.col.f32.bf16.bf16.f32 {%0,%1,%2,%3},{%4,%5,%6,%7},{%8,%9},{%0,%1,%2,%3};" \
    :"+f"((d)[0]),"+f"((d)[1]),"+f"((d)[2]),"+f"((d)[3]) \
    :"r"((a)[0]),"r"((a)[1]),"r"((a)[2]),"r"((a)[3]),"r"(b0),"r"(b1))

__device__ __forceinline__ void wsplit(float v, bf16& h, bf16& l){
    h=__float2bfloat16(v); l=__float2bfloat16(v-__bfloat162float(h));
}

// ======================= projection/FFN GEMM ====================
#define STB2 32768
#define GSMEM (2*STB2)
__device__ __forceinline__ void load_stage(uint32_t st,int tid,
    const bf16* Ah,const bf16* Al,const bf16* Bh,const bf16* Bl,
    int m0,int n0,int k0,int K){
    #pragma unroll
    for(int i=0;i<8;i++){
        int id=i*256+tid;
        int reg=id>>9, rid=id&511, row=rid>>2, c=rid&3;
        const bf16* src;
        if(reg==0)      src=Ah+(size_t)(m0+row)*K+k0+c*8;
        else if(reg==1) src=Al+(size_t)(m0+row)*K+k0+c*8;
        else if(reg==2) src=Bh+(size_t)(n0+row)*K+k0+c*8;
        else            src=Bl+(size_t)(n0+row)*K+k0+c*8;
        cp16(st+reg*8192+row*64+((c^((row>>1)&3))*16),src);
    }
    CPC();
}

// OUT: 0=fp32 C, 1=bf16 hi/lo same layout
template<int ACT, bool RES, int OUT>
__global__ void __launch_bounds__(256,2)
gemm_mma(const bf16* __restrict__ Ah,const bf16* __restrict__ Al,
         const bf16* __restrict__ Bh,const bf16* __restrict__ Bl,
         const float* __restrict__ bias,const float* __restrict__ res,
         float* __restrict__ C,bf16* __restrict__ Ch,bf16* __restrict__ Cl,
         int N,int K){
    extern __shared__ char sm[];
    uint32_t sb=(uint32_t)__cvta_generic_to_shared(sm);
    const int tid=threadIdx.x, wid=tid>>5, lane=tid&31;
    const int n0=blockIdx.x*128, m0=blockIdx.y*128;
    const int wm=(wid>>2)*64, wn=(wid&3)*32;
    const int chunks=K>>5;
    float acc[4][4][4];
    #pragma unroll
    for(int i=0;i<4;i++)
        #pragma unroll
        for(int j=0;j<4;j++){acc[i][j][0]=0;acc[i][j][1]=0;acc[i][j][2]=0;acc[i][j][3]=0;}
    load_stage(sb,tid,Ah,Al,Bh,Bl,m0,n0,0,K);
    load_stage(sb+STB2,tid,Ah,Al,Bh,Bl,m0,n0,32,K);
    const int arow=lane&15, ah8=lane>>4;
    for(int c=0;c<chunks;c++){
        uint32_t st=sb+(c&1)*STB2;
        if(c+2<chunks) asm volatile("cp.async.wait_group 1;":::"memory");
        else           asm volatile("cp.async.wait_group 0;":::"memory");
        __syncthreads();
        #pragma unroll
        for(int s=0;s<2;s++){
            uint32_t ahf[4][4],alf[4][4],bhf[2][4],blf[2][4];
            #pragma unroll
            for(int mi=0;mi<4;mi++){
                int row=wm+mi*16+arow;
                uint32_t ad=st+row*64+(((s*2+ah8)^((row>>1)&3))*16);
                LDSM4(ahf[mi][0],ahf[mi][1],ahf[mi][2],ahf[mi][3],ad);
                LDSM4(alf[mi][0],alf[mi][1],alf[mi][2],alf[mi][3],ad+8192);
            }
            #pragma unroll
            for(int nq=0;nq<2;nq++){
                int row=wn+nq*16+arow;
                uint32_t ad=st+16384+row*64+(((s*2+ah8)^((row>>1)&3))*16);
                LDSM4(bhf[nq][0],bhf[nq][1],bhf[nq][2],bhf[nq][3],ad);
                LDSM4(blf[nq][0],blf[nq][1],blf[nq][2],blf[nq][3],ad+8192);
            }
            #pragma unroll
            for(int mi=0;mi<4;mi++)
                #pragma unroll
                for(int nq=0;nq<2;nq++)
                    #pragma unroll
                    for(int p=0;p<2;p++){
                        int nt=nq*2+p;
                        MMA(acc[mi][nt],ahf[mi],bhf[nq][p],bhf[nq][p+2]);
                        MMA(acc[mi][nt],ahf[mi],blf[nq][p],blf[nq][p+2]);
                        MMA(acc[mi][nt],alf[mi],bhf[nq][p],bhf[nq][p+2]);
                    }
        }
        __syncthreads();
        if(c+2<chunks) load_stage(sb+(c&1)*STB2,tid,Ah,Al,Bh,Bl,m0,n0,(c+2)*32,K);
    }
    const int r4=lane>>2, c2=(lane&3)*2;
    #pragma unroll
    for(int mi=0;mi<4;mi++)
        #pragma unroll
        for(int nt=0;nt<4;nt++){
            int col=n0+wn+nt*8+c2;
            float2 bv=*(const float2*)&bias[col];
            #pragma unroll
            for(int hr=0;hr<2;hr++){
                int row=m0+wm+mi*16+r4+hr*8;
                float2 o;
                o.x=acc[mi][nt][hr*2+0]+bv.x;
                o.y=acc[mi][nt][hr*2+1]+bv.y;
                if(RES){float2 rv=*(const float2*)&res[(size_t)row*N+col]; o.x+=rv.x;o.y+=rv.y;}
                if(ACT==1){o.x=gelu_e(o.x);o.y=gelu_e(o.y);}
                if(OUT==0){
                    *(float2*)&C[(size_t)row*N+col]=o;
                }else{
                    bf16 h0,l0,h1,l1; wsplit(o.x,h0,l0); wsplit(o.y,h1,l1);
                    *(bf162*)&Ch[(size_t)row*N+col]=__halves2bfloat162(h0,h1);
                    *(bf162*)&Cl[(size_t)row*N+col]=__halves2bfloat162(l0,l1);
                }
            }
        }
}

// ============ V transpose: [b*S+s][h*64+dh] -> [(b*8+h)*64+dh][s], hi+lo ========
__global__ void vtrans_k(const bf16* __restrict__ sh,const bf16* __restrict__ sl,
                         bf16* __restrict__ dh_,bf16* __restrict__ dl_){
    __shared__ bf16 t1[32][33], t2[32][33];
    const int n0=blockIdx.x*32, m0=blockIdx.y*32;
    const int x=threadIdx.x, y0=threadIdx.y;
    for(int j=y0;j<32;j+=8){
        t1[j][x]=sh[(size_t)(m0+j)*Dd+n0+x];
        t2[j][x]=sl[(size_t)(m0+j)*Dd+n0+x];
    }
    __syncthreads();
    const int b=m0>>9, sl_=m0&511;
    for(int j=y0;j<32;j+=8){
        int c=n0+j, hh=c>>6, dhh=c&63;
        size_t o=((size_t)((b*Hh+hh)*64+dhh))*512+sl_+x;
        dh_[o]=t1[x][j];
        dl_[o]=t2[x][j];
    }
}

// ================= scores: S = Q@K^T /scale + pbias (per b,h) ====================
#define SCSM 65536
__global__ void __launch_bounds__(256,1)
scores_mma(const bf16* __restrict__ Qh,const bf16* __restrict__ Ql,
           const bf16* __restrict__ Kh,const bf16* __restrict__ Kl,
           const float* __restrict__ pbias,const long long* __restrict__ ts,
           float* __restrict__ scores){
    extern __shared__ char sm[];
    uint32_t sb=(uint32_t)__cvta_generic_to_shared(sm);
    const int tid=threadIdx.x, wid=tid>>5, lane=tid&31;
    const int bh=blockIdx.z, b=bh>>3, h=bh&7;
    const int m0=blockIdx.y*128, n0=blockIdx.x*128;
    const int wm=(wid>>2)*64, wn=(wid&3)*32;
    #pragma unroll
    for(int i=0;i<16;i++){
        int id=i*256+tid;
        int reg=id>>10, rid=id&1023, row=rid>>3, c=rid&7;
        const bf16* base=(reg==0)?Qh:(reg==1)?Ql:(reg==2)?Kh:Kl;
        int r0=(reg<2)?m0:n0;
        cp16(sb+reg*16384+row*128+((c^(row&7))*16),
             base+((size_t)(b*Ss+r0+row))*Dd+h*DH+c*8);
    }
    CPC();
    asm volatile("cp.async.wait_group 0;":::"memory");
    __syncthreads();

    float acc[4][4][4];
    #pragma unroll
    for(int i=0;i<4;i++)
        #pragma unroll
        for(int j=0;j<4;j++){acc[i][j][0]=0;acc[i][j][1]=0;acc[i][j][2]=0;acc[i][j][3]=0;}
    const int arow=lane&15, ah8=lane>>4;
    #pragma unroll
    for(int s=0;s<4;s++){
        uint32_t ahf[4][4],alf[4][4],bhf[2][4],blf[2][4];
        #pragma unroll
        for(int mi=0;mi<4;mi++){
            int row=wm+mi*16+arow;
            uint32_t ad=sb+row*128+((((s*2+ah8))^(row&7))*16);
            LDSM4(ahf[mi][0],ahf[mi][1],ahf[mi][2],ahf[mi][3],ad);
            LDSM4(alf[mi][0],alf[mi][1],alf[mi][2],alf[mi][3],ad+16384);
        }
        #pragma unroll
        for(int nq=0;nq<2;nq++){
            int row=wn+nq*16+arow;
            uint32_t ad=sb+32768+row*128+((((s*2+ah8))^(row&7))*16);
            LDSM4(bhf[nq][0],bhf[nq][1],bhf[nq][2],bhf[nq][3],ad);
            LDSM4(blf[nq][0],blf[nq][1],blf[nq][2],blf[nq][3],ad+16384);
        }
        #pragma unroll
        for(int mi=0;mi<4;mi++)
            #pragma unroll
            for(int nq=0;nq<2;nq++)
                #pragma unroll
                for(int p=0;p<2;p++){
                    int nt=nq*2+p;
                    MMA(acc[mi][nt],ahf[mi],bhf[nq][p],bhf[nq][p+2]);
                    MMA(acc[mi][nt],ahf[mi],blf[nq][p],blf[nq][p+2]);
                    MMA(acc[mi][nt],alf[mi],bhf[nq][p],bhf[nq][p+2]);
                }
    }
    const int r4=lane>>2, c2=(lane&3)*2;
    #pragma unroll
    for(int mi=0;mi<4;mi++)
        #pragma unroll
        for(int nt=0;nt<4;nt++){
            int kc=n0+wn+nt*8+c2;
            long long tk0=ts[b*Ss+kc], tk1=ts[b*Ss+kc+1];
            #pragma unroll
            for(int hr=0;hr<2;hr++){
                int qi=m0+wm+mi*16+r4+hr*8;
                long long tq=ts[b*Ss+qi];
                float2 pb=*(const float2*)&pbias[((size_t)(h*Ss+qi))*Ss+kc];
                float l0=(float)(tq-tk0)*(1.0f/60000.0f);
                float l1=(float)(tq-tk1)*(1.0f/60000.0f);
                float s0=9.0f-1.0f/(fmaxf(l0,0.0f)+1.0f);
                float s1=9.0f-1.0f/(fmaxf(l1,0.0f)+1.0f);
                float2 o;
                o.x=acc[mi][nt][hr*2+0]/s0+pb.x;
                o.y=acc[mi][nt][hr*2+1]/s1+pb.y;
                *(float2*)&scores[((size_t)bh*Ss+qi)*Ss+kc]=o;
            }
        }
}

// ============== softmax: fp32 in -> bf16 hi/lo out =============================
__global__ void softmax_k(const float* __restrict__ p, bf16* __restrict__ ph,
                          bf16* __restrict__ pl){
    const size_t row=(size_t)blockIdx.x*8+(threadIdx.x>>5);
    const int lane=threadIdx.x&31;
    const float* pr=p+row*Ss;
    float v[16], m=-1e30f;
    #pragma unroll
    for(int i=0;i<16;i++){v[i]=pr[lane*16+i];m=fmaxf(m,v[i]);}
    #pragma unroll
    for(int o=16;o;o>>=1)m=fmaxf(m,__shfl_xor_sync(0xffffffffu,m,o));
    float s=0.0f;
    #pragma unroll
    for(int i=0;i<16;i++){v[i]=__expf(v[i]-m);s+=v[i];}
    #pragma unroll
    for(int o=16;o;o>>=1)s+=__shfl_xor_sync(0xffffffffu,s,o);
    float inv=1.0f/s;
    bf16 hb[16], lb[16];
    #pragma unroll
    for(int i=0;i<16;i++){float pv=v[i]*inv; wsplit(pv,hb[i],lb[i]);}
    #pragma unroll
    for(int i=0;i<8;i++){
        ((bf162*)(ph+row*Ss+lane*16))[i]=__halves2bfloat162(hb[2*i],hb[2*i+1]);
        ((bf162*)(pl+row*Ss+lane*16))[i]=__halves2bfloat162(lb[2*i],lb[2*i+1]);
    }
}

// ================= ctx: C = P@V (per b,h), out bf16 hi/lo [s,d] ==================
#define CTST 24576
#define CTSM (2*CTST)
__global__ void __launch_bounds__(256,2)
ctx_mma(const bf16* __restrict__ Ph,const bf16* __restrict__ Pl,
        const bf16* __restrict__ Vh,const bf16* __restrict__ Vl,
        bf16* __restrict__ Ch,bf16* __restrict__ Cl){
    extern __shared__ char sm[];
    uint32_t sb=(uint32_t)__cvta_generic_to_shared(sm);
    const int tid=threadIdx.x, wid=tid>>5, lane=tid&31;
    const int bh=blockIdx.y, b=bh>>3, h=bh&7;
    const int m0=blockIdx.x*128;
    const int wm=(wid>>1)*32, wn=(wid&1)*32;
    float acc[2][4][4];
    #pragma unroll
    for(int i=0;i<2;i++)
        #pragma unroll
        for(int j=0;j<4;j++){acc[i][j][0]=0;acc[i][j][1]=0;acc[i][j][2]=0;acc[i][j][3]=0;}

    auto load=[&](uint32_t st,int k0){
        #pragma unroll
        for(int i=0;i<6;i++){
            int id=i*256+tid;
            const bf16* src; uint32_t off; int row,c;
            if(id<1024){
                int reg=id>>9; row=(id&511)>>2; c=id&3;
                src=(reg?Pl:Ph)+((size_t)(bh*Ss+m0+row))*Ss+k0+c*8;
                off=reg*8192;
            }else{
                int id2=id-1024; int reg=id2>>8; row=(id2&255)>>2; c=id2&3;
                src=(reg?Vl:Vh)+((size_t)(bh*64+row))*Ss+k0+c*8;
                off=16384+reg*4096;
            }
            cp16(st+off+row*64+((c^((row>>1)&3))*16),src);
        }
        CPC();
    };
    load(sb,0); load(sb+CTST,32);
    const int arow=lane&15, ah8=lane>>4;
    for(int c=0;c<16;c++){
        uint32_t st=sb+(c&1)*CTST;
        if(c+2<16) asm volatile("cp.async.wait_group 1;":::"memory");
        else       asm volatile("cp.async.wait_group 0;":::"memory");
        __syncthreads();
        #pragma unroll
        for(int s=0;s<2;s++){
            uint32_t ahf[2][4],alf[2][4],bhf[2][4],blf[2][4];
            #pragma unroll
            for(int mi=0;mi<2;mi++){
                int row=wm+mi*16+arow;
                uint32_t ad=st+row*64+(((s*2+ah8)^((row>>1)&3))*16);
                LDSM4(ahf[mi][0],ahf[mi][1],ahf[mi][2],ahf[mi][3],ad);
                LDSM4(alf[mi][0],alf[mi][1],alf[mi][2],alf[mi][3],ad+8192);
            }
            #pragma unroll
            for(int nq=0;nq<2;nq++){
                int row=wn+nq*16+arow;
                uint32_t ad=st+16384+row*64+(((s*2+ah8)^((row>>1)&3))*16);
                LDSM4(bhf[nq][0],bhf[nq][1],bhf[nq][2],bhf[nq][3],ad);
                LDSM4(blf[nq][0],blf[nq][1],blf[nq][2],blf[nq][3],ad+4096);
            }
            #pragma unroll
            for(int mi=0;mi<2;mi++)
                #pragma unroll
                for(int nq=0;nq<2;nq++)
                    #pragma unroll
                    for(int p=0;p<2;p++){
                        int nt=nq*2+p;
                        MMA(acc[mi][nt],ahf[mi],bhf[nq][p],bhf[nq][p+2]);
                        MMA(acc[mi][nt],ahf[mi],blf[nq][p],blf[nq][p+2]);
                        MMA(acc[mi][nt],alf[mi],bhf[nq][p],bhf[nq][p+2]);
                    }
        }
        __syncthreads();
        if(c+2<16) load(sb+(c&1)*CTST,(c+2)*32);
    }
    const int r4=lane>>2, c2=(lane&3)*2;
    #pragma unroll
    for(int mi=0;mi<2;mi++)
        #pragma unroll
        for(int nt=0;nt<4;nt++){
            int dh=wn+nt*8+c2;
            #pragma unroll
            for(int hr=0;hr<2;hr++){
                int si=m0+wm+mi*16+r4+hr*8;
                float ox=acc[mi][nt][hr*2+0], oy=acc[mi][nt][hr*2+1];
                bf16 h0,l0,h1,l1; wsplit(ox,h0,l0); wsplit(oy,h1,l1);
                size_t idx=((size_t)(b*Ss+si))*Dd+h*DH+dh;
                *(bf162*)&Ch[idx]=__halves2bfloat162(h0,h1);
                *(bf162*)&Cl[idx]=__halves2bfloat162(l0,l1);
            }
        }
}

// ================= LayerNorm: fp32 out + bf16 hi/lo out ========================
__global__ void ln_k(const float* __restrict__ in,const float* __restrict__ g,
                     const float* __restrict__ bt,float* __restrict__ out,
                     bf16* __restrict__ oh,bf16* __restrict__ ol){
    const size_t row=blockIdx.x;
    const int tid=threadIdx.x, lane=tid&31, wid=tid>>5;
    __shared__ float red[4];
    float4 v=*(const float4*)&in[row*Dd+tid*4];
    float s=v.x+v.y+v.z+v.w;
    #pragma unroll
    for(int o=16;o;o>>=1)s+=__shfl_xor_sync(0xffffffffu,s,o);
    if(lane==0)red[wid]=s;
    __syncthreads();
    float mu=(red[0]+red[1]+red[2]+red[3])*(1.0f/512.0f);
    __syncthreads();
    float dx=v.x-mu,dy=v.y-mu,dz=v.z-mu,dw=v.w-mu;
    float s2=dx*dx+dy*dy+dz*dz+dw*dw;
    #pragma unroll
    for(int o=16;o;o>>=1)s2+=__shfl_xor_sync(0xffffffffu,s2,o);
    if(lane==0)red[wid]=s2;
    __syncthreads();
    float var=(red[0]+red[1]+red[2]+red[3])*(1.0f/512.0f);
    float inv=rsqrtf(var+1e-12f);
    float4 gv=*(const float4*)&g[tid*4];
    float4 bv=*(const float4*)&bt[tid*4];
    float4 o;
    o.x=dx*inv*gv.x+bv.x; o.y=dy*inv*gv.y+bv.y;
    o.z=dz*inv*gv.z+bv.z; o.w=dw*inv*gv.w+bv.w;
    *(float4*)&out[row*Dd+tid*4]=o;
    bf16 h0,l0,h1,l1,h2,l2,h3,l3;
    wsplit(o.x,h0,l0);wsplit(o.y,h1,l1);wsplit(o.z,h2,l2);wsplit(o.w,h3,l3);
    ((bf162*)(oh+row*Dd+tid*4))[0]=__halves2bfloat162(h0,h1);
    ((bf162*)(oh+row*Dd+tid*4))[1]=__halves2bfloat162(h2,h3);
    ((bf162*)(ol+row*Dd+tid*4))[0]=__halves2bfloat162(l0,l1);
    ((bf162*)(ol+row*Dd+tid*4))[1]=__halves2bfloat162(l2,l3);
}

__global__ void split_k(const float* __restrict__ s,bf16* __restrict__ hi,
                        bf16* __restrict__ lo,int n4){
    int i=blockIdx.x*256+threadIdx.x;
    if(i>=n4)return;
    float4 v=((const float4*)s)[i];
    bf16 h0,l0,h1,l1,h2,l2,h3,l3;
    wsplit(v.x,h0,l0);wsplit(v.y,h1,l1);wsplit(v.z,h2,l2);wsplit(v.w,h3,l3);
    ((bf162*)hi)[i*2+0]=__halves2bfloat162(h0,h1);
    ((bf162*)hi)[i*2+1]=__halves2bfloat162(h2,h3);
    ((bf162*)lo)[i*2+0]=__halves2bfloat162(l0,l1);
    ((bf162*)lo)[i*2+1]=__halves2bfloat162(l2,l3);
}

__global__ void tsplit_k(const float* __restrict__ W,bf16* __restrict__ hi,
                         bf16* __restrict__ lo,int K,int N){
    __shared__ float t[32][33];
    int n=blockIdx.x*32+threadIdx.x, k0=blockIdx.y*32;
    for(int j=threadIdx.y;j<32;j+=8) t[j][threadIdx.x]=W[(size_t)(k0+j)*N+n];
    __syncthreads();
    int k=k0+threadIdx.x, n0=blockIdx.x*32;
    for(int j=threadIdx.y;j<32;j+=8){
        float v=t[threadIdx.x][j];
        bf16 h,l; wsplit(v,h,l);
        hi[(size_t)(n0+j)*K+k]=h;
        lo[(size_t)(n0+j)*K+k]=l;
    }
}

extern "C" void kernel_launch(void* const* d_in, const int* in_sizes, int n_in,
                              void* d_out, int out_size){
    const float* hidden=(const float*)d_in[0];
    const float* pbias=(const float*)d_in[1];
    const long long* ts=(const long long*)d_in[2];
    const float* Wq=(const float*)d_in[3];  const float* bq=(const float*)d_in[4];
    const float* Wk=(const float*)d_in[5];  const float* bk=(const float*)d_in[6];
    const float* Wv=(const float*)d_in[7];  const float* bv=(const float*)d_in[8];
    const float* Wo=(const float*)d_in[9];  const float* bo=(const float*)d_in[10];
    const float* l1g=(const float*)d_in[11];const float* l1b=(const float*)d_in[12];
    const float* Wi=(const float*)d_in[13]; const float* bi=(const float*)d_in[14];
    const float* Wf=(const float*)d_in[15]; const float* bfp=(const float*)d_in[16];
    const float* l2g=(const float*)d_in[17];const float* l2b=(const float*)d_in[18];

    float *px,*pattn,*ptmp,*pprobs;
    cudaGetSymbolAddress((void**)&px,g_x);       cudaGetSymbolAddress((void**)&pattn,g_attn);
    cudaGetSymbolAddress((void**)&ptmp,g_tmp);   cudaGetSymbolAddress((void**)&pprobs,g_probs);
    bf16 *xh,*xl,*qh,*ql,*kh,*kl,*vrh,*vrl,*vth,*vtl,*ch,*cl,*ah,*al,*fh,*fl,*ph,*pl,*wh,*wl;
    cudaGetSymbolAddress((void**)&xh,g_xh);   cudaGetSymbolAddress((void**)&xl,g_xl);
    cudaGetSymbolAddress((void**)&qh,g_qh);   cudaGetSymbolAddress((void**)&ql,g_ql);
    cudaGetSymbolAddress((void**)&kh,g_kh);   cudaGetSymbolAddress((void**)&kl,g_kl);
    cudaGetSymbolAddress((void**)&vrh,g_vrh); cudaGetSymbolAddress((void**)&vrl,g_vrl);
    cudaGetSymbolAddress((void**)&vth,g_vth); cudaGetSymbolAddress((void**)&vtl,g_vtl);
    cudaGetSymbolAddress((void**)&ch,g_ch);   cudaGetSymbolAddress((void**)&cl,g_cl);
    cudaGetSymbolAddress((void**)&ah,g_ah);   cudaGetSymbolAddress((void**)&al,g_al);
    cudaGetSymbolAddress((void**)&fh,g_fh);   cudaGetSymbolAddress((void**)&fl,g_fl);
    cudaGetSymbolAddress((void**)&ph,g_ph);   cudaGetSymbolAddress((void**)&pl,g_pl);
    cudaGetSymbolAddress((void**)&wh,g_wh);   cudaGetSymbolAddress((void**)&wl,g_wl);

    cudaFuncSetAttribute(gemm_mma<0,false,1>,cudaFuncAttributeMaxDynamicSharedMemorySize,GSMEM);
    cudaFuncSetAttribute(gemm_mma<0,true,0>, cudaFuncAttributeMaxDynamicSharedMemorySize,GSMEM);
    cudaFuncSetAttribute(gemm_mma<1,false,1>,cudaFuncAttributeMaxDynamicSharedMemorySize,GSMEM);
    cudaFuncSetAttribute(scores_mma,cudaFuncAttributeMaxDynamicSharedMemorySize,SCSM);
    cudaFuncSetAttribute(ctx_mma,cudaFuncAttributeMaxDynamicSharedMemorySize,CTSM);

    const size_t LW=(size_t)(4*Dd*Dd+2*Dd*Ff);
    for(int l=0;l<Ll;l++){
        bf16* bh_=wh+l*LW; bf16* bl_=wl+l*LW;
        dim3 tb(32,8);
        tsplit_k<<<dim3(Dd/32,Dd/32),tb>>>(Wq+(size_t)l*Dd*Dd,bh_,         bl_,         Dd,Dd);
        tsplit_k<<<dim3(Dd/32,Dd/32),tb>>>(Wk+(size_t)l*Dd*Dd,bh_+Dd*Dd,   bl_+Dd*Dd,   Dd,Dd);
        tsplit_k<<<dim3(Dd/32,Dd/32),tb>>>(Wv+(size_t)l*Dd*Dd,bh_+2*Dd*Dd, bl_+2*Dd*Dd, Dd,Dd);
        tsplit_k<<<dim3(Dd/32,Dd/32),tb>>>(Wo+(size_t)l*Dd*Dd,bh_+3*Dd*Dd, bl_+3*Dd*Dd, Dd,Dd);
        tsplit_k<<<dim3(Ff/32,Dd/32),tb>>>(Wi+(size_t)l*Dd*Ff,bh_+4*Dd*Dd, bl_+4*Dd*Dd, Dd,Ff);
        tsplit_k<<<dim3(Dd/32,Ff/32),tb>>>(Wf+(size_t)l*Ff*Dd,bh_+4*Dd*Dd+(size_t)Dd*Ff,bl_+4*Dd*Dd+(size_t)Dd*Ff,Ff,Dd);
    }

    const dim3 gDD(Dd/128,Mrows/128), gDF(Ff/128,Mrows/128);
    const int nD4=Mrows*Dd/4;
    split_k<<<(nD4+255)/256,256>>>(hidden,xh,xl,nD4);

    const float* X=hidden;
    for(int l=0;l<Ll;l++){
        bf16* bh_=wh+l*LW; bf16* bl_=wl+l*LW;
        bf16* wih=bh_+4*Dd*Dd; bf16* wil=bl_+4*Dd*Dd;
        bf16* wfh=wih+(size_t)Dd*Ff; bf16* wfl=wil+(size_t)Dd*Ff;

        gemm_mma<0,false,1><<<gDD,256,GSMEM>>>(xh,xl,bh_,        bl_,        bq+l*Dd,nullptr,nullptr,qh,ql,Dd,Dd);
        gemm_mma<0,false,1><<<gDD,256,GSMEM>>>(xh,xl,bh_+Dd*Dd,  bl_+Dd*Dd,  bk+l*Dd,nullptr,nullptr,kh,kl,Dd,Dd);
        gemm_mma<0,false,1><<<gDD,256,GSMEM>>>(xh,xl,bh_+2*Dd*Dd,bl_+2*Dd*Dd,bv+l*Dd,nullptr,nullptr,vrh,vrl,Dd,Dd);
        vtrans_k<<<dim3(Dd/32,Mrows/32),dim3(32,8)>>>(vrh,vrl,vth,vtl);

        scores_mma<<<dim3(4,4,Bb*Hh),256,SCSM>>>(qh,ql,kh,kl,pbias,ts,pprobs);
        softmax_k<<<(Bb*Hh*Ss)/8,256>>>(pprobs,ph,pl);
        ctx_mma<<<dim3(4,Bb*Hh),256,CTSM>>>(ph,pl,vth,vtl,ch,cl);

        gemm_mma<0,true,0><<<gDD,256,GSMEM>>>(ch,cl,bh_+3*Dd*Dd,bl_+3*Dd*Dd,bo+l*Dd,X,ptmp,nullptr,nullptr,Dd,Dd);
        ln_k<<<Mrows,128>>>(ptmp,l1g+l*Dd,l1b+l*Dd,pattn,ah,al);

        gemm_mma<1,false,1><<<gDF,256,GSMEM>>>(ah,al,wih,wil,bi+l*Ff,nullptr,nullptr,fh,fl,Ff,Dd);
        gemm_mma<0,true,0><<<gDD,256,GSMEM>>>(fh,fl,wfh,wfl,bfp+l*Dd,pattn,ptmp,nullptr,nullptr,Dd,Ff);
        ln_k<<<Mrows,128>>>(ptmp,l2g+l*Dd,l2b+l*Dd,px,xh,xl);
        X=px;
    }
    cudaMemcpyAsync(d_out,px,(size_t)Mrows*Dd*sizeof(float),cudaMemcpyDeviceToDevice,0);
}

// round 7
// speedup vs baseline: 2.4645x; 1.2160x over previous
#include <cuda_runtime.h>
#include <cuda_bf16.h>
#include <math.h>
#include <stdint.h>

#define Bb 32
#define Ss 512
#define Dd 512
#define Hh 8
#define Ff 2048
#define Ll 4
#define DH 64
#define Mrows (Bb*Ss)

typedef __nv_bfloat16 bf16;
typedef __nv_bfloat162 bf162;

__device__ float g_x[Mrows*Dd];
__device__ float g_attn[Mrows*Dd];
__device__ float g_tmp[Mrows*Dd];
__device__ bf16 g_xh[Mrows*Dd], g_xl[Mrows*Dd];
__device__ bf16 g_qkvh[(size_t)Mrows*3*Dd], g_qkvl[(size_t)Mrows*3*Dd];
__device__ bf16 g_ch[Mrows*Dd], g_cl[Mrows*Dd];
__device__ bf16 g_ah[Mrows*Dd], g_al[Mrows*Dd];
__device__ bf16 g_fh[(size_t)Mrows*Ff], g_fl[(size_t)Mrows*Ff];
__device__ bf16 g_wh[(size_t)Ll*(4*Dd*Dd+2*Dd*Ff)];
__device__ bf16 g_wl[(size_t)Ll*(4*Dd*Dd+2*Dd*Ff)];
__device__ float g_catb[Ll*3*Dd];

__device__ __forceinline__ float gelu_e(float x){return 0.5f*x*(1.0f+erff(x*0.70710678118654752f));}
__device__ __forceinline__ void cp16(uint32_t d,const void* s){
    asm volatile("cp.async.cg.shared.global [%0], [%1], 16;"::"r"(d),"l"(s));
}
#define CPC() asm volatile("cp.async.commit_group;":::"memory")
#define LDSM4(r0,r1,r2,r3,a) asm volatile("ldmatrix.sync.aligned.m8n8.x4.shared.b16 {%0,%1,%2,%3},[%4];":"=r"(r0),"=r"(r1),"=r"(r2),"=r"(r3):"r"(a))
#define LDSM4T(r0,r1,r2,r3,a) asm volatile("ldmatrix.sync.aligned.m8n8.x4.trans.shared.b16 {%0,%1,%2,%3},[%4];":"=r"(r0),"=r"(r1),"=r"(r2),"=r"(r3):"r"(a))
#define MMA(d,a,b0,b1) asm volatile( \
    "mma.sync.aligned.m16n8k16.row.col.f32.bf16.bf16.f32 {%0,%1,%2,%3},{%4,%5,%6,%7},{%8,%9},{%0,%1,%2,%3};" \
    :"+f"((d)[0]),"+f"((d)[1]),"+f"((d)[2]),"+f"((d)[3]) \
    :"r"((a)[0]),"r"((a)[1]),"r"((a)[2]),"r"((a)[3]),"r"(b0),"r"(b1))

__device__ __forceinline__ void wsplit(float v, bf16& h, bf16& l){
    h=__float2bfloat16(v); l=__float2bfloat16(v-__bfloat162float(h));
}
__device__ __forceinline__ uint32_t packhi(float a,float b,uint32_t& lo){
    bf16 h0,l0,h1,l1; wsplit(a,h0,l0); wsplit(b,h1,l1);
    bf162 L=__halves2bfloat162(l0,l1); lo=*(uint32_t*)&L;
    bf162 H=__halves2bfloat162(h0,h1); return *(uint32_t*)&H;
}

// ======================= projection/FFN GEMM ====================
#define STB2 32768
#define GSMEM (2*STB2)
__device__ __forceinline__ void load_stage(uint32_t st,int tid,
    const bf16* Ah,const bf16* Al,const bf16* Bh,const bf16* Bl,
    int m0,int n0,int k0,int K){
    #pragma unroll
    for(int i=0;i<8;i++){
        int id=i*256+tid;
        int reg=id>>9, rid=id&511, row=rid>>2, c=rid&3;
        const bf16* src;
        if(reg==0)      src=Ah+(size_t)(m0+row)*K+k0+c*8;
        else if(reg==1) src=Al+(size_t)(m0+row)*K+k0+c*8;
        else if(reg==2) src=Bh+(size_t)(n0+row)*K+k0+c*8;
        else            src=Bl+(size_t)(n0+row)*K+k0+c*8;
        cp16(st+reg*8192+row*64+((c^((row>>1)&3))*16),src);
    }
    CPC();
}

template<int ACT, bool RES, int OUT>
__global__ void __launch_bounds__(256,2)
gemm_mma(const bf16* __restrict__ Ah,const bf16* __restrict__ Al,
         const bf16* __restrict__ Bh,const bf16* __restrict__ Bl,
         const float* __restrict__ bias,const float* __restrict__ res,
         float* __restrict__ C,bf16* __restrict__ Ch,bf16* __restrict__ Cl,
         int N,int K){
    extern __shared__ char sm[];
    uint32_t sb=(uint32_t)__cvta_generic_to_shared(sm);
    const int tid=threadIdx.x, wid=tid>>5, lane=tid&31;
    const int n0=blockIdx.x*128, m0=blockIdx.y*128;
    const int wm=(wid>>2)*64, wn=(wid&3)*32;
    const int chunks=K>>5;
    float acc[4][4][4];
    #pragma unroll
    for(int i=0;i<4;i++)
        #pragma unroll
        for(int j=0;j<4;j++){acc[i][j][0]=0;acc[i][j][1]=0;acc[i][j][2]=0;acc[i][j][3]=0;}
    load_stage(sb,tid,Ah,Al,Bh,Bl,m0,n0,0,K);
    load_stage(sb+STB2,tid,Ah,Al,Bh,Bl,m0,n0,32,K);
    const int arow=lane&15, ah8=lane>>4;
    for(int c=0;c<chunks;c++){
        uint32_t st=sb+(c&1)*STB2;
        if(c+2<chunks) asm volatile("cp.async.wait_group 1;":::"memory");
        else           asm volatile("cp.async.wait_group 0;":::"memory");
        __syncthreads();
        #pragma unroll
        for(int s=0;s<2;s++){
            uint32_t ahf[4][4],alf[4][4],bhf[2][4],blf[2][4];
            #pragma unroll
            for(int mi=0;mi<4;mi++){
                int row=wm+mi*16+arow;
                uint32_t ad=st+row*64+(((s*2+ah8)^((row>>1)&3))*16);
                LDSM4(ahf[mi][0],ahf[mi][1],ahf[mi][2],ahf[mi][3],ad);
                LDSM4(alf[mi][0],alf[mi][1],alf[mi][2],alf[mi][3],ad+8192);
            }
            #pragma unroll
            for(int nq=0;nq<2;nq++){
                int row=wn+nq*16+arow;
                uint32_t ad=st+16384+row*64+(((s*2+ah8)^((row>>1)&3))*16);
                LDSM4(bhf[nq][0],bhf[nq][1],bhf[nq][2],bhf[nq][3],ad);
                LDSM4(blf[nq][0],blf[nq][1],blf[nq][2],blf[nq][3],ad+8192);
            }
            #pragma unroll
            for(int mi=0;mi<4;mi++)
                #pragma unroll
                for(int nq=0;nq<2;nq++)
                    #pragma unroll
                    for(int p=0;p<2;p++){
                        int nt=nq*2+p;
                        MMA(acc[mi][nt],ahf[mi],bhf[nq][p],bhf[nq][p+2]);
                        MMA(acc[mi][nt],ahf[mi],blf[nq][p],blf[nq][p+2]);
                        MMA(acc[mi][nt],alf[mi],bhf[nq][p],bhf[nq][p+2]);
                    }
        }
        __syncthreads();
        if(c+2<chunks) load_stage(sb+(c&1)*STB2,tid,Ah,Al,Bh,Bl,m0,n0,(c+2)*32,K);
    }
    const int r4=lane>>2, c2=(lane&3)*2;
    #pragma unroll
    for(int mi=0;mi<4;mi++)
        #pragma unroll
        for(int nt=0;nt<4;nt++){
            int col=n0+wn+nt*8+c2;
            float2 bv=*(const float2*)&bias[col];
            #pragma unroll
            for(int hr=0;hr<2;hr++){
                int row=m0+wm+mi*16+r4+hr*8;
                float2 o;
                o.x=acc[mi][nt][hr*2+0]+bv.x;
                o.y=acc[mi][nt][hr*2+1]+bv.y;
                if(RES){float2 rv=*(const float2*)&res[(size_t)row*N+col]; o.x+=rv.x;o.y+=rv.y;}
                if(ACT==1){o.x=gelu_e(o.x);o.y=gelu_e(o.y);}
                if(OUT==0){
                    *(float2*)&C[(size_t)row*N+col]=o;
                }else{
                    uint32_t lo,hi=packhi(o.x,o.y,lo);
                    *(uint32_t*)&Ch[(size_t)row*N+col]=hi;
                    *(uint32_t*)&Cl[(size_t)row*N+col]=lo;
                }
            }
        }
}

// ================= fused flash attention: per (b,h,128q) CTA =====================
// smem: Qh 0, Ql 16K, stages at 32K: per stage Kh 0, Kl 8K, Vh 16K, Vl 24K (32K/stage)
#define FLSM (32768 + 2*32768)
__global__ void __launch_bounds__(256,2)
flash_k(const bf16* __restrict__ qkvh,const bf16* __restrict__ qkvl,
        const float* __restrict__ pbias,const long long* __restrict__ ts,
        bf16* __restrict__ Ch,bf16* __restrict__ Cl){
    extern __shared__ char sm[];
    uint32_t sb=(uint32_t)__cvta_generic_to_shared(sm);
    const int tid=threadIdx.x, wid=tid>>5, lane=tid&31;
    const int bh=blockIdx.y, b=bh>>3, h=bh&7;
    const int q0=blockIdx.x*128;
    const int wm=wid*16;
    const int arow=lane&15, ah8=lane>>4, r4=lane>>2, j2=(lane&3)*2;

    // load Q hi/lo (128 rows x 64 dh)
    #pragma unroll
    for(int i=0;i<8;i++){
        int id=i*256+tid;
        int reg=id>>10, rid=id&1023, row=rid>>3, c=rid&7;
        const bf16* src=(reg?qkvl:qkvh)+(size_t)(b*Ss+q0+row)*1536+h*DH+c*8;
        cp16(sb+reg*16384+row*128+((c^(row&7))*16),src);
    }
    CPC();

    auto loadkv=[&](int st,int k0){
        #pragma unroll
        for(int i=0;i<8;i++){
            int id=i*256+tid;
            int part=id>>9, rid=id&511, row=rid>>3, c=rid&7;
            int colb=(part<2)?(Dd+h*DH):(2*Dd+h*DH);
            const bf16* src=((part&1)?qkvl:qkvh)+(size_t)(b*Ss+k0+row)*1536+colb+c*8;
            cp16(sb+32768+st*32768+part*8192+row*128+((c^(row&7))*16),src);
        }
        CPC();
    };
    loadkv(0,0); loadkv(1,64);

    float m0_=-1e30f, m1_=-1e30f, l0_=0.0f, l1_=0.0f;
    float oacc[8][4];
    #pragma unroll
    for(int i=0;i<8;i++){oacc[i][0]=0;oacc[i][1]=0;oacc[i][2]=0;oacc[i][3]=0;}
    const long long tq0=ts[b*Ss+q0+wm+r4], tq1=ts[b*Ss+q0+wm+r4+8];
    const int qi0=q0+wm+r4, qi1=qi0+8;

    for(int t=0;t<8;t++){
        uint32_t stv=sb+32768+(t&1)*32768;
        if(t<6) asm volatile("cp.async.wait_group 1;":::"memory");
        else    asm volatile("cp.async.wait_group 0;":::"memory");
        __syncthreads();

        float sacc[8][4];
        #pragma unroll
        for(int i=0;i<8;i++){sacc[i][0]=0;sacc[i][1]=0;sacc[i][2]=0;sacc[i][3]=0;}
        // S = Q@K^T (3-term split)
        #pragma unroll
        for(int kt=0;kt<4;kt++){
            uint32_t qh_[4],ql_[4];
            {
                int row=wm+arow;
                uint32_t ad=sb+row*128+(((kt*2+ah8)^(row&7))*16);
                LDSM4(qh_[0],qh_[1],qh_[2],qh_[3],ad);
                LDSM4(ql_[0],ql_[1],ql_[2],ql_[3],ad+16384);
            }
            #pragma unroll
            for(int nq=0;nq<4;nq++){
                int row=nq*16+arow;
                uint32_t ad=stv+row*128+(((kt*2+ah8)^(row&7))*16);
                uint32_t kh_[4],kl_[4];
                LDSM4(kh_[0],kh_[1],kh_[2],kh_[3],ad);
                LDSM4(kl_[0],kl_[1],kl_[2],kl_[3],ad+8192);
                #pragma unroll
                for(int p=0;p<2;p++){
                    int nt=nq*2+p;
                    MMA(sacc[nt],qh_,kh_[p],kh_[p+2]);
                    MMA(sacc[nt],qh_,kl_[p],kl_[p+2]);
                    MMA(sacc[nt],ql_,kh_[p],kh_[p+2]);
                }
            }
        }
        // scale + pbias
        int k0=t*64;
        #pragma unroll
        for(int nt=0;nt<8;nt++){
            int kc=k0+nt*8+j2;
            long long tk0=ts[b*Ss+kc], tk1=ts[b*Ss+kc+1];
            {
                float2 pb=*(const float2*)&pbias[((size_t)(h*Ss+qi0))*Ss+kc];
                float la=(float)(tq0-tk0)*(1.0f/60000.0f);
                float lb=(float)(tq0-tk1)*(1.0f/60000.0f);
                sacc[nt][0]=sacc[nt][0]/(9.0f-1.0f/(fmaxf(la,0.0f)+1.0f))+pb.x;
                sacc[nt][1]=sacc[nt][1]/(9.0f-1.0f/(fmaxf(lb,0.0f)+1.0f))+pb.y;
            }
            {
                float2 pb=*(const float2*)&pbias[((size_t)(h*Ss+qi1))*Ss+kc];
                float la=(float)(tq1-tk0)*(1.0f/60000.0f);
                float lb=(float)(tq1-tk1)*(1.0f/60000.0f);
                sacc[nt][2]=sacc[nt][2]/(9.0f-1.0f/(fmaxf(la,0.0f)+1.0f))+pb.x;
                sacc[nt][3]=sacc[nt][3]/(9.0f-1.0f/(fmaxf(lb,0.0f)+1.0f))+pb.y;
            }
        }
        // online softmax
        float tm0=-1e30f, tm1=-1e30f;
        #pragma unroll
        for(int nt=0;nt<8;nt++){
            tm0=fmaxf(tm0,fmaxf(sacc[nt][0],sacc[nt][1]));
            tm1=fmaxf(tm1,fmaxf(sacc[nt][2],sacc[nt][3]));
        }
        tm0=fmaxf(tm0,__shfl_xor_sync(0xffffffffu,tm0,1));
        tm0=fmaxf(tm0,__shfl_xor_sync(0xffffffffu,tm0,2));
        tm1=fmaxf(tm1,__shfl_xor_sync(0xffffffffu,tm1,1));
        tm1=fmaxf(tm1,__shfl_xor_sync(0xffffffffu,tm1,2));
        float mn0=fmaxf(m0_,tm0), mn1=fmaxf(m1_,tm1);
        float al0=__expf(m0_-mn0), al1=__expf(m1_-mn1);
        m0_=mn0; m1_=mn1;
        float s0=0.0f, s1=0.0f;
        #pragma unroll
        for(int nt=0;nt<8;nt++){
            sacc[nt][0]=__expf(sacc[nt][0]-mn0); s0+=sacc[nt][0];
            sacc[nt][1]=__expf(sacc[nt][1]-mn0); s0+=sacc[nt][1];
            sacc[nt][2]=__expf(sacc[nt][2]-mn1); s1+=sacc[nt][2];
            sacc[nt][3]=__expf(sacc[nt][3]-mn1); s1+=sacc[nt][3];
        }
        s0+=__shfl_xor_sync(0xffffffffu,s0,1); s0+=__shfl_xor_sync(0xffffffffu,s0,2);
        s1+=__shfl_xor_sync(0xffffffffu,s1,1); s1+=__shfl_xor_sync(0xffffffffu,s1,2);
        l0_=l0_*al0+s0; l1_=l1_*al1+s1;
        #pragma unroll
        for(int nt=0;nt<8;nt++){
            oacc[nt][0]*=al0; oacc[nt][1]*=al0;
            oacc[nt][2]*=al1; oacc[nt][3]*=al1;
        }
        // pack P to A-fragments (hi/lo)
        uint32_t ph_[4][4], pl_[4][4];
        #pragma unroll
        for(int kt=0;kt<4;kt++){
            ph_[kt][0]=packhi(sacc[2*kt][0],  sacc[2*kt][1],  pl_[kt][0]);
            ph_[kt][1]=packhi(sacc[2*kt][2],  sacc[2*kt][3],  pl_[kt][1]);
            ph_[kt][2]=packhi(sacc[2*kt+1][0],sacc[2*kt+1][1],pl_[kt][2]);
            ph_[kt][3]=packhi(sacc[2*kt+1][2],sacc[2*kt+1][3],pl_[kt][3]);
        }
        // O += P@V (V via ldmatrix.trans)
        #pragma unroll
        for(int kt=0;kt<4;kt++){
            #pragma unroll
            for(int dg=0;dg<4;dg++){
                int row=kt*16+((lane>>3)&1)*8+(lane&7);
                int ch_=dg*2+(lane>>4);
                uint32_t ad=stv+16384+row*128+((ch_^(row&7))*16);
                uint32_t vh_[4],vl_[4];
                LDSM4T(vh_[0],vh_[1],vh_[2],vh_[3],ad);
                LDSM4T(vl_[0],vl_[1],vl_[2],vl_[3],ad+8192);
                #pragma unroll
                for(int p=0;p<2;p++){
                    int nt=dg*2+p;
                    MMA(oacc[nt],ph_[kt],vh_[p*2],vh_[p*2+1]);
                    MMA(oacc[nt],ph_[kt],vl_[p*2],vl_[p*2+1]);
                    MMA(oacc[nt],pl_[kt],vh_[p*2],vh_[p*2+1]);
                }
            }
        }
        __syncthreads();
        if(t<6) loadkv(t&1,(t+2)*64);
    }
    // normalize + write ctx bf16 hi/lo [s,d]
    float inv0=1.0f/l0_, inv1=1.0f/l1_;
    #pragma unroll
    for(int nt=0;nt<8;nt++){
        int dh=nt*8+j2;
        {
            size_t idx=((size_t)(b*Ss+qi0))*Dd+h*DH+dh;
            uint32_t lo,hi=packhi(oacc[nt][0]*inv0,oacc[nt][1]*inv0,lo);
            *(uint32_t*)&Ch[idx]=hi; *(uint32_t*)&Cl[idx]=lo;
        }
        {
            size_t idx=((size_t)(b*Ss+qi1))*Dd+h*DH+dh;
            uint32_t lo,hi=packhi(oacc[nt][2]*inv1,oacc[nt][3]*inv1,lo);
            *(uint32_t*)&Ch[idx]=hi; *(uint32_t*)&Cl[idx]=lo;
        }
    }
}

// ================= LayerNorm: fp32 out + bf16 hi/lo out ========================
__global__ void ln_k(const float* __restrict__ in,const float* __restrict__ g,
                     const float* __restrict__ bt,float* __restrict__ out,
                     bf16* __restrict__ oh,bf16* __restrict__ ol){
    const size_t row=blockIdx.x;
    const int tid=threadIdx.x, lane=tid&31, wid=tid>>5;
    __shared__ float red[4];
    float4 v=*(const float4*)&in[row*Dd+tid*4];
    float s=v.x+v.y+v.z+v.w;
    #pragma unroll
    for(int o=16;o;o>>=1)s+=__shfl_xor_sync(0xffffffffu,s,o);
    if(lane==0)red[wid]=s;
    __syncthreads();
    float mu=(red[0]+red[1]+red[2]+red[3])*(1.0f/512.0f);
    __syncthreads();
    float dx=v.x-mu,dy=v.y-mu,dz=v.z-mu,dw=v.w-mu;
    float s2=dx*dx+dy*dy+dz*dz+dw*dw;
    #pragma unroll
    for(int o=16;o;o>>=1)s2+=__shfl_xor_sync(0xffffffffu,s2,o);
    if(lane==0)red[wid]=s2;
    __syncthreads();
    float var=(red[0]+red[1]+red[2]+red[3])*(1.0f/512.0f);
    float inv=rsqrtf(var+1e-12f);
    float4 gv=*(const float4*)&g[tid*4];
    float4 bv=*(const float4*)&bt[tid*4];
    float4 o;
    o.x=dx*inv*gv.x+bv.x; o.y=dy*inv*gv.y+bv.y;
    o.z=dz*inv*gv.z+bv.z; o.w=dw*inv*gv.w+bv.w;
    *(float4*)&out[row*Dd+tid*4]=o;
    uint32_t lo0,hi0=packhi(o.x,o.y,lo0);
    uint32_t lo1,hi1=packhi(o.z,o.w,lo1);
    ((uint32_t*)(oh+row*Dd+tid*4))[0]=hi0; ((uint32_t*)(oh+row*Dd+tid*4))[1]=hi1;
    ((uint32_t*)(ol+row*Dd+tid*4))[0]=lo0; ((uint32_t*)(ol+row*Dd+tid*4))[1]=lo1;
}

__global__ void split_k(const float* __restrict__ s,bf16* __restrict__ hi,
                        bf16* __restrict__ lo,int n4){
    int i=blockIdx.x*256+threadIdx.x;
    if(i>=n4)return;
    float4 v=((const float4*)s)[i];
    uint32_t lo0,hi0=packhi(v.x,v.y,lo0);
    uint32_t lo1,hi1=packhi(v.z,v.w,lo1);
    ((uint32_t*)hi)[i*2+0]=hi0; ((uint32_t*)hi)[i*2+1]=hi1;
    ((uint32_t*)lo)[i*2+0]=lo0; ((uint32_t*)lo)[i*2+1]=lo1;
}

__global__ void tsplit_k(const float* __restrict__ W,bf16* __restrict__ hi,
                         bf16* __restrict__ lo,int K,int N){
    __shared__ float t[32][33];
    int n=blockIdx.x*32+threadIdx.x, k0=blockIdx.y*32;
    for(int j=threadIdx.y;j<32;j+=8) t[j][threadIdx.x]=W[(size_t)(k0+j)*N+n];
    __syncthreads();
    int k=k0+threadIdx.x, n0=blockIdx.x*32;
    for(int j=threadIdx.y;j<32;j+=8){
        float v=t[threadIdx.x][j];
        bf16 h,l; wsplit(v,h,l);
        hi[(size_t)(n0+j)*K+k]=h;
        lo[(size_t)(n0+j)*K+k]=l;
    }
}

__global__ void catb_k(const float* bq,const float* bk,const float* bv,float* o){
    int i=blockIdx.x*256+threadIdx.x;
    if(i>=Ll*3*Dd)return;
    int l=i/(3*Dd), r=i%(3*Dd);
    o[i]= r<Dd ? bq[l*Dd+r] : (r<2*Dd ? bk[l*Dd+r-Dd] : bv[l*Dd+r-2*Dd]);
}

extern "C" void kernel_launch(void* const* d_in, const int* in_sizes, int n_in,
                              void* d_out, int out_size){
    const float* hidden=(const float*)d_in[0];
    const float* pbias=(const float*)d_in[1];
    const long long* ts=(const long long*)d_in[2];
    const float* Wq=(const float*)d_in[3];  const float* bq=(const float*)d_in[4];
    const float* Wk=(const float*)d_in[5];  const float* bk=(const float*)d_in[6];
    const float* Wv=(const float*)d_in[7];  const float* bv=(const float*)d_in[8];
    const float* Wo=(const float*)d_in[9];  const float* bo=(const float*)d_in[10];
    const float* l1g=(const float*)d_in[11];const float* l1b=(const float*)d_in[12];
    const float* Wi=(const float*)d_in[13]; const float* bi=(const float*)d_in[14];
    const float* Wf=(const float*)d_in[15]; const float* bfp=(const float*)d_in[16];
    const float* l2g=(const float*)d_in[17];const float* l2b=(const float*)d_in[18];

    float *px,*pattn,*ptmp,*pcatb;
    cudaGetSymbolAddress((void**)&px,g_x);     cudaGetSymbolAddress((void**)&pattn,g_attn);
    cudaGetSymbolAddress((void**)&ptmp,g_tmp); cudaGetSymbolAddress((void**)&pcatb,g_catb);
    bf16 *xh,*xl,*qkh,*qkl,*ch,*cl,*ah,*al,*fh,*fl,*wh,*wl;
    cudaGetSymbolAddress((void**)&xh,g_xh);   cudaGetSymbolAddress((void**)&xl,g_xl);
    cudaGetSymbolAddress((void**)&qkh,g_qkvh);cudaGetSymbolAddress((void**)&qkl,g_qkvl);
    cudaGetSymbolAddress((void**)&ch,g_ch);   cudaGetSymbolAddress((void**)&cl,g_cl);
    cudaGetSymbolAddress((void**)&ah,g_ah);   cudaGetSymbolAddress((void**)&al,g_al);
    cudaGetSymbolAddress((void**)&fh,g_fh);   cudaGetSymbolAddress((void**)&fl,g_fl);
    cudaGetSymbolAddress((void**)&wh,g_wh);   cudaGetSymbolAddress((void**)&wl,g_wl);

    cudaFuncSetAttribute(gemm_mma<0,false,1>,cudaFuncAttributeMaxDynamicSharedMemorySize,GSMEM);
    cudaFuncSetAttribute(gemm_mma<0,true,0>, cudaFuncAttributeMaxDynamicSharedMemorySize,GSMEM);
    cudaFuncSetAttribute(gemm_mma<1,false,1>,cudaFuncAttributeMaxDynamicSharedMemorySize,GSMEM);
    cudaFuncSetAttribute(flash_k,cudaFuncAttributeMaxDynamicSharedMemorySize,FLSM);

    const size_t LW=(size_t)(4*Dd*Dd+2*Dd*Ff);
    catb_k<<<(Ll*3*Dd+255)/256,256>>>(bq,bk,bv,pcatb);
    for(int l=0;l<Ll;l++){
        bf16* bh_=wh+l*LW; bf16* bl_=wl+l*LW;
        dim3 tb(32,8);
        tsplit_k<<<dim3(Dd/32,Dd/32),tb>>>(Wq+(size_t)l*Dd*Dd,bh_,         bl_,         Dd,Dd);
        tsplit_k<<<dim3(Dd/32,Dd/32),tb>>>(Wk+(size_t)l*Dd*Dd,bh_+Dd*Dd,   bl_+Dd*Dd,   Dd,Dd);
        tsplit_k<<<dim3(Dd/32,Dd/32),tb>>>(Wv+(size_t)l*Dd*Dd,bh_+2*Dd*Dd, bl_+2*Dd*Dd, Dd,Dd);
        tsplit_k<<<dim3(Dd/32,Dd/32),tb>>>(Wo+(size_t)l*Dd*Dd,bh_+3*Dd*Dd, bl_+3*Dd*Dd, Dd,Dd);
        tsplit_k<<<dim3(Ff/32,Dd/32),tb>>>(Wi+(size_t)l*Dd*Ff,bh_+4*Dd*Dd, bl_+4*Dd*Dd, Dd,Ff);
        tsplit_k<<<dim3(Dd/32,Ff/32),tb>>>(Wf+(size_t)l*Ff*Dd,bh_+4*Dd*Dd+(size_t)Dd*Ff,bl_+4*Dd*Dd+(size_t)Dd*Ff,Ff,Dd);
    }

    const dim3 gDD(Dd/128,Mrows/128), gQKV(3*Dd/128,Mrows/128), gDF(Ff/128,Mrows/128);
    const int nD4=Mrows*Dd/4;
    split_k<<<(nD4+255)/256,256>>>(hidden,xh,xl,nD4);

    const float* X=hidden;
    for(int l=0;l<Ll;l++){
        bf16* bh_=wh+l*LW; bf16* bl_=wl+l*LW;
        bf16* wih=bh_+4*Dd*Dd; bf16* wil=bl_+4*Dd*Dd;
        bf16* wfh=wih+(size_t)Dd*Ff; bf16* wfl=wil+(size_t)Dd*Ff;

        gemm_mma<0,false,1><<<gQKV,256,GSMEM>>>(xh,xl,bh_,bl_,pcatb+l*3*Dd,nullptr,nullptr,qkh,qkl,3*Dd,Dd);
        flash_k<<<dim3(4,Bb*Hh),256,FLSM>>>(qkh,qkl,pbias,ts,ch,cl);

        gemm_mma<0,true,0><<<gDD,256,GSMEM>>>(ch,cl,bh_+3*Dd*Dd,bl_+3*Dd*Dd,bo+l*Dd,X,ptmp,nullptr,nullptr,Dd,Dd);
        ln_k<<<Mrows,128>>>(ptmp,l1g+l*Dd,l1b+l*Dd,pattn,ah,al);

        gemm_mma<1,false,1><<<gDF,256,GSMEM>>>(ah,al,wih,wil,bi+l*Ff,nullptr,nullptr,fh,fl,Ff,Dd);
        gemm_mma<0,true,0><<<gDD,256,GSMEM>>>(fh,fl,wfh,wfl,bfp+l*Dd,pattn,ptmp,nullptr,nullptr,Dd,Ff);
        ln_k<<<Mrows,128>>>(ptmp,l2g+l*Dd,l2b+l*Dd,px,xh,xl);
        X=px;
    }
    cudaMemcpyAsync(d_out,px,(size_t)Mrows*Dd*sizeof(float),cudaMemcpyDeviceToDevice,0);
}

// round 8
// speedup vs baseline: 2.4751x; 1.0043x over previous
#include <cuda_runtime.h>
#include <cuda_bf16.h>
#include <math.h>
#include <stdint.h>

#define Bb 32
#define Ss 512
#define Dd 512
#define Hh 8
#define Ff 2048
#define Ll 4
#define DH 64
#define Mrows (Bb*Ss)
#define LWc ((size_t)(4*Dd*Dd+2*Dd*Ff))

typedef __nv_bfloat16 bf16;
typedef __nv_bfloat162 bf162;

__device__ float g_x[Mrows*Dd];
__device__ float g_attn[Mrows*Dd];
__device__ float g_tmp[Mrows*Dd];
__device__ bf16 g_xh[Mrows*Dd], g_xl[Mrows*Dd];
__device__ bf16 g_qkvh[(size_t)Mrows*3*Dd], g_qkvl[(size_t)Mrows*3*Dd];
__device__ bf16 g_ch[Mrows*Dd], g_cl[Mrows*Dd];
__device__ bf16 g_ah[Mrows*Dd], g_al[Mrows*Dd];
__device__ bf16 g_fh[(size_t)Mrows*Ff], g_fl[(size_t)Mrows*Ff];
__device__ bf16 g_wh[Ll*LWc];
__device__ bf16 g_wl[Ll*LWc];
__device__ float g_catb[Ll*3*Dd];

__device__ __forceinline__ float gelu_e(float x){return 0.5f*x*(1.0f+erff(x*0.70710678118654752f));}
__device__ __forceinline__ void cp16(uint32_t d,const void* s){
    asm volatile("cp.async.cg.shared.global [%0], [%1], 16;"::"r"(d),"l"(s));
}
#define CPC() asm volatile("cp.async.commit_group;":::"memory")
#define LDSM4(r0,r1,r2,r3,a) asm volatile("ldmatrix.sync.aligned.m8n8.x4.shared.b16 {%0,%1,%2,%3},[%4];":"=r"(r0),"=r"(r1),"=r"(r2),"=r"(r3):"r"(a))
#define LDSM4T(r0,r1,r2,r3,a) asm volatile("ldmatrix.sync.aligned.m8n8.x4.trans.shared.b16 {%0,%1,%2,%3},[%4];":"=r"(r0),"=r"(r1),"=r"(r2),"=r"(r3):"r"(a))
#define MMA(d,a,b0,b1) asm volatile( \
    "mma.sync.aligned.m16n8k16.row.col.f32.bf16.bf16.f32 {%0,%1,%2,%3},{%4,%5,%6,%7},{%8,%9},{%0,%1,%2,%3};" \
    :"+f"((d)[0]),"+f"((d)[1]),"+f"((d)[2]),"+f"((d)[3]) \
    :"r"((a)[0]),"r"((a)[1]),"r"((a)[2]),"r"((a)[3]),"r"(b0),"r"(b1))

__device__ __forceinline__ void wsplit(float v, bf16& h, bf16& l){
    h=__float2bfloat16(v); l=__float2bfloat16(v-__bfloat162float(h));
}
__device__ __forceinline__ uint32_t packhi(float a,float b,uint32_t& lo){
    bf16 h0,l0,h1,l1; wsplit(a,h0,l0); wsplit(b,h1,l1);
    bf162 L=__halves2bfloat162(l0,l1); lo=*(uint32_t*)&L;
    bf162 H=__halves2bfloat162(h0,h1); return *(uint32_t*)&H;
}

// ======================= projection/FFN GEMM: 3-stage pipeline ====================
#define STB2 32768
#define GSMEM (3*STB2)
__device__ __forceinline__ void load_stage(uint32_t st,int tid,
    const bf16* Ah,const bf16* Al,const bf16* Bh,const bf16* Bl,
    int m0,int n0,int k0,int K){
    #pragma unroll
    for(int i=0;i<8;i++){
        int id=i*256+tid;
        int reg=id>>9, rid=id&511, row=rid>>2, c=rid&3;
        const bf16* src;
        if(reg==0)      src=Ah+(size_t)(m0+row)*K+k0+c*8;
        else if(reg==1) src=Al+(size_t)(m0+row)*K+k0+c*8;
        else if(reg==2) src=Bh+(size_t)(n0+row)*K+k0+c*8;
        else            src=Bl+(size_t)(n0+row)*K+k0+c*8;
        cp16(st+reg*8192+row*64+((c^((row>>1)&3))*16),src);
    }
    CPC();
}

template<int ACT, bool RES, int OUT>
__global__ void __launch_bounds__(256,2)
gemm_mma(const bf16* __restrict__ Ah,const bf16* __restrict__ Al,
         const bf16* __restrict__ Bh,const bf16* __restrict__ Bl,
         const float* __restrict__ bias,const float* __restrict__ res,
         float* __restrict__ C,bf16* __restrict__ Ch,bf16* __restrict__ Cl,
         int N,int K){
    extern __shared__ char sm[];
    uint32_t sb=(uint32_t)__cvta_generic_to_shared(sm);
    const int tid=threadIdx.x, wid=tid>>5, lane=tid&31;
    const int n0=blockIdx.x*128, m0=blockIdx.y*128;
    const int wm=(wid>>2)*64, wn=(wid&3)*32;
    const int chunks=K>>5;
    float acc[4][4][4];
    #pragma unroll
    for(int i=0;i<4;i++)
        #pragma unroll
        for(int j=0;j<4;j++){acc[i][j][0]=0;acc[i][j][1]=0;acc[i][j][2]=0;acc[i][j][3]=0;}
    load_stage(sb,tid,Ah,Al,Bh,Bl,m0,n0,0,K);
    load_stage(sb+STB2,tid,Ah,Al,Bh,Bl,m0,n0,32,K);
    const int arow=lane&15, ah8=lane>>4;
    int s2=2;  // next stage slot to fill
    for(int c=0;c<chunks;c++){
        uint32_t st=sb+(c%3)*STB2;
        if(c<chunks-1) asm volatile("cp.async.wait_group 1;":::"memory");
        else           asm volatile("cp.async.wait_group 0;":::"memory");
        __syncthreads();
        if(c+2<chunks){
            load_stage(sb+s2*STB2,tid,Ah,Al,Bh,Bl,m0,n0,(c+2)*32,K);
            s2++; if(s2==3)s2=0;
        }
        #pragma unroll
        for(int s=0;s<2;s++){
            uint32_t ahf[4][4],alf[4][4],bhf[2][4],blf[2][4];
            #pragma unroll
            for(int mi=0;mi<4;mi++){
                int row=wm+mi*16+arow;
                uint32_t ad=st+row*64+(((s*2+ah8)^((row>>1)&3))*16);
                LDSM4(ahf[mi][0],ahf[mi][1],ahf[mi][2],ahf[mi][3],ad);
                LDSM4(alf[mi][0],alf[mi][1],alf[mi][2],alf[mi][3],ad+8192);
            }
            #pragma unroll
            for(int nq=0;nq<2;nq++){
                int row=wn+nq*16+arow;
                uint32_t ad=st+16384+row*64+(((s*2+ah8)^((row>>1)&3))*16);
                LDSM4(bhf[nq][0],bhf[nq][1],bhf[nq][2],bhf[nq][3],ad);
                LDSM4(blf[nq][0],blf[nq][1],blf[nq][2],blf[nq][3],ad+8192);
            }
            #pragma unroll
            for(int mi=0;mi<4;mi++)
                #pragma unroll
                for(int nq=0;nq<2;nq++)
                    #pragma unroll
                    for(int p=0;p<2;p++){
                        int nt=nq*2+p;
                        MMA(acc[mi][nt],ahf[mi],bhf[nq][p],bhf[nq][p+2]);
                        MMA(acc[mi][nt],ahf[mi],blf[nq][p],blf[nq][p+2]);
                        MMA(acc[mi][nt],alf[mi],bhf[nq][p],bhf[nq][p+2]);
                    }
        }
    }
    const int r4=lane>>2, c2=(lane&3)*2;
    #pragma unroll
    for(int mi=0;mi<4;mi++)
        #pragma unroll
        for(int nt=0;nt<4;nt++){
            int col=n0+wn+nt*8+c2;
            float2 bv=*(const float2*)&bias[col];
            #pragma unroll
            for(int hr=0;hr<2;hr++){
                int row=m0+wm+mi*16+r4+hr*8;
                float2 o;
                o.x=acc[mi][nt][hr*2+0]+bv.x;
                o.y=acc[mi][nt][hr*2+1]+bv.y;
                if(RES){float2 rv=*(const float2*)&res[(size_t)row*N+col]; o.x+=rv.x;o.y+=rv.y;}
                if(ACT==1){o.x=gelu_e(o.x);o.y=gelu_e(o.y);}
                if(OUT==0){
                    *(float2*)&C[(size_t)row*N+col]=o;
                }else{
                    uint32_t lo,hi=packhi(o.x,o.y,lo);
                    *(uint32_t*)&Ch[(size_t)row*N+col]=hi;
                    *(uint32_t*)&Cl[(size_t)row*N+col]=lo;
                }
            }
        }
}

// ================= fused flash attention: per (b,h,128q) CTA =====================
#define FLSM (32768 + 2*32768)
__global__ void __launch_bounds__(256,2)
flash_k(const bf16* __restrict__ qkvh,const bf16* __restrict__ qkvl,
        const float* __restrict__ pbias,const long long* __restrict__ ts,
        bf16* __restrict__ Ch,bf16* __restrict__ Cl){
    extern __shared__ char sm[];
    uint32_t sb=(uint32_t)__cvta_generic_to_shared(sm);
    const int tid=threadIdx.x, wid=tid>>5, lane=tid&31;
    const int bh=blockIdx.y, b=bh>>3, h=bh&7;
    const int q0=blockIdx.x*128;
    const int wm=wid*16;
    const int arow=lane&15, ah8=lane>>4, r4=lane>>2, j2=(lane&3)*2;

    #pragma unroll
    for(int i=0;i<8;i++){
        int id=i*256+tid;
        int reg=id>>10, rid=id&1023, row=rid>>3, c=rid&7;
        const bf16* src=(reg?qkvl:qkvh)+(size_t)(b*Ss+q0+row)*1536+h*DH+c*8;
        cp16(sb+reg*16384+row*128+((c^(row&7))*16),src);
    }
    CPC();

    auto loadkv=[&](int st,int k0){
        #pragma unroll
        for(int i=0;i<8;i++){
            int id=i*256+tid;
            int part=id>>9, rid=id&511, row=rid>>3, c=rid&7;
            int colb=(part<2)?(Dd+h*DH):(2*Dd+h*DH);
            const bf16* src=((part&1)?qkvl:qkvh)+(size_t)(b*Ss+k0+row)*1536+colb+c*8;
            cp16(sb+32768+st*32768+part*8192+row*128+((c^(row&7))*16),src);
        }
        CPC();
    };
    loadkv(0,0); loadkv(1,64);

    float m0_=-1e30f, m1_=-1e30f, l0_=0.0f, l1_=0.0f;
    float oacc[8][4];
    #pragma unroll
    for(int i=0;i<8;i++){oacc[i][0]=0;oacc[i][1]=0;oacc[i][2]=0;oacc[i][3]=0;}
    const long long tq0=ts[b*Ss+q0+wm+r4], tq1=ts[b*Ss+q0+wm+r4+8];
    const int qi0=q0+wm+r4, qi1=qi0+8;

    for(int t=0;t<8;t++){
        uint32_t stv=sb+32768+(t&1)*32768;
        if(t<6) asm volatile("cp.async.wait_group 1;":::"memory");
        else    asm volatile("cp.async.wait_group 0;":::"memory");
        __syncthreads();

        float sacc[8][4];
        #pragma unroll
        for(int i=0;i<8;i++){sacc[i][0]=0;sacc[i][1]=0;sacc[i][2]=0;sacc[i][3]=0;}
        #pragma unroll
        for(int kt=0;kt<4;kt++){
            uint32_t qh_[4],ql_[4];
            {
                int row=wm+arow;
                uint32_t ad=sb+row*128+(((kt*2+ah8)^(row&7))*16);
                LDSM4(qh_[0],qh_[1],qh_[2],qh_[3],ad);
                LDSM4(ql_[0],ql_[1],ql_[2],ql_[3],ad+16384);
            }
            #pragma unroll
            for(int nq=0;nq<4;nq++){
                int row=nq*16+arow;
                uint32_t ad=stv+row*128+(((kt*2+ah8)^(row&7))*16);
                uint32_t kh_[4],kl_[4];
                LDSM4(kh_[0],kh_[1],kh_[2],kh_[3],ad);
                LDSM4(kl_[0],kl_[1],kl_[2],kl_[3],ad+8192);
                #pragma unroll
                for(int p=0;p<2;p++){
                    int nt=nq*2+p;
                    MMA(sacc[nt],qh_,kh_[p],kh_[p+2]);
                    MMA(sacc[nt],qh_,kl_[p],kl_[p+2]);
                    MMA(sacc[nt],ql_,kh_[p],kh_[p+2]);
                }
            }
        }
        int k0=t*64;
        #pragma unroll
        for(int nt=0;nt<8;nt++){
            int kc=k0+nt*8+j2;
            long long tk0=ts[b*Ss+kc], tk1=ts[b*Ss+kc+1];
            {
                float2 pb=*(const float2*)&pbias[((size_t)(h*Ss+qi0))*Ss+kc];
                float la=(float)(tq0-tk0)*(1.0f/60000.0f);
                float lb=(float)(tq0-tk1)*(1.0f/60000.0f);
                sacc[nt][0]=sacc[nt][0]/(9.0f-1.0f/(fmaxf(la,0.0f)+1.0f))+pb.x;
                sacc[nt][1]=sacc[nt][1]/(9.0f-1.0f/(fmaxf(lb,0.0f)+1.0f))+pb.y;
            }
            {
                float2 pb=*(const float2*)&pbias[((size_t)(h*Ss+qi1))*Ss+kc];
                float la=(float)(tq1-tk0)*(1.0f/60000.0f);
                float lb=(float)(tq1-tk1)*(1.0f/60000.0f);
                sacc[nt][2]=sacc[nt][2]/(9.0f-1.0f/(fmaxf(la,0.0f)+1.0f))+pb.x;
                sacc[nt][3]=sacc[nt][3]/(9.0f-1.0f/(fmaxf(lb,0.0f)+1.0f))+pb.y;
            }
        }
        float tm0=-1e30f, tm1=-1e30f;
        #pragma unroll
        for(int nt=0;nt<8;nt++){
            tm0=fmaxf(tm0,fmaxf(sacc[nt][0],sacc[nt][1]));
            tm1=fmaxf(tm1,fmaxf(sacc[nt][2],sacc[nt][3]));
        }
        tm0=fmaxf(tm0,__shfl_xor_sync(0xffffffffu,tm0,1));
        tm0=fmaxf(tm0,__shfl_xor_sync(0xffffffffu,tm0,2));
        tm1=fmaxf(tm1,__shfl_xor_sync(0xffffffffu,tm1,1));
        tm1=fmaxf(tm1,__shfl_xor_sync(0xffffffffu,tm1,2));
        float mn0=fmaxf(m0_,tm0), mn1=fmaxf(m1_,tm1);
        float al0=__expf(m0_-mn0), al1=__expf(m1_-mn1);
        m0_=mn0; m1_=mn1;
        float s0=0.0f, s1=0.0f;
        #pragma unroll
        for(int nt=0;nt<8;nt++){
            sacc[nt][0]=__expf(sacc[nt][0]-mn0); s0+=sacc[nt][0];
            sacc[nt][1]=__expf(sacc[nt][1]-mn0); s0+=sacc[nt][1];
            sacc[nt][2]=__expf(sacc[nt][2]-mn1); s1+=sacc[nt][2];
            sacc[nt][3]=__expf(sacc[nt][3]-mn1); s1+=sacc[nt][3];
        }
        s0+=__shfl_xor_sync(0xffffffffu,s0,1); s0+=__shfl_xor_sync(0xffffffffu,s0,2);
        s1+=__shfl_xor_sync(0xffffffffu,s1,1); s1+=__shfl_xor_sync(0xffffffffu,s1,2);
        l0_=l0_*al0+s0; l1_=l1_*al1+s1;
        #pragma unroll
        for(int nt=0;nt<8;nt++){
            oacc[nt][0]*=al0; oacc[nt][1]*=al0;
            oacc[nt][2]*=al1; oacc[nt][3]*=al1;
        }
        uint32_t ph_[4][4], pl_[4][4];
        #pragma unroll
        for(int kt=0;kt<4;kt++){
            ph_[kt][0]=packhi(sacc[2*kt][0],  sacc[2*kt][1],  pl_[kt][0]);
            ph_[kt][1]=packhi(sacc[2*kt][2],  sacc[2*kt][3],  pl_[kt][1]);
            ph_[kt][2]=packhi(sacc[2*kt+1][0],sacc[2*kt+1][1],pl_[kt][2]);
            ph_[kt][3]=packhi(sacc[2*kt+1][2],sacc[2*kt+1][3],pl_[kt][3]);
        }
        #pragma unroll
        for(int kt=0;kt<4;kt++){
            #pragma unroll
            for(int dg=0;dg<4;dg++){
                int row=kt*16+((lane>>3)&1)*8+(lane&7);
                int ch_=dg*2+(lane>>4);
                uint32_t ad=stv+16384+row*128+((ch_^(row&7))*16);
                uint32_t vh_[4],vl_[4];
                LDSM4T(vh_[0],vh_[1],vh_[2],vh_[3],ad);
                LDSM4T(vl_[0],vl_[1],vl_[2],vl_[3],ad+8192);
                #pragma unroll
                for(int p=0;p<2;p++){
                    int nt=dg*2+p;
                    MMA(oacc[nt],ph_[kt],vh_[p*2],vh_[p*2+1]);
                    MMA(oacc[nt],ph_[kt],vl_[p*2],vl_[p*2+1]);
                    MMA(oacc[nt],pl_[kt],vh_[p*2],vh_[p*2+1]);
                }
            }
        }
        __syncthreads();
        if(t<6) loadkv(t&1,(t+2)*64);
    }
    float inv0=1.0f/l0_, inv1=1.0f/l1_;
    #pragma unroll
    for(int nt=0;nt<8;nt++){
        int dh=nt*8+j2;
        {
            size_t idx=((size_t)(b*Ss+qi0))*Dd+h*DH+dh;
            uint32_t lo,hi=packhi(oacc[nt][0]*inv0,oacc[nt][1]*inv0,lo);
            *(uint32_t*)&Ch[idx]=hi; *(uint32_t*)&Cl[idx]=lo;
        }
        {
            size_t idx=((size_t)(b*Ss+qi1))*Dd+h*DH+dh;
            uint32_t lo,hi=packhi(oacc[nt][2]*inv1,oacc[nt][3]*inv1,lo);
            *(uint32_t*)&Ch[idx]=hi; *(uint32_t*)&Cl[idx]=lo;
        }
    }
}

// ================= LayerNorm: fp32 out + bf16 hi/lo out ========================
__global__ void ln_k(const float* __restrict__ in,const float* __restrict__ g,
                     const float* __restrict__ bt,float* __restrict__ out,
                     bf16* __restrict__ oh,bf16* __restrict__ ol){
    const size_t row=blockIdx.x;
    const int tid=threadIdx.x, lane=tid&31, wid=tid>>5;
    __shared__ float red[4];
    float4 v=*(const float4*)&in[row*Dd+tid*4];
    float s=v.x+v.y+v.z+v.w;
    #pragma unroll
    for(int o=16;o;o>>=1)s+=__shfl_xor_sync(0xffffffffu,s,o);
    if(lane==0)red[wid]=s;
    __syncthreads();
    float mu=(red[0]+red[1]+red[2]+red[3])*(1.0f/512.0f);
    __syncthreads();
    float dx=v.x-mu,dy=v.y-mu,dz=v.z-mu,dw=v.w-mu;
    float s2=dx*dx+dy*dy+dz*dz+dw*dw;
    #pragma unroll
    for(int o=16;o;o>>=1)s2+=__shfl_xor_sync(0xffffffffu,s2,o);
    if(lane==0)red[wid]=s2;
    __syncthreads();
    float var=(red[0]+red[1]+red[2]+red[3])*(1.0f/512.0f);
    float inv=rsqrtf(var+1e-12f);
    float4 gv=*(const float4*)&g[tid*4];
    float4 bv=*(const float4*)&bt[tid*4];
    float4 o;
    o.x=dx*inv*gv.x+bv.x; o.y=dy*inv*gv.y+bv.y;
    o.z=dz*inv*gv.z+bv.z; o.w=dw*inv*gv.w+bv.w;
    *(float4*)&out[row*Dd+tid*4]=o;
    uint32_t lo0,hi0=packhi(o.x,o.y,lo0);
    uint32_t lo1,hi1=packhi(o.z,o.w,lo1);
    ((uint32_t*)(oh+row*Dd+tid*4))[0]=hi0; ((uint32_t*)(oh+row*Dd+tid*4))[1]=hi1;
    ((uint32_t*)(ol+row*Dd+tid*4))[0]=lo0; ((uint32_t*)(ol+row*Dd+tid*4))[1]=lo1;
}

__global__ void split_k(const float* __restrict__ s,bf16* __restrict__ hi,
                        bf16* __restrict__ lo,int n4){
    int i=blockIdx.x*256+threadIdx.x;
    if(i>=n4)return;
    float4 v=((const float4*)s)[i];
    uint32_t lo0,hi0=packhi(v.x,v.y,lo0);
    uint32_t lo1,hi1=packhi(v.z,v.w,lo1);
    ((uint32_t*)hi)[i*2+0]=hi0; ((uint32_t*)hi)[i*2+1]=hi1;
    ((uint32_t*)lo)[i*2+0]=lo0; ((uint32_t*)lo)[i*2+1]=lo1;
}

// ======= single weight-prep kernel: transpose+split ALL matrices, all layers =====
__global__ void wprep_k(const float* __restrict__ Wq,const float* __restrict__ Wk,
                        const float* __restrict__ Wv,const float* __restrict__ Wo,
                        const float* __restrict__ Wi,const float* __restrict__ Wf,
                        bf16* __restrict__ wh,bf16* __restrict__ wl){
    __shared__ float t[32][33];
    int tile=blockIdx.x;
    int l=tile/3072, r=tile%3072;
    const float* src; size_t off; int K,N;
    if(r<1024){
        int m=r>>8; r&=255;
        src=(m==0?Wq:m==1?Wk:m==2?Wv:Wo)+(size_t)l*Dd*Dd;
        off=(size_t)m*Dd*Dd; K=Dd; N=Dd;
    }else if(r<2048){
        r-=1024; src=Wi+(size_t)l*Dd*Ff; off=4*Dd*Dd; K=Dd; N=Ff;
    }else{
        r-=2048; src=Wf+(size_t)l*Ff*Dd; off=4*Dd*Dd+(size_t)Dd*Ff; K=Ff; N=Dd;
    }
    bf16* dh=wh+(size_t)l*LWc+off;
    bf16* dl=wl+(size_t)l*LWc+off;
    int ntk=K>>5;
    int n0=(r/ntk)*32, k0=(r%ntk)*32;
    int x=threadIdx.x, y0=threadIdx.y;
    for(int j=y0;j<32;j+=8) t[j][x]=src[(size_t)(k0+j)*N+n0+x];
    __syncthreads();
    for(int j=y0;j<32;j+=8){
        float v=t[x][j];
        bf16 h,l2; wsplit(v,h,l2);
        dh[(size_t)(n0+j)*K+k0+x]=h;
        dl[(size_t)(n0+j)*K+k0+x]=l2;
    }
}

__global__ void catb_k(const float* bq,const float* bk,const float* bv,float* o){
    int i=blockIdx.x*256+threadIdx.x;
    if(i>=Ll*3*Dd)return;
    int l=i/(3*Dd), r=i%(3*Dd);
    o[i]= r<Dd ? bq[l*Dd+r] : (r<2*Dd ? bk[l*Dd+r-Dd] : bv[l*Dd+r-2*Dd]);
}

extern "C" void kernel_launch(void* const* d_in, const int* in_sizes, int n_in,
                              void* d_out, int out_size){
    const float* hidden=(const float*)d_in[0];
    const float* pbias=(const float*)d_in[1];
    const long long* ts=(const long long*)d_in[2];
    const float* Wq=(const float*)d_in[3];  const float* bq=(const float*)d_in[4];
    const float* Wk=(const float*)d_in[5];  const float* bk=(const float*)d_in[6];
    const float* Wv=(const float*)d_in[7];  const float* bv=(const float*)d_in[8];
    const float* Wo=(const float*)d_in[9];  const float* bo=(const float*)d_in[10];
    const float* l1g=(const float*)d_in[11];const float* l1b=(const float*)d_in[12];
    const float* Wi=(const float*)d_in[13]; const float* bi=(const float*)d_in[14];
    const float* Wf=(const float*)d_in[15]; const float* bfp=(const float*)d_in[16];
    const float* l2g=(const float*)d_in[17];const float* l2b=(const float*)d_in[18];

    float *px,*pattn,*ptmp,*pcatb;
    cudaGetSymbolAddress((void**)&px,g_x);     cudaGetSymbolAddress((void**)&pattn,g_attn);
    cudaGetSymbolAddress((void**)&ptmp,g_tmp); cudaGetSymbolAddress((void**)&pcatb,g_catb);
    bf16 *xh,*xl,*qkh,*qkl,*ch,*cl,*ah,*al,*fh,*fl,*wh,*wl;
    cudaGetSymbolAddress((void**)&xh,g_xh);   cudaGetSymbolAddress((void**)&xl,g_xl);
    cudaGetSymbolAddress((void**)&qkh,g_qkvh);cudaGetSymbolAddress((void**)&qkl,g_qkvl);
    cudaGetSymbolAddress((void**)&ch,g_ch);   cudaGetSymbolAddress((void**)&cl,g_cl);
    cudaGetSymbolAddress((void**)&ah,g_ah);   cudaGetSymbolAddress((void**)&al,g_al);
    cudaGetSymbolAddress((void**)&fh,g_fh);   cudaGetSymbolAddress((void**)&fl,g_fl);
    cudaGetSymbolAddress((void**)&wh,g_wh);   cudaGetSymbolAddress((void**)&wl,g_wl);

    cudaFuncSetAttribute(gemm_mma<0,false,1>,cudaFuncAttributeMaxDynamicSharedMemorySize,GSMEM);
    cudaFuncSetAttribute(gemm_mma<0,true,0>, cudaFuncAttributeMaxDynamicSharedMemorySize,GSMEM);
    cudaFuncSetAttribute(gemm_mma<1,false,1>,cudaFuncAttributeMaxDynamicSharedMemorySize,GSMEM);
    cudaFuncSetAttribute(flash_k,cudaFuncAttributeMaxDynamicSharedMemorySize,FLSM);

    // prep (3 launches total)
    wprep_k<<<Ll*3072,dim3(32,8)>>>(Wq,Wk,Wv,Wo,Wi,Wf,wh,wl);
    catb_k<<<(Ll*3*Dd+255)/256,256>>>(bq,bk,bv,pcatb);
    const int nD4=Mrows*Dd/4;
    split_k<<<(nD4+255)/256,256>>>(hidden,xh,xl,nD4);

    const dim3 gDD(Dd/128,Mrows/128), gQKV(3*Dd/128,Mrows/128), gDF(Ff/128,Mrows/128);
    const float* X=hidden;
    for(int l=0;l<Ll;l++){
        bf16* bh_=wh+(size_t)l*LWc; bf16* bl_=wl+(size_t)l*LWc;
        bf16* wih=bh_+4*Dd*Dd; bf16* wil=bl_+4*Dd*Dd;
        bf16* wfh=wih+(size_t)Dd*Ff; bf16* wfl=wil+(size_t)Dd*Ff;

        gemm_mma<0,false,1><<<gQKV,256,GSMEM>>>(xh,xl,bh_,bl_,pcatb+l*3*Dd,nullptr,nullptr,qkh,qkl,3*Dd,Dd);
        flash_k<<<dim3(4,Bb*Hh),256,FLSM>>>(qkh,qkl,pbias,ts,ch,cl);

        gemm_mma<0,true,0><<<gDD,256,GSMEM>>>(ch,cl,bh_+3*Dd*Dd,bl_+3*Dd*Dd,bo+l*Dd,X,ptmp,nullptr,nullptr,Dd,Dd);
        ln_k<<<Mrows,128>>>(ptmp,l1g+l*Dd,l1b+l*Dd,pattn,ah,al);

        gemm_mma<1,false,1><<<gDF,256,GSMEM>>>(ah,al,wih,wil,bi+l*Ff,nullptr,nullptr,fh,fl,Ff,Dd);
        gemm_mma<0,true,0><<<gDD,256,GSMEM>>>(fh,fl,wfh,wfl,bfp+l*Dd,pattn,ptmp,nullptr,nullptr,Dd,Ff);
        ln_k<<<Mrows,128>>>(ptmp,l2g+l*Dd,l2b+l*Dd,px,xh,xl);
        X=px;
    }
    cudaMemcpyAsync(d_out,px,(size_t)Mrows*Dd*sizeof(float),cudaMemcpyDeviceToDevice,0);
}

// round 9
// speedup vs baseline: 2.6530x; 1.0718x over previous
#include <cuda_runtime.h>
#include <cuda_bf16.h>
#include <math.h>
#include <stdint.h>

#define Bb 32
#define Ss 512
#define Dd 512
#define Hh 8
#define Ff 2048
#define Ll 4
#define DH 64
#define Mrows (Bb*Ss)
#define LWc ((size_t)(4*Dd*Dd+2*Dd*Ff))

typedef __nv_bfloat16 bf16;
typedef __nv_bfloat162 bf162;

__device__ float g_x[Mrows*Dd];
__device__ float g_attn[Mrows*Dd];
__device__ float g_tmp[Mrows*Dd];
__device__ bf16 g_xh[Mrows*Dd], g_xl[Mrows*Dd];
__device__ bf16 g_qkvh[(size_t)Mrows*3*Dd], g_qkvl[(size_t)Mrows*3*Dd];
__device__ bf16 g_ch[Mrows*Dd], g_cl[Mrows*Dd];
__device__ bf16 g_ah[Mrows*Dd], g_al[Mrows*Dd];
__device__ bf16 g_fh[(size_t)Mrows*Ff], g_fl[(size_t)Mrows*Ff];
__device__ bf16 g_wh[Ll*LWc];
__device__ bf16 g_wl[Ll*LWc];
__device__ float g_catb[Ll*3*Dd];

__device__ __forceinline__ float gelu_e(float x){return 0.5f*x*(1.0f+erff(x*0.70710678118654752f));}
__device__ __forceinline__ void cp16(uint32_t d,const void* s){
    asm volatile("cp.async.cg.shared.global [%0], [%1], 16;"::"r"(d),"l"(s));
}
#define CPC() asm volatile("cp.async.commit_group;":::"memory")
#define LDSM4(r0,r1,r2,r3,a) asm volatile("ldmatrix.sync.aligned.m8n8.x4.shared.b16 {%0,%1,%2,%3},[%4];":"=r"(r0),"=r"(r1),"=r"(r2),"=r"(r3):"r"(a))
#define LDSM4T(r0,r1,r2,r3,a) asm volatile("ldmatrix.sync.aligned.m8n8.x4.trans.shared.b16 {%0,%1,%2,%3},[%4];":"=r"(r0),"=r"(r1),"=r"(r2),"=r"(r3):"r"(a))
#define MMA(d,a,b0,b1) asm volatile( \
    "mma.sync.aligned.m16n8k16.row.col.f32.bf16.bf16.f32 {%0,%1,%2,%3},{%4,%5,%6,%7},{%8,%9},{%0,%1,%2,%3};" \
    :"+f"((d)[0]),"+f"((d)[1]),"+f"((d)[2]),"+f"((d)[3]) \
    :"r"((a)[0]),"r"((a)[1]),"r"((a)[2]),"r"((a)[3]),"r"(b0),"r"(b1))

__device__ __forceinline__ void wsplit(float v, bf16& h, bf16& l){
    h=__float2bfloat16(v); l=__float2bfloat16(v-__bfloat162float(h));
}
__device__ __forceinline__ uint32_t packhi(float a,float b,uint32_t& lo){
    bf16 h0,l0,h1,l1; wsplit(a,h0,l0); wsplit(b,h1,l1);
    bf162 L=__halves2bfloat162(l0,l1); lo=*(uint32_t*)&L;
    bf162 H=__halves2bfloat162(h0,h1); return *(uint32_t*)&H;
}

// ======================= projection/FFN GEMM: 3-stage pipeline ====================
#define STB2 32768
#define GSMEM (3*STB2)
__device__ __forceinline__ void load_stage(uint32_t st,int tid,
    const bf16* Ah,const bf16* Al,const bf16* Bh,const bf16* Bl,
    int m0,int n0,int k0,int K){
    #pragma unroll
    for(int i=0;i<8;i++){
        int id=i*256+tid;
        int reg=id>>9, rid=id&511, row=rid>>2, c=rid&3;
        const bf16* src;
        if(reg==0)      src=Ah+(size_t)(m0+row)*K+k0+c*8;
        else if(reg==1) src=Al+(size_t)(m0+row)*K+k0+c*8;
        else if(reg==2) src=Bh+(size_t)(n0+row)*K+k0+c*8;
        else            src=Bl+(size_t)(n0+row)*K+k0+c*8;
        cp16(st+reg*8192+row*64+((c^((row>>1)&3))*16),src);
    }
    CPC();
}

template<int ACT, bool RES, int OUT, int KT>
__global__ void __launch_bounds__(256,2)
gemm_mma(const bf16* __restrict__ Ah,const bf16* __restrict__ Al,
         const bf16* __restrict__ Bh,const bf16* __restrict__ Bl,
         const float* __restrict__ bias,const float* __restrict__ res,
         float* __restrict__ C,bf16* __restrict__ Ch,bf16* __restrict__ Cl,
         int N){
    extern __shared__ char sm[];
    uint32_t sb=(uint32_t)__cvta_generic_to_shared(sm);
    const int tid=threadIdx.x, wid=tid>>5, lane=tid&31;
    const int n0=blockIdx.x*128, m0=blockIdx.y*128;
    const int wm=(wid>>2)*64, wn=(wid&3)*32;
    constexpr int chunks=KT>>5;
    float acc[4][4][4];
    #pragma unroll
    for(int i=0;i<4;i++)
        #pragma unroll
        for(int j=0;j<4;j++){acc[i][j][0]=0;acc[i][j][1]=0;acc[i][j][2]=0;acc[i][j][3]=0;}
    load_stage(sb,tid,Ah,Al,Bh,Bl,m0,n0,0,KT);
    load_stage(sb+STB2,tid,Ah,Al,Bh,Bl,m0,n0,32,KT);
    const int arow=lane&15, ah8=lane>>4;
    int s2=2;
    for(int c=0;c<chunks;c++){
        uint32_t st=sb+(c%3)*STB2;
        if(c<chunks-1) asm volatile("cp.async.wait_group 1;":::"memory");
        else           asm volatile("cp.async.wait_group 0;":::"memory");
        __syncthreads();
        if(c+2<chunks){
            load_stage(sb+s2*STB2,tid,Ah,Al,Bh,Bl,m0,n0,(c+2)*32,KT);
            s2++; if(s2==3)s2=0;
        }
        #pragma unroll
        for(int s=0;s<2;s++){
            // B fragments first (shared across all mi)
            uint32_t bhf[2][4],blf[2][4];
            #pragma unroll
            for(int nq=0;nq<2;nq++){
                int row=wn+nq*16+arow;
                uint32_t ad=st+16384+row*64+(((s*2+ah8)^((row>>1)&3))*16);
                LDSM4(bhf[nq][0],bhf[nq][1],bhf[nq][2],bhf[nq][3],ad);
                LDSM4(blf[nq][0],blf[nq][1],blf[nq][2],blf[nq][3],ad+8192);
            }
            // per-mi: load A frags then run its MMAs (A latency overlaps prev mi MMAs)
            #pragma unroll
            for(int mi=0;mi<4;mi++){
                uint32_t ahf[4],alf[4];
                int row=wm+mi*16+arow;
                uint32_t ad=st+row*64+(((s*2+ah8)^((row>>1)&3))*16);
                LDSM4(ahf[0],ahf[1],ahf[2],ahf[3],ad);
                LDSM4(alf[0],alf[1],alf[2],alf[3],ad+8192);
                #pragma unroll
                for(int nq=0;nq<2;nq++)
                    #pragma unroll
                    for(int p=0;p<2;p++){
                        int nt=nq*2+p;
                        MMA(acc[mi][nt],ahf,bhf[nq][p],bhf[nq][p+2]);
                        MMA(acc[mi][nt],ahf,blf[nq][p],blf[nq][p+2]);
                        MMA(acc[mi][nt],alf,bhf[nq][p],bhf[nq][p+2]);
                    }
            }
        }
    }
    const int r4=lane>>2, c2=(lane&3)*2;
    #pragma unroll
    for(int mi=0;mi<4;mi++)
        #pragma unroll
        for(int nt=0;nt<4;nt++){
            int col=n0+wn+nt*8+c2;
            float2 bv=*(const float2*)&bias[col];
            #pragma unroll
            for(int hr=0;hr<2;hr++){
                int row=m0+wm+mi*16+r4+hr*8;
                float2 o;
                o.x=acc[mi][nt][hr*2+0]+bv.x;
                o.y=acc[mi][nt][hr*2+1]+bv.y;
                if(RES){float2 rv=*(const float2*)&res[(size_t)row*N+col]; o.x+=rv.x;o.y+=rv.y;}
                if(ACT==1){o.x=gelu_e(o.x);o.y=gelu_e(o.y);}
                if(OUT==0){
                    *(float2*)&C[(size_t)row*N+col]=o;
                }else{
                    uint32_t lo,hi=packhi(o.x,o.y,lo);
                    *(uint32_t*)&Ch[(size_t)row*N+col]=hi;
                    *(uint32_t*)&Cl[(size_t)row*N+col]=lo;
                }
            }
        }
}

// ================= fused flash attention: per (b,h,128q) CTA =====================
#define FLSM (32768 + 2*32768)
__global__ void __launch_bounds__(256,2)
flash_k(const bf16* __restrict__ qkvh,const bf16* __restrict__ qkvl,
        const float* __restrict__ pbias,const long long* __restrict__ ts,
        bf16* __restrict__ Ch,bf16* __restrict__ Cl){
    extern __shared__ char sm[];
    uint32_t sb=(uint32_t)__cvta_generic_to_shared(sm);
    const int tid=threadIdx.x, wid=tid>>5, lane=tid&31;
    const int bh=blockIdx.y, b=bh>>3, h=bh&7;
    const int q0=blockIdx.x*128;
    const int wm=wid*16;
    const int arow=lane&15, ah8=lane>>4, r4=lane>>2, j2=(lane&3)*2;

    #pragma unroll
    for(int i=0;i<8;i++){
        int id=i*256+tid;
        int reg=id>>10, rid=id&1023, row=rid>>3, c=rid&7;
        const bf16* src=(reg?qkvl:qkvh)+(size_t)(b*Ss+q0+row)*1536+h*DH+c*8;
        cp16(sb+reg*16384+row*128+((c^(row&7))*16),src);
    }
    CPC();

    auto loadkv=[&](int st,int k0){
        #pragma unroll
        for(int i=0;i<8;i++){
            int id=i*256+tid;
            int part=id>>9, rid=id&511, row=rid>>3, c=rid&7;
            int colb=(part<2)?(Dd+h*DH):(2*Dd+h*DH);
            const bf16* src=((part&1)?qkvl:qkvh)+(size_t)(b*Ss+k0+row)*1536+colb+c*8;
            cp16(sb+32768+st*32768+part*8192+row*128+((c^(row&7))*16),src);
        }
        CPC();
    };
    loadkv(0,0); loadkv(1,64);

    float m0_=-1e30f, m1_=-1e30f, l0_=0.0f, l1_=0.0f;
    float oacc[8][4];
    #pragma unroll
    for(int i=0;i<8;i++){oacc[i][0]=0;oacc[i][1]=0;oacc[i][2]=0;oacc[i][3]=0;}
    const long long tq0=ts[b*Ss+q0+wm+r4], tq1=ts[b*Ss+q0+wm+r4+8];
    const int qi0=q0+wm+r4, qi1=qi0+8;

    for(int t=0;t<8;t++){
        uint32_t stv=sb+32768+(t&1)*32768;
        if(t<6) asm volatile("cp.async.wait_group 1;":::"memory");
        else    asm volatile("cp.async.wait_group 0;":::"memory");
        __syncthreads();

        float sacc[8][4];
        #pragma unroll
        for(int i=0;i<8;i++){sacc[i][0]=0;sacc[i][1]=0;sacc[i][2]=0;sacc[i][3]=0;}
        #pragma unroll
        for(int kt=0;kt<4;kt++){
            uint32_t qh_[4],ql_[4];
            {
                int row=wm+arow;
                uint32_t ad=sb+row*128+(((kt*2+ah8)^(row&7))*16);
                LDSM4(qh_[0],qh_[1],qh_[2],qh_[3],ad);
                LDSM4(ql_[0],ql_[1],ql_[2],ql_[3],ad+16384);
            }
            #pragma unroll
            for(int nq=0;nq<4;nq++){
                int row=nq*16+arow;
                uint32_t ad=stv+row*128+(((kt*2+ah8)^(row&7))*16);
                uint32_t kh_[4],kl_[4];
                LDSM4(kh_[0],kh_[1],kh_[2],kh_[3],ad);
                LDSM4(kl_[0],kl_[1],kl_[2],kl_[3],ad+8192);
                #pragma unroll
                for(int p=0;p<2;p++){
                    int nt=nq*2+p;
                    MMA(sacc[nt],qh_,kh_[p],kh_[p+2]);
                    MMA(sacc[nt],qh_,kl_[p],kl_[p+2]);
                    MMA(sacc[nt],ql_,kh_[p],kh_[p+2]);
                }
            }
        }
        int k0=t*64;
        #pragma unroll
        for(int nt=0;nt<8;nt++){
            int kc=k0+nt*8+j2;
            long long tk0=ts[b*Ss+kc], tk1=ts[b*Ss+kc+1];
            {
                float2 pb=*(const float2*)&pbias[((size_t)(h*Ss+qi0))*Ss+kc];
                float la=(float)(tq0-tk0)*(1.0f/60000.0f);
                float lb=(float)(tq0-tk1)*(1.0f/60000.0f);
                float sa=9.0f-__fdividef(1.0f,fmaxf(la,0.0f)+1.0f);
                float sbb=9.0f-__fdividef(1.0f,fmaxf(lb,0.0f)+1.0f);
                sacc[nt][0]=__fdividef(sacc[nt][0],sa)+pb.x;
                sacc[nt][1]=__fdividef(sacc[nt][1],sbb)+pb.y;
            }
            {
                float2 pb=*(const float2*)&pbias[((size_t)(h*Ss+qi1))*Ss+kc];
                float la=(float)(tq1-tk0)*(1.0f/60000.0f);
                float lb=(float)(tq1-tk1)*(1.0f/60000.0f);
                float sa=9.0f-__fdividef(1.0f,fmaxf(la,0.0f)+1.0f);
                float sbb=9.0f-__fdividef(1.0f,fmaxf(lb,0.0f)+1.0f);
                sacc[nt][2]=__fdividef(sacc[nt][2],sa)+pb.x;
                sacc[nt][3]=__fdividef(sacc[nt][3],sbb)+pb.y;
            }
        }
        float tm0=-1e30f, tm1=-1e30f;
        #pragma unroll
        for(int nt=0;nt<8;nt++){
            tm0=fmaxf(tm0,fmaxf(sacc[nt][0],sacc[nt][1]));
            tm1=fmaxf(tm1,fmaxf(sacc[nt][2],sacc[nt][3]));
        }
        tm0=fmaxf(tm0,__shfl_xor_sync(0xffffffffu,tm0,1));
        tm0=fmaxf(tm0,__shfl_xor_sync(0xffffffffu,tm0,2));
        tm1=fmaxf(tm1,__shfl_xor_sync(0xffffffffu,tm1,1));
        tm1=fmaxf(tm1,__shfl_xor_sync(0xffffffffu,tm1,2));
        float mn0=fmaxf(m0_,tm0), mn1=fmaxf(m1_,tm1);
        float al0=__expf(m0_-mn0), al1=__expf(m1_-mn1);
        m0_=mn0; m1_=mn1;
        float s0=0.0f, s1=0.0f;
        #pragma unroll
        for(int nt=0;nt<8;nt++){
            sacc[nt][0]=__expf(sacc[nt][0]-mn0); s0+=sacc[nt][0];
            sacc[nt][1]=__expf(sacc[nt][1]-mn0); s0+=sacc[nt][1];
            sacc[nt][2]=__expf(sacc[nt][2]-mn1); s1+=sacc[nt][2];
            sacc[nt][3]=__expf(sacc[nt][3]-mn1); s1+=sacc[nt][3];
        }
        s0+=__shfl_xor_sync(0xffffffffu,s0,1); s0+=__shfl_xor_sync(0xffffffffu,s0,2);
        s1+=__shfl_xor_sync(0xffffffffu,s1,1); s1+=__shfl_xor_sync(0xffffffffu,s1,2);
        l0_=l0_*al0+s0; l1_=l1_*al1+s1;
        #pragma unroll
        for(int nt=0;nt<8;nt++){
            oacc[nt][0]*=al0; oacc[nt][1]*=al0;
            oacc[nt][2]*=al1; oacc[nt][3]*=al1;
        }
        uint32_t ph_[4][4], pl_[4][4];
        #pragma unroll
        for(int kt=0;kt<4;kt++){
            ph_[kt][0]=packhi(sacc[2*kt][0],  sacc[2*kt][1],  pl_[kt][0]);
            ph_[kt][1]=packhi(sacc[2*kt][2],  sacc[2*kt][3],  pl_[kt][1]);
            ph_[kt][2]=packhi(sacc[2*kt+1][0],sacc[2*kt+1][1],pl_[kt][2]);
            ph_[kt][3]=packhi(sacc[2*kt+1][2],sacc[2*kt+1][3],pl_[kt][3]);
        }
        #pragma unroll
        for(int kt=0;kt<4;kt++){
            #pragma unroll
            for(int dg=0;dg<4;dg++){
                int row=kt*16+((lane>>3)&1)*8+(lane&7);
                int ch_=dg*2+(lane>>4);
                uint32_t ad=stv+16384+row*128+((ch_^(row&7))*16);
                uint32_t vh_[4],vl_[4];
                LDSM4T(vh_[0],vh_[1],vh_[2],vh_[3],ad);
                LDSM4T(vl_[0],vl_[1],vl_[2],vl_[3],ad+8192);
                #pragma unroll
                for(int p=0;p<2;p++){
                    int nt=dg*2+p;
                    MMA(oacc[nt],ph_[kt],vh_[p*2],vh_[p*2+1]);
                    MMA(oacc[nt],ph_[kt],vl_[p*2],vl_[p*2+1]);
                    MMA(oacc[nt],pl_[kt],vh_[p*2],vh_[p*2+1]);
                }
            }
        }
        __syncthreads();
        if(t<6) loadkv(t&1,(t+2)*64);
    }
    float inv0=__fdividef(1.0f,l0_), inv1=__fdividef(1.0f,l1_);
    #pragma unroll
    for(int nt=0;nt<8;nt++){
        int dh=nt*8+j2;
        {
            size_t idx=((size_t)(b*Ss+qi0))*Dd+h*DH+dh;
            uint32_t lo,hi=packhi(oacc[nt][0]*inv0,oacc[nt][1]*inv0,lo);
            *(uint32_t*)&Ch[idx]=hi; *(uint32_t*)&Cl[idx]=lo;
        }
        {
            size_t idx=((size_t)(b*Ss+qi1))*Dd+h*DH+dh;
            uint32_t lo,hi=packhi(oacc[nt][2]*inv1,oacc[nt][3]*inv1,lo);
            *(uint32_t*)&Ch[idx]=hi; *(uint32_t*)&Cl[idx]=lo;
        }
    }
}

// ================= LayerNorm: fp32 out + bf16 hi/lo out ========================
__global__ void ln_k(const float* __restrict__ in,const float* __restrict__ g,
                     const float* __restrict__ bt,float* __restrict__ out,
                     bf16* __restrict__ oh,bf16* __restrict__ ol){
    const size_t row=blockIdx.x;
    const int tid=threadIdx.x, lane=tid&31, wid=tid>>5;
    __shared__ float red[4];
    float4 v=*(const float4*)&in[row*Dd+tid*4];
    float s=v.x+v.y+v.z+v.w;
    #pragma unroll
    for(int o=16;o;o>>=1)s+=__shfl_xor_sync(0xffffffffu,s,o);
    if(lane==0)red[wid]=s;
    __syncthreads();
    float mu=(red[0]+red[1]+red[2]+red[3])*(1.0f/512.0f);
    __syncthreads();
    float dx=v.x-mu,dy=v.y-mu,dz=v.z-mu,dw=v.w-mu;
    float s2=dx*dx+dy*dy+dz*dz+dw*dw;
    #pragma unroll
    for(int o=16;o;o>>=1)s2+=__shfl_xor_sync(0xffffffffu,s2,o);
    if(lane==0)red[wid]=s2;
    __syncthreads();
    float var=(red[0]+red[1]+red[2]+red[3])*(1.0f/512.0f);
    float inv=rsqrtf(var+1e-12f);
    float4 gv=*(const float4*)&g[tid*4];
    float4 bv=*(const float4*)&bt[tid*4];
    float4 o;
    o.x=dx*inv*gv.x+bv.x; o.y=dy*inv*gv.y+bv.y;
    o.z=dz*inv*gv.z+bv.z; o.w=dw*inv*gv.w+bv.w;
    *(float4*)&out[row*Dd+tid*4]=o;
    uint32_t lo0,hi0=packhi(o.x,o.y,lo0);
    uint32_t lo1,hi1=packhi(o.z,o.w,lo1);
    ((uint32_t*)(oh+row*Dd+tid*4))[0]=hi0; ((uint32_t*)(oh+row*Dd+tid*4))[1]=hi1;
    ((uint32_t*)(ol+row*Dd+tid*4))[0]=lo0; ((uint32_t*)(ol+row*Dd+tid*4))[1]=lo1;
}

__global__ void split_k(const float* __restrict__ s,bf16* __restrict__ hi,
                        bf16* __restrict__ lo,int n4){
    int i=blockIdx.x*256+threadIdx.x;
    if(i>=n4)return;
    float4 v=((const float4*)s)[i];
    uint32_t lo0,hi0=packhi(v.x,v.y,lo0);
    uint32_t lo1,hi1=packhi(v.z,v.w,lo1);
    ((uint32_t*)hi)[i*2+0]=hi0; ((uint32_t*)hi)[i*2+1]=hi1;
    ((uint32_t*)lo)[i*2+0]=lo0; ((uint32_t*)lo)[i*2+1]=lo1;
}

// ======= single weight-prep kernel: transpose+split ALL matrices, all layers =====
__global__ void wprep_k(const float* __restrict__ Wq,const float* __restrict__ Wk,
                        const float* __restrict__ Wv,const float* __restrict__ Wo,
                        const float* __restrict__ Wi,const float* __restrict__ Wf,
                        bf16* __restrict__ wh,bf16* __restrict__ wl){
    __shared__ float t[32][33];
    int tile=blockIdx.x;
    int l=tile/3072, r=tile%3072;
    const float* src; size_t off; int K,N;
    if(r<1024){
        int m=r>>8; r&=255;
        src=(m==0?Wq:m==1?Wk:m==2?Wv:Wo)+(size_t)l*Dd*Dd;
        off=(size_t)m*Dd*Dd; K=Dd; N=Dd;
    }else if(r<2048){
        r-=1024; src=Wi+(size_t)l*Dd*Ff; off=4*Dd*Dd; K=Dd; N=Ff;
    }else{
        r-=2048; src=Wf+(size_t)l*Ff*Dd; off=4*Dd*Dd+(size_t)Dd*Ff; K=Ff; N=Dd;
    }
    bf16* dh=wh+(size_t)l*LWc+off;
    bf16* dl=wl+(size_t)l*LWc+off;
    int ntk=K>>5;
    int n0=(r/ntk)*32, k0=(r%ntk)*32;
    int x=threadIdx.x, y0=threadIdx.y;
    for(int j=y0;j<32;j+=8) t[j][x]=src[(size_t)(k0+j)*N+n0+x];
    __syncthreads();
    for(int j=y0;j<32;j+=8){
        float v=t[x][j];
        bf16 h,l2; wsplit(v,h,l2);
        dh[(size_t)(n0+j)*K+k0+x]=h;
        dl[(size_t)(n0+j)*K+k0+x]=l2;
    }
}

__global__ void catb_k(const float* bq,const float* bk,const float* bv,float* o){
    int i=blockIdx.x*256+threadIdx.x;
    if(i>=Ll*3*Dd)return;
    int l=i/(3*Dd), r=i%(3*Dd);
    o[i]= r<Dd ? bq[l*Dd+r] : (r<2*Dd ? bk[l*Dd+r-Dd] : bv[l*Dd+r-2*Dd]);
}

extern "C" void kernel_launch(void* const* d_in, const int* in_sizes, int n_in,
                              void* d_out, int out_size){
    const float* hidden=(const float*)d_in[0];
    const float* pbias=(const float*)d_in[1];
    const long long* ts=(const long long*)d_in[2];
    const float* Wq=(const float*)d_in[3];  const float* bq=(const float*)d_in[4];
    const float* Wk=(const float*)d_in[5];  const float* bk=(const float*)d_in[6];
    const float* Wv=(const float*)d_in[7];  const float* bv=(const float*)d_in[8];
    const float* Wo=(const float*)d_in[9];  const float* bo=(const float*)d_in[10];
    const float* l1g=(const float*)d_in[11];const float* l1b=(const float*)d_in[12];
    const float* Wi=(const float*)d_in[13]; const float* bi=(const float*)d_in[14];
    const float* Wf=(const float*)d_in[15]; const float* bfp=(const float*)d_in[16];
    const float* l2g=(const float*)d_in[17];const float* l2b=(const float*)d_in[18];

    float *px,*pattn,*ptmp,*pcatb;
    cudaGetSymbolAddress((void**)&px,g_x);     cudaGetSymbolAddress((void**)&pattn,g_attn);
    cudaGetSymbolAddress((void**)&ptmp,g_tmp); cudaGetSymbolAddress((void**)&pcatb,g_catb);
    bf16 *xh,*xl,*qkh,*qkl,*ch,*cl,*ah,*al,*fh,*fl,*wh,*wl;
    cudaGetSymbolAddress((void**)&xh,g_xh);   cudaGetSymbolAddress((void**)&xl,g_xl);
    cudaGetSymbolAddress((void**)&qkh,g_qkvh);cudaGetSymbolAddress((void**)&qkl,g_qkvl);
    cudaGetSymbolAddress((void**)&ch,g_ch);   cudaGetSymbolAddress((void**)&cl,g_cl);
    cudaGetSymbolAddress((void**)&ah,g_ah);   cudaGetSymbolAddress((void**)&al,g_al);
    cudaGetSymbolAddress((void**)&fh,g_fh);   cudaGetSymbolAddress((void**)&fl,g_fl);
    cudaGetSymbolAddress((void**)&wh,g_wh);   cudaGetSymbolAddress((void**)&wl,g_wl);

    cudaFuncSetAttribute(gemm_mma<0,false,1,512>, cudaFuncAttributeMaxDynamicSharedMemorySize,GSMEM);
    cudaFuncSetAttribute(gemm_mma<0,true,0,512>,  cudaFuncAttributeMaxDynamicSharedMemorySize,GSMEM);
    cudaFuncSetAttribute(gemm_mma<1,false,1,512>, cudaFuncAttributeMaxDynamicSharedMemorySize,GSMEM);
    cudaFuncSetAttribute(gemm_mma<0,true,0,2048>, cudaFuncAttributeMaxDynamicSharedMemorySize,GSMEM);
    cudaFuncSetAttribute(flash_k,cudaFuncAttributeMaxDynamicSharedMemorySize,FLSM);

    wprep_k<<<Ll*3072,dim3(32,8)>>>(Wq,Wk,Wv,Wo,Wi,Wf,wh,wl);
    catb_k<<<(Ll*3*Dd+255)/256,256>>>(bq,bk,bv,pcatb);
    const int nD4=Mrows*Dd/4;
    split_k<<<(nD4+255)/256,256>>>(hidden,xh,xl,nD4);

    const dim3 gDD(Dd/128,Mrows/128), gQKV(3*Dd/128,Mrows/128), gDF(Ff/128,Mrows/128);
    const float* X=hidden;
    for(int l=0;l<Ll;l++){
        bf16* bh_=wh+(size_t)l*LWc; bf16* bl_=wl+(size_t)l*LWc;
        bf16* wih=bh_+4*Dd*Dd; bf16* wil=bl_+4*Dd*Dd;
        bf16* wfh=wih+(size_t)Dd*Ff; bf16* wfl=wil+(size_t)Dd*Ff;

        gemm_mma<0,false,1,512><<<gQKV,256,GSMEM>>>(xh,xl,bh_,bl_,pcatb+l*3*Dd,nullptr,nullptr,qkh,qkl,3*Dd);
        flash_k<<<dim3(4,Bb*Hh),256,FLSM>>>(qkh,qkl,pbias,ts,ch,cl);

        gemm_mma<0,true,0,512><<<gDD,256,GSMEM>>>(ch,cl,bh_+3*Dd*Dd,bl_+3*Dd*Dd,bo+l*Dd,X,ptmp,nullptr,nullptr,Dd);
        ln_k<<<Mrows,128>>>(ptmp,l1g+l*Dd,l1b+l*Dd,pattn,ah,al);

        gemm_mma<1,false,1,512><<<gDF,256,GSMEM>>>(ah,al,wih,wil,bi+l*Ff,nullptr,nullptr,fh,fl,Ff);
        gemm_mma<0,true,0,2048><<<gDD,256,GSMEM>>>(fh,fl,wfh,wfl,bfp+l*Dd,pattn,ptmp,nullptr,nullptr,Dd);
        ln_k<<<Mrows,128>>>(ptmp,l2g+l*Dd,l2b+l*Dd,px,xh,xl);
        X=px;
    }
    cudaMemcpyAsync(d_out,px,(size_t)Mrows*Dd*sizeof(float),cudaMemcpyDeviceToDevice,0);
}

// round 10
// speedup vs baseline: 3.4212x; 1.2896x over previous
#include <cuda_runtime.h>
#include <cuda_fp16.h>
#include <math.h>
#include <stdint.h>

#define Bb 32
#define Ss 512
#define Dd 512
#define Hh 8
#define Ff 2048
#define Ll 4
#define DH 64
#define Mrows (Bb*Ss)
#define LWc ((size_t)(4*Dd*Dd+2*Dd*Ff))

typedef __half hf;

__device__ float g_x[Mrows*Dd];
__device__ float g_attn[Mrows*Dd];
__device__ float g_tmp[Mrows*Dd];
__device__ hf g_xh[Mrows*Dd], g_xl[Mrows*Dd];
__device__ hf g_qkvh[(size_t)Mrows*3*Dd], g_qkvl[(size_t)Mrows*3*Dd];
__device__ hf g_ch[Mrows*Dd], g_cl[Mrows*Dd];
__device__ hf g_ah[Mrows*Dd], g_al[Mrows*Dd];
__device__ hf g_fh[(size_t)Mrows*Ff], g_fl[(size_t)Mrows*Ff];
__device__ hf g_wh[Ll*LWc];
__device__ float g_catb[Ll*3*Dd];

__device__ __forceinline__ float gelu_e(float x){return 0.5f*x*(1.0f+erff(x*0.70710678118654752f));}
__device__ __forceinline__ void cp16(uint32_t d,const void* s){
    asm volatile("cp.async.cg.shared.global [%0], [%1], 16;"::"r"(d),"l"(s));
}
#define CPC() asm volatile("cp.async.commit_group;":::"memory")
#define LDSM4(r0,r1,r2,r3,a) asm volatile("ldmatrix.sync.aligned.m8n8.x4.shared.b16 {%0,%1,%2,%3},[%4];":"=r"(r0),"=r"(r1),"=r"(r2),"=r"(r3):"r"(a))
#define LDSM4T(r0,r1,r2,r3,a) asm volatile("ldmatrix.sync.aligned.m8n8.x4.trans.shared.b16 {%0,%1,%2,%3},[%4];":"=r"(r0),"=r"(r1),"=r"(r2),"=r"(r3):"r"(a))
#define MMA(d,a,b0,b1) asm volatile( \
    "mma.sync.aligned.m16n8k16.row.col.f32.f16.f16.f32 {%0,%1,%2,%3},{%4,%5,%6,%7},{%8,%9},{%0,%1,%2,%3};" \
    :"+f"((d)[0]),"+f"((d)[1]),"+f"((d)[2]),"+f"((d)[3]) \
    :"r"((a)[0]),"r"((a)[1]),"r"((a)[2]),"r"((a)[3]),"r"(b0),"r"(b1))

__device__ __forceinline__ void wsplit(float v, hf& h, hf& l){
    h=__float2half_rn(v); l=__float2half_rn(v-__half2float(h));
}
__device__ __forceinline__ uint32_t packhi(float a,float b,uint32_t& lo){
    hf h0,l0,h1,l1; wsplit(a,h0,l0); wsplit(b,h1,l1);
    __half2 L=__halves2half2(l0,l1); lo=*(uint32_t*)&L;
    __half2 H=__halves2half2(h0,h1); return *(uint32_t*)&H;
}

// ============== GEMM: 2-term fp16 split (A=hi+lo, W=hi), 3-stage ================
#define STB2 24576
#define GSMEM (3*STB2)
__device__ __forceinline__ void load_stage(uint32_t st,int tid,
    const hf* Ah,const hf* Al,const hf* Bh,
    int m0,int n0,int k0,int K){
    #pragma unroll
    for(int i=0;i<6;i++){
        int id=i*256+tid;
        int reg=id>>9, rid=id&511, row=rid>>2, c=rid&3;
        const hf* src;
        if(reg==0)      src=Ah+(size_t)(m0+row)*K+k0+c*8;
        else if(reg==1) src=Al+(size_t)(m0+row)*K+k0+c*8;
        else            src=Bh+(size_t)(n0+row)*K+k0+c*8;
        cp16(st+reg*8192+row*64+((c^((row>>1)&3))*16),src);
    }
    CPC();
}

template<int ACT, bool RES, int OUT, int KT>
__global__ void __launch_bounds__(256,2)
gemm_mma(const hf* __restrict__ Ah,const hf* __restrict__ Al,
         const hf* __restrict__ Bh,
         const float* __restrict__ bias,const float* __restrict__ res,
         float* __restrict__ C,hf* __restrict__ Ch,hf* __restrict__ Cl,
         int N){
    extern __shared__ char sm[];
    uint32_t sb=(uint32_t)__cvta_generic_to_shared(sm);
    const int tid=threadIdx.x, wid=tid>>5, lane=tid&31;
    const int n0=blockIdx.x*128, m0=blockIdx.y*128;
    const int wm=(wid>>2)*64, wn=(wid&3)*32;
    constexpr int chunks=KT>>5;
    float acc[4][4][4];
    #pragma unroll
    for(int i=0;i<4;i++)
        #pragma unroll
        for(int j=0;j<4;j++){acc[i][j][0]=0;acc[i][j][1]=0;acc[i][j][2]=0;acc[i][j][3]=0;}
    load_stage(sb,tid,Ah,Al,Bh,m0,n0,0,KT);
    load_stage(sb+STB2,tid,Ah,Al,Bh,m0,n0,32,KT);
    const int arow=lane&15, ah8=lane>>4;
    int s2=2;
    for(int c=0;c<chunks;c++){
        uint32_t st=sb+(c%3)*STB2;
        if(c<chunks-1) asm volatile("cp.async.wait_group 1;":::"memory");
        else           asm volatile("cp.async.wait_group 0;":::"memory");
        __syncthreads();
        if(c+2<chunks){
            load_stage(sb+s2*STB2,tid,Ah,Al,Bh,m0,n0,(c+2)*32,KT);
            s2++; if(s2==3)s2=0;
        }
        #pragma unroll
        for(int s=0;s<2;s++){
            uint32_t bhf[2][4];
            #pragma unroll
            for(int nq=0;nq<2;nq++){
                int row=wn+nq*16+arow;
                uint32_t ad=st+16384+row*64+(((s*2+ah8)^((row>>1)&3))*16);
                LDSM4(bhf[nq][0],bhf[nq][1],bhf[nq][2],bhf[nq][3],ad);
            }
            #pragma unroll
            for(int mi=0;mi<4;mi++){
                uint32_t ahf[4],alf[4];
                int row=wm+mi*16+arow;
                uint32_t ad=st+row*64+(((s*2+ah8)^((row>>1)&3))*16);
                LDSM4(ahf[0],ahf[1],ahf[2],ahf[3],ad);
                LDSM4(alf[0],alf[1],alf[2],alf[3],ad+8192);
                #pragma unroll
                for(int nq=0;nq<2;nq++)
                    #pragma unroll
                    for(int p=0;p<2;p++){
                        int nt=nq*2+p;
                        MMA(acc[mi][nt],ahf,bhf[nq][p],bhf[nq][p+2]);
                        MMA(acc[mi][nt],alf,bhf[nq][p],bhf[nq][p+2]);
                    }
            }
        }
    }
    const int r4=lane>>2, c2=(lane&3)*2;
    #pragma unroll
    for(int mi=0;mi<4;mi++)
        #pragma unroll
        for(int nt=0;nt<4;nt++){
            int col=n0+wn+nt*8+c2;
            float2 bv=*(const float2*)&bias[col];
            #pragma unroll
            for(int hr=0;hr<2;hr++){
                int row=m0+wm+mi*16+r4+hr*8;
                float2 o;
                o.x=acc[mi][nt][hr*2+0]+bv.x;
                o.y=acc[mi][nt][hr*2+1]+bv.y;
                if(RES){float2 rv=*(const float2*)&res[(size_t)row*N+col]; o.x+=rv.x;o.y+=rv.y;}
                if(ACT==1){o.x=gelu_e(o.x);o.y=gelu_e(o.y);}
                if(OUT==0){
                    *(float2*)&C[(size_t)row*N+col]=o;
                }else{
                    uint32_t lo,hi=packhi(o.x,o.y,lo);
                    *(uint32_t*)&Ch[(size_t)row*N+col]=hi;
                    *(uint32_t*)&Cl[(size_t)row*N+col]=lo;
                }
            }
        }
}

// ================= fused flash attention (fp16 pieces, 3-term) ===================
#define FLSM (32768 + 2*32768)
__global__ void __launch_bounds__(256,2)
flash_k(const hf* __restrict__ qkvh,const hf* __restrict__ qkvl,
        const float* __restrict__ pbias,const long long* __restrict__ ts,
        hf* __restrict__ Ch,hf* __restrict__ Cl){
    extern __shared__ char sm[];
    uint32_t sb=(uint32_t)__cvta_generic_to_shared(sm);
    const int tid=threadIdx.x, wid=tid>>5, lane=tid&31;
    const int bh=blockIdx.y, b=bh>>3, h=bh&7;
    const int q0=blockIdx.x*128;
    const int wm=wid*16;
    const int arow=lane&15, ah8=lane>>4, r4=lane>>2, j2=(lane&3)*2;

    #pragma unroll
    for(int i=0;i<8;i++){
        int id=i*256+tid;
        int reg=id>>10, rid=id&1023, row=rid>>3, c=rid&7;
        const hf* src=(reg?qkvl:qkvh)+(size_t)(b*Ss+q0+row)*1536+h*DH+c*8;
        cp16(sb+reg*16384+row*128+((c^(row&7))*16),src);
    }
    CPC();

    auto loadkv=[&](int st,int k0){
        #pragma unroll
        for(int i=0;i<8;i++){
            int id=i*256+tid;
            int part=id>>9, rid=id&511, row=rid>>3, c=rid&7;
            int colb=(part<2)?(Dd+h*DH):(2*Dd+h*DH);
            const hf* src=((part&1)?qkvl:qkvh)+(size_t)(b*Ss+k0+row)*1536+colb+c*8;
            cp16(sb+32768+st*32768+part*8192+row*128+((c^(row&7))*16),src);
        }
        CPC();
    };
    loadkv(0,0); loadkv(1,64);

    float m0_=-1e30f, m1_=-1e30f, l0_=0.0f, l1_=0.0f;
    float oacc[8][4];
    #pragma unroll
    for(int i=0;i<8;i++){oacc[i][0]=0;oacc[i][1]=0;oacc[i][2]=0;oacc[i][3]=0;}
    const long long tq0=ts[b*Ss+q0+wm+r4], tq1=ts[b*Ss+q0+wm+r4+8];
    const int qi0=q0+wm+r4, qi1=qi0+8;

    for(int t=0;t<8;t++){
        uint32_t stv=sb+32768+(t&1)*32768;
        if(t<6) asm volatile("cp.async.wait_group 1;":::"memory");
        else    asm volatile("cp.async.wait_group 0;":::"memory");
        __syncthreads();

        float sacc[8][4];
        #pragma unroll
        for(int i=0;i<8;i++){sacc[i][0]=0;sacc[i][1]=0;sacc[i][2]=0;sacc[i][3]=0;}
        #pragma unroll
        for(int kt=0;kt<4;kt++){
            uint32_t qh_[4],ql_[4];
            {
                int row=wm+arow;
                uint32_t ad=sb+row*128+(((kt*2+ah8)^(row&7))*16);
                LDSM4(qh_[0],qh_[1],qh_[2],qh_[3],ad);
                LDSM4(ql_[0],ql_[1],ql_[2],ql_[3],ad+16384);
            }
            #pragma unroll
            for(int nq=0;nq<4;nq++){
                int row=nq*16+arow;
                uint32_t ad=stv+row*128+(((kt*2+ah8)^(row&7))*16);
                uint32_t kh_[4],kl_[4];
                LDSM4(kh_[0],kh_[1],kh_[2],kh_[3],ad);
                LDSM4(kl_[0],kl_[1],kl_[2],kl_[3],ad+8192);
                #pragma unroll
                for(int p=0;p<2;p++){
                    int nt=nq*2+p;
                    MMA(sacc[nt],qh_,kh_[p],kh_[p+2]);
                    MMA(sacc[nt],qh_,kl_[p],kl_[p+2]);
                    MMA(sacc[nt],ql_,kh_[p],kh_[p+2]);
                }
            }
        }
        int k0=t*64;
        #pragma unroll
        for(int nt=0;nt<8;nt++){
            int kc=k0+nt*8+j2;
            long long tk0=ts[b*Ss+kc], tk1=ts[b*Ss+kc+1];
            {
                float2 pb=*(const float2*)&pbias[((size_t)(h*Ss+qi0))*Ss+kc];
                float la=(float)(tq0-tk0)*(1.0f/60000.0f);
                float lb=(float)(tq0-tk1)*(1.0f/60000.0f);
                float sa=9.0f-__fdividef(1.0f,fmaxf(la,0.0f)+1.0f);
                float sbb=9.0f-__fdividef(1.0f,fmaxf(lb,0.0f)+1.0f);
                sacc[nt][0]=__fdividef(sacc[nt][0],sa)+pb.x;
                sacc[nt][1]=__fdividef(sacc[nt][1],sbb)+pb.y;
            }
            {
                float2 pb=*(const float2*)&pbias[((size_t)(h*Ss+qi1))*Ss+kc];
                float la=(float)(tq1-tk0)*(1.0f/60000.0f);
                float lb=(float)(tq1-tk1)*(1.0f/60000.0f);
                float sa=9.0f-__fdividef(1.0f,fmaxf(la,0.0f)+1.0f);
                float sbb=9.0f-__fdividef(1.0f,fmaxf(lb,0.0f)+1.0f);
                sacc[nt][2]=__fdividef(sacc[nt][2],sa)+pb.x;
                sacc[nt][3]=__fdividef(sacc[nt][3],sbb)+pb.y;
            }
        }
        float tm0=-1e30f, tm1=-1e30f;
        #pragma unroll
        for(int nt=0;nt<8;nt++){
            tm0=fmaxf(tm0,fmaxf(sacc[nt][0],sacc[nt][1]));
            tm1=fmaxf(tm1,fmaxf(sacc[nt][2],sacc[nt][3]));
        }
        tm0=fmaxf(tm0,__shfl_xor_sync(0xffffffffu,tm0,1));
        tm0=fmaxf(tm0,__shfl_xor_sync(0xffffffffu,tm0,2));
        tm1=fmaxf(tm1,__shfl_xor_sync(0xffffffffu,tm1,1));
        tm1=fmaxf(tm1,__shfl_xor_sync(0xffffffffu,tm1,2));
        float mn0=fmaxf(m0_,tm0), mn1=fmaxf(m1_,tm1);
        float al0=__expf(m0_-mn0), al1=__expf(m1_-mn1);
        m0_=mn0; m1_=mn1;
        float s0=0.0f, s1=0.0f;
        #pragma unroll
        for(int nt=0;nt<8;nt++){
            sacc[nt][0]=__expf(sacc[nt][0]-mn0); s0+=sacc[nt][0];
            sacc[nt][1]=__expf(sacc[nt][1]-mn0); s0+=sacc[nt][1];
            sacc[nt][2]=__expf(sacc[nt][2]-mn1); s1+=sacc[nt][2];
            sacc[nt][3]=__expf(sacc[nt][3]-mn1); s1+=sacc[nt][3];
        }
        s0+=__shfl_xor_sync(0xffffffffu,s0,1); s0+=__shfl_xor_sync(0xffffffffu,s0,2);
        s1+=__shfl_xor_sync(0xffffffffu,s1,1); s1+=__shfl_xor_sync(0xffffffffu,s1,2);
        l0_=l0_*al0+s0; l1_=l1_*al1+s1;
        #pragma unroll
        for(int nt=0;nt<8;nt++){
            oacc[nt][0]*=al0; oacc[nt][1]*=al0;
            oacc[nt][2]*=al1; oacc[nt][3]*=al1;
        }
        uint32_t ph_[4][4], pl_[4][4];
        #pragma unroll
        for(int kt=0;kt<4;kt++){
            ph_[kt][0]=packhi(sacc[2*kt][0],  sacc[2*kt][1],  pl_[kt][0]);
            ph_[kt][1]=packhi(sacc[2*kt][2],  sacc[2*kt][3],  pl_[kt][1]);
            ph_[kt][2]=packhi(sacc[2*kt+1][0],sacc[2*kt+1][1],pl_[kt][2]);
            ph_[kt][3]=packhi(sacc[2*kt+1][2],sacc[2*kt+1][3],pl_[kt][3]);
        }
        #pragma unroll
        for(int kt=0;kt<4;kt++){
            #pragma unroll
            for(int dg=0;dg<4;dg++){
                int row=kt*16+((lane>>3)&1)*8+(lane&7);
                int ch_=dg*2+(lane>>4);
                uint32_t ad=stv+16384+row*128+((ch_^(row&7))*16);
                uint32_t vh_[4],vl_[4];
                LDSM4T(vh_[0],vh_[1],vh_[2],vh_[3],ad);
                LDSM4T(vl_[0],vl_[1],vl_[2],vl_[3],ad+8192);
                #pragma unroll
                for(int p=0;p<2;p++){
                    int nt=dg*2+p;
                    MMA(oacc[nt],ph_[kt],vh_[p*2],vh_[p*2+1]);
                    MMA(oacc[nt],ph_[kt],vl_[p*2],vl_[p*2+1]);
                    MMA(oacc[nt],pl_[kt],vh_[p*2],vh_[p*2+1]);
                }
            }
        }
        __syncthreads();
        if(t<6) loadkv(t&1,(t+2)*64);
    }
    float inv0=__fdividef(1.0f,l0_), inv1=__fdividef(1.0f,l1_);
    #pragma unroll
    for(int nt=0;nt<8;nt++){
        int dh=nt*8+j2;
        {
            size_t idx=((size_t)(b*Ss+qi0))*Dd+h*DH+dh;
            uint32_t lo,hi=packhi(oacc[nt][0]*inv0,oacc[nt][1]*inv0,lo);
            *(uint32_t*)&Ch[idx]=hi; *(uint32_t*)&Cl[idx]=lo;
        }
        {
            size_t idx=((size_t)(b*Ss+qi1))*Dd+h*DH+dh;
            uint32_t lo,hi=packhi(oacc[nt][2]*inv1,oacc[nt][3]*inv1,lo);
            *(uint32_t*)&Ch[idx]=hi; *(uint32_t*)&Cl[idx]=lo;
        }
    }
}

// ================= LayerNorm: fp32 out + fp16 hi/lo out ========================
__global__ void ln_k(const float* __restrict__ in,const float* __restrict__ g,
                     const float* __restrict__ bt,float* __restrict__ out,
                     hf* __restrict__ oh,hf* __restrict__ ol){
    const size_t row=blockIdx.x;
    const int tid=threadIdx.x, lane=tid&31, wid=tid>>5;
    __shared__ float red[4];
    float4 v=*(const float4*)&in[row*Dd+tid*4];
    float s=v.x+v.y+v.z+v.w;
    #pragma unroll
    for(int o=16;o;o>>=1)s+=__shfl_xor_sync(0xffffffffu,s,o);
    if(lane==0)red[wid]=s;
    __syncthreads();
    float mu=(red[0]+red[1]+red[2]+red[3])*(1.0f/512.0f);
    __syncthreads();
    float dx=v.x-mu,dy=v.y-mu,dz=v.z-mu,dw=v.w-mu;
    float s2=dx*dx+dy*dy+dz*dz+dw*dw;
    #pragma unroll
    for(int o=16;o;o>>=1)s2+=__shfl_xor_sync(0xffffffffu,s2,o);
    if(lane==0)red[wid]=s2;
    __syncthreads();
    float var=(red[0]+red[1]+red[2]+red[3])*(1.0f/512.0f);
    float inv=rsqrtf(var+1e-12f);
    float4 gv=*(const float4*)&g[tid*4];
    float4 bv=*(const float4*)&bt[tid*4];
    float4 o;
    o.x=dx*inv*gv.x+bv.x; o.y=dy*inv*gv.y+bv.y;
    o.z=dz*inv*gv.z+bv.z; o.w=dw*inv*gv.w+bv.w;
    *(float4*)&out[row*Dd+tid*4]=o;
    uint32_t lo0,hi0=packhi(o.x,o.y,lo0);
    uint32_t lo1,hi1=packhi(o.z,o.w,lo1);
    ((uint32_t*)(oh+row*Dd+tid*4))[0]=hi0; ((uint32_t*)(oh+row*Dd+tid*4))[1]=hi1;
    ((uint32_t*)(ol+row*Dd+tid*4))[0]=lo0; ((uint32_t*)(ol+row*Dd+tid*4))[1]=lo1;
}

__global__ void split_k(const float* __restrict__ s,hf* __restrict__ hi,
                        hf* __restrict__ lo,int n4){
    int i=blockIdx.x*256+threadIdx.x;
    if(i>=n4)return;
    float4 v=((const float4*)s)[i];
    uint32_t lo0,hi0=packhi(v.x,v.y,lo0);
    uint32_t lo1,hi1=packhi(v.z,v.w,lo1);
    ((uint32_t*)hi)[i*2+0]=hi0; ((uint32_t*)hi)[i*2+1]=hi1;
    ((uint32_t*)lo)[i*2+0]=lo0; ((uint32_t*)lo)[i*2+1]=lo1;
}

// ======= weight prep: transpose, single fp16 =====================================
__global__ void wprep_k(const float* __restrict__ Wq,const float* __restrict__ Wk,
                        const float* __restrict__ Wv,const float* __restrict__ Wo,
                        const float* __restrict__ Wi,const float* __restrict__ Wf,
                        hf* __restrict__ wh){
    __shared__ float t[32][33];
    int tile=blockIdx.x;
    int l=tile/3072, r=tile%3072;
    const float* src; size_t off; int K,N;
    if(r<1024){
        int m=r>>8; r&=255;
        src=(m==0?Wq:m==1?Wk:m==2?Wv:Wo)+(size_t)l*Dd*Dd;
        off=(size_t)m*Dd*Dd; K=Dd; N=Dd;
    }else if(r<2048){
        r-=1024; src=Wi+(size_t)l*Dd*Ff; off=4*Dd*Dd; K=Dd; N=Ff;
    }else{
        r-=2048; src=Wf+(size_t)l*Ff*Dd; off=4*Dd*Dd+(size_t)Dd*Ff; K=Ff; N=Dd;
    }
    hf* dh=wh+(size_t)l*LWc+off;
    int ntk=K>>5;
    int n0=(r/ntk)*32, k0=(r%ntk)*32;
    int x=threadIdx.x, y0=threadIdx.y;
    for(int j=y0;j<32;j+=8) t[j][x]=src[(size_t)(k0+j)*N+n0+x];
    __syncthreads();
    for(int j=y0;j<32;j+=8)
        dh[(size_t)(n0+j)*K+k0+x]=__float2half_rn(t[x][j]);
}

__global__ void catb_k(const float* bq,const float* bk,const float* bv,float* o){
    int i=blockIdx.x*256+threadIdx.x;
    if(i>=Ll*3*Dd)return;
    int l=i/(3*Dd), r=i%(3*Dd);
    o[i]= r<Dd ? bq[l*Dd+r] : (r<2*Dd ? bk[l*Dd+r-Dd] : bv[l*Dd+r-2*Dd]);
}

extern "C" void kernel_launch(void* const* d_in, const int* in_sizes, int n_in,
                              void* d_out, int out_size){
    const float* hidden=(const float*)d_in[0];
    const float* pbias=(const float*)d_in[1];
    const long long* ts=(const long long*)d_in[2];
    const float* Wq=(const float*)d_in[3];  const float* bq=(const float*)d_in[4];
    const float* Wk=(const float*)d_in[5];  const float* bk=(const float*)d_in[6];
    const float* Wv=(const float*)d_in[7];  const float* bv=(const float*)d_in[8];
    const float* Wo=(const float*)d_in[9];  const float* bo=(const float*)d_in[10];
    const float* l1g=(const float*)d_in[11];const float* l1b=(const float*)d_in[12];
    const float* Wi=(const float*)d_in[13]; const float* bi=(const float*)d_in[14];
    const float* Wf=(const float*)d_in[15]; const float* bfp=(const float*)d_in[16];
    const float* l2g=(const float*)d_in[17];const float* l2b=(const float*)d_in[18];

    float *px,*pattn,*ptmp,*pcatb;
    cudaGetSymbolAddress((void**)&px,g_x);     cudaGetSymbolAddress((void**)&pattn,g_attn);
    cudaGetSymbolAddress((void**)&ptmp,g_tmp); cudaGetSymbolAddress((void**)&pcatb,g_catb);
    hf *xh,*xl,*qkh,*qkl,*ch,*cl,*ah,*al,*fh,*fl,*wh;
    cudaGetSymbolAddress((void**)&xh,g_xh);   cudaGetSymbolAddress((void**)&xl,g_xl);
    cudaGetSymbolAddress((void**)&qkh,g_qkvh);cudaGetSymbolAddress((void**)&qkl,g_qkvl);
    cudaGetSymbolAddress((void**)&ch,g_ch);   cudaGetSymbolAddress((void**)&cl,g_cl);
    cudaGetSymbolAddress((void**)&ah,g_ah);   cudaGetSymbolAddress((void**)&al,g_al);
    cudaGetSymbolAddress((void**)&fh,g_fh);   cudaGetSymbolAddress((void**)&fl,g_fl);
    cudaGetSymbolAddress((void**)&wh,g_wh);

    cudaFuncSetAttribute(gemm_mma<0,false,1,512>, cudaFuncAttributeMaxDynamicSharedMemorySize,GSMEM);
    cudaFuncSetAttribute(gemm_mma<0,true,0,512>,  cudaFuncAttributeMaxDynamicSharedMemorySize,GSMEM);
    cudaFuncSetAttribute(gemm_mma<1,false,1,512>, cudaFuncAttributeMaxDynamicSharedMemorySize,GSMEM);
    cudaFuncSetAttribute(gemm_mma<0,true,0,2048>, cudaFuncAttributeMaxDynamicSharedMemorySize,GSMEM);
    cudaFuncSetAttribute(flash_k,cudaFuncAttributeMaxDynamicSharedMemorySize,FLSM);

    wprep_k<<<Ll*3072,dim3(32,8)>>>(Wq,Wk,Wv,Wo,Wi,Wf,wh);
    catb_k<<<(Ll*3*Dd+255)/256,256>>>(bq,bk,bv,pcatb);
    const int nD4=Mrows*Dd/4;
    split_k<<<(nD4+255)/256,256>>>(hidden,xh,xl,nD4);

    const dim3 gDD(Dd/128,Mrows/128), gQKV(3*Dd/128,Mrows/128), gDF(Ff/128,Mrows/128);
    const float* X=hidden;
    for(int l=0;l<Ll;l++){
        hf* bh_=wh+(size_t)l*LWc;
        hf* wih=bh_+4*Dd*Dd;
        hf* wfh=wih+(size_t)Dd*Ff;

        gemm_mma<0,false,1,512><<<gQKV,256,GSMEM>>>(xh,xl,bh_,pcatb+l*3*Dd,nullptr,nullptr,qkh,qkl,3*Dd);
        flash_k<<<dim3(4,Bb*Hh),256,FLSM>>>(qkh,qkl,pbias,ts,ch,cl);

        gemm_mma<0,true,0,512><<<gDD,256,GSMEM>>>(ch,cl,bh_+3*Dd*Dd,bo+l*Dd,X,ptmp,nullptr,nullptr,Dd);
        ln_k<<<Mrows,128>>>(ptmp,l1g+l*Dd,l1b+l*Dd,pattn,ah,al);

        gemm_mma<1,false,1,512><<<gDF,256,GSMEM>>>(ah,al,wih,bi+l*Ff,nullptr,nullptr,fh,fl,Ff);
        gemm_mma<0,true,0,2048><<<gDD,256,GSMEM>>>(fh,fl,wfh,bfp+l*Dd,pattn,ptmp,nullptr,nullptr,Dd);
        ln_k<<<Mrows,128>>>(ptmp,l2g+l*Dd,l2b+l*Dd,px,xh,xl);
        X=px;
    }
    cudaMemcpyAsync(d_out,px,(size_t)Mrows*Dd*sizeof(float),cudaMemcpyDeviceToDevice,0);
}

// round 11
// speedup vs baseline: 5.4537x; 1.5941x over previous
#include <cuda_runtime.h>
#include <cuda_fp16.h>
#include <math.h>
#include <stdint.h>

#define Bb 32
#define Ss 512
#define Dd 512
#define Hh 8
#define Ff 2048
#define Ll 4
#define DH 64
#define Mrows (Bb*Ss)
#define LWc ((size_t)(4*Dd*Dd+2*Dd*Ff))

typedef __half hf;

__device__ float g_x[Mrows*Dd];
__device__ float g_attn[Mrows*Dd];
__device__ float g_tmp[Mrows*Dd];
__device__ hf g_xh[Mrows*Dd];
__device__ hf g_qkvh[(size_t)Mrows*3*Dd], g_qkvl[(size_t)Mrows*3*Dd];
__device__ hf g_ch[Mrows*Dd];
__device__ hf g_ah[Mrows*Dd];
__device__ hf g_fh[(size_t)Mrows*Ff];
__device__ hf g_wh[Ll*LWc];
__device__ float g_catb[Ll*3*Dd];

__device__ __forceinline__ float gelu_e(float x){return 0.5f*x*(1.0f+erff(x*0.70710678118654752f));}
__device__ __forceinline__ void cp16(uint32_t d,const void* s){
    asm volatile("cp.async.cg.shared.global [%0], [%1], 16;"::"r"(d),"l"(s));
}
#define CPC() asm volatile("cp.async.commit_group;":::"memory")
#define LDSM4(r0,r1,r2,r3,a) asm volatile("ldmatrix.sync.aligned.m8n8.x4.shared.b16 {%0,%1,%2,%3},[%4];":"=r"(r0),"=r"(r1),"=r"(r2),"=r"(r3):"r"(a))
#define LDSM4T(r0,r1,r2,r3,a) asm volatile("ldmatrix.sync.aligned.m8n8.x4.trans.shared.b16 {%0,%1,%2,%3},[%4];":"=r"(r0),"=r"(r1),"=r"(r2),"=r"(r3):"r"(a))
#define MMA(d,a,b0,b1) asm volatile( \
    "mma.sync.aligned.m16n8k16.row.col.f32.f16.f16.f32 {%0,%1,%2,%3},{%4,%5,%6,%7},{%8,%9},{%0,%1,%2,%3};" \
    :"+f"((d)[0]),"+f"((d)[1]),"+f"((d)[2]),"+f"((d)[3]) \
    :"r"((a)[0]),"r"((a)[1]),"r"((a)[2]),"r"((a)[3]),"r"(b0),"r"(b1))

__device__ __forceinline__ void wsplit(float v, hf& h, hf& l){
    h=__float2half_rn(v); l=__float2half_rn(v-__half2float(h));
}
__device__ __forceinline__ uint32_t packhi(float a,float b,uint32_t& lo){
    hf h0,l0,h1,l1; wsplit(a,h0,l0); wsplit(b,h1,l1);
    __half2 L=__halves2half2(l0,l1); lo=*(uint32_t*)&L;
    __half2 H=__halves2half2(h0,h1); return *(uint32_t*)&H;
}
__device__ __forceinline__ uint32_t pack2(float a,float b){
    __half2 H=__halves2half2(__float2half_rn(a),__float2half_rn(b));
    return *(uint32_t*)&H;
}

// ============== GEMM: pure fp16 (A=hi, W=hi), 1 MMA/tile, 3-stage ================
#define STB2 16384
#define GSMEM (3*STB2)
__device__ __forceinline__ void load_stage(uint32_t st,int tid,
    const hf* Ah,const hf* Bh,int m0,int n0,int k0,int K){
    #pragma unroll
    for(int i=0;i<4;i++){
        int id=i*256+tid;
        int reg=id>>9, rid=id&511, row=rid>>2, c=rid&3;
        const hf* src=reg? Bh+(size_t)(n0+row)*K+k0+c*8 : Ah+(size_t)(m0+row)*K+k0+c*8;
        cp16(st+reg*8192+row*64+((c^((row>>1)&3))*16),src);
    }
    CPC();
}

// OUT: 0=fp32, 1=fp16 hi+lo, 2=fp16 hi only
template<int ACT, bool RES, int OUT, int KT>
__global__ void __launch_bounds__(256,2)
gemm_mma(const hf* __restrict__ Ah,const hf* __restrict__ Bh,
         const float* __restrict__ bias,const float* __restrict__ res,
         float* __restrict__ C,hf* __restrict__ Ch,hf* __restrict__ Cl,
         int N){
    extern __shared__ char sm[];
    uint32_t sb=(uint32_t)__cvta_generic_to_shared(sm);
    const int tid=threadIdx.x, wid=tid>>5, lane=tid&31;
    const int n0=blockIdx.x*128, m0=blockIdx.y*128;
    const int wm=(wid>>2)*64, wn=(wid&3)*32;
    constexpr int chunks=KT>>5;
    float acc[4][4][4];
    #pragma unroll
    for(int i=0;i<4;i++)
        #pragma unroll
        for(int j=0;j<4;j++){acc[i][j][0]=0;acc[i][j][1]=0;acc[i][j][2]=0;acc[i][j][3]=0;}
    load_stage(sb,tid,Ah,Bh,m0,n0,0,KT);
    load_stage(sb+STB2,tid,Ah,Bh,m0,n0,32,KT);
    const int arow=lane&15, ah8=lane>>4;
    int s2=2;
    for(int c=0;c<chunks;c++){
        uint32_t st=sb+(c%3)*STB2;
        if(c<chunks-1) asm volatile("cp.async.wait_group 1;":::"memory");
        else           asm volatile("cp.async.wait_group 0;":::"memory");
        __syncthreads();
        if(c+2<chunks){
            load_stage(sb+s2*STB2,tid,Ah,Bh,m0,n0,(c+2)*32,KT);
            s2++; if(s2==3)s2=0;
        }
        #pragma unroll
        for(int s=0;s<2;s++){
            uint32_t bhf[2][4];
            #pragma unroll
            for(int nq=0;nq<2;nq++){
                int row=wn+nq*16+arow;
                uint32_t ad=st+8192+row*64+(((s*2+ah8)^((row>>1)&3))*16);
                LDSM4(bhf[nq][0],bhf[nq][1],bhf[nq][2],bhf[nq][3],ad);
            }
            #pragma unroll
            for(int mi=0;mi<4;mi++){
                uint32_t ahf[4];
                int row=wm+mi*16+arow;
                uint32_t ad=st+row*64+(((s*2+ah8)^((row>>1)&3))*16);
                LDSM4(ahf[0],ahf[1],ahf[2],ahf[3],ad);
                #pragma unroll
                for(int nq=0;nq<2;nq++)
                    #pragma unroll
                    for(int p=0;p<2;p++)
                        MMA(acc[mi][nq*2+p],ahf,bhf[nq][p],bhf[nq][p+2]);
            }
        }
    }
    const int r4=lane>>2, c2=(lane&3)*2;
    #pragma unroll
    for(int mi=0;mi<4;mi++)
        #pragma unroll
        for(int nt=0;nt<4;nt++){
            int col=n0+wn+nt*8+c2;
            float2 bv=*(const float2*)&bias[col];
            #pragma unroll
            for(int hr=0;hr<2;hr++){
                int row=m0+wm+mi*16+r4+hr*8;
                float2 o;
                o.x=acc[mi][nt][hr*2+0]+bv.x;
                o.y=acc[mi][nt][hr*2+1]+bv.y;
                if(RES){float2 rv=*(const float2*)&res[(size_t)row*N+col]; o.x+=rv.x;o.y+=rv.y;}
                if(ACT==1){o.x=gelu_e(o.x);o.y=gelu_e(o.y);}
                if(OUT==0){
                    *(float2*)&C[(size_t)row*N+col]=o;
                }else if(OUT==1){
                    uint32_t lo,hi=packhi(o.x,o.y,lo);
                    *(uint32_t*)&Ch[(size_t)row*N+col]=hi;
                    *(uint32_t*)&Cl[(size_t)row*N+col]=lo;
                }else{
                    *(uint32_t*)&Ch[(size_t)row*N+col]=pack2(o.x,o.y);
                }
            }
        }
}

// ===== flash attention: Q=hi+lo, K=hi, V=hi; P=hi+lo. 2 MMA per product ==========
#define FLSM (32768 + 2*16384)
__global__ void __launch_bounds__(256,2)
flash_k(const hf* __restrict__ qkvh,const hf* __restrict__ qkvl,
        const float* __restrict__ pbias,const long long* __restrict__ ts,
        hf* __restrict__ Ch){
    extern __shared__ char sm[];
    uint32_t sb=(uint32_t)__cvta_generic_to_shared(sm);
    const int tid=threadIdx.x, wid=tid>>5, lane=tid&31;
    const int bh=blockIdx.y, b=bh>>3, h=bh&7;
    const int q0=blockIdx.x*128;
    const int wm=wid*16;
    const int arow=lane&15, ah8=lane>>4, r4=lane>>2, j2=(lane&3)*2;

    // Q hi (16KB) + Q lo (16KB)
    #pragma unroll
    for(int i=0;i<8;i++){
        int id=i*256+tid;
        int reg=id>>10, rid=id&1023, row=rid>>3, c=rid&7;
        const hf* src=(reg?qkvl:qkvh)+(size_t)(b*Ss+q0+row)*1536+h*DH+c*8;
        cp16(sb+reg*16384+row*128+((c^(row&7))*16),src);
    }
    CPC();

    // per KV stage: K hi (8KB) + V hi (8KB)
    auto loadkv=[&](int st,int k0){
        #pragma unroll
        for(int i=0;i<4;i++){
            int id=i*256+tid;
            int part=id>>9, rid=id&511, row=rid>>3, c=rid&7;
            int colb=part? (2*Dd+h*DH) : (Dd+h*DH);
            const hf* src=qkvh+(size_t)(b*Ss+k0+row)*1536+colb+c*8;
            cp16(sb+32768+st*16384+part*8192+row*128+((c^(row&7))*16),src);
        }
        CPC();
    };
    loadkv(0,0); loadkv(1,64);

    float m0_=-1e30f, m1_=-1e30f, l0_=0.0f, l1_=0.0f;
    float oacc[8][4];
    #pragma unroll
    for(int i=0;i<8;i++){oacc[i][0]=0;oacc[i][1]=0;oacc[i][2]=0;oacc[i][3]=0;}
    const long long tq0=ts[b*Ss+q0+wm+r4], tq1=ts[b*Ss+q0+wm+r4+8];
    const int qi0=q0+wm+r4, qi1=qi0+8;

    for(int t=0;t<8;t++){
        uint32_t stv=sb+32768+(t&1)*16384;
        if(t<6) asm volatile("cp.async.wait_group 1;":::"memory");
        else    asm volatile("cp.async.wait_group 0;":::"memory");
        __syncthreads();

        float sacc[8][4];
        #pragma unroll
        for(int i=0;i<8;i++){sacc[i][0]=0;sacc[i][1]=0;sacc[i][2]=0;sacc[i][3]=0;}
        #pragma unroll
        for(int kt=0;kt<4;kt++){
            uint32_t qh_[4],ql_[4];
            {
                int row=wm+arow;
                uint32_t ad=sb+row*128+(((kt*2+ah8)^(row&7))*16);
                LDSM4(qh_[0],qh_[1],qh_[2],qh_[3],ad);
                LDSM4(ql_[0],ql_[1],ql_[2],ql_[3],ad+16384);
            }
            #pragma unroll
            for(int nq=0;nq<4;nq++){
                int row=nq*16+arow;
                uint32_t ad=stv+row*128+(((kt*2+ah8)^(row&7))*16);
                uint32_t kh_[4];
                LDSM4(kh_[0],kh_[1],kh_[2],kh_[3],ad);
                #pragma unroll
                for(int p=0;p<2;p++){
                    int nt=nq*2+p;
                    MMA(sacc[nt],qh_,kh_[p],kh_[p+2]);
                    MMA(sacc[nt],ql_,kh_[p],kh_[p+2]);
                }
            }
        }
        int k0=t*64;
        #pragma unroll
        for(int nt=0;nt<8;nt++){
            int kc=k0+nt*8+j2;
            long long tk0=ts[b*Ss+kc], tk1=ts[b*Ss+kc+1];
            {
                float2 pb=*(const float2*)&pbias[((size_t)(h*Ss+qi0))*Ss+kc];
                float la=(float)(tq0-tk0)*(1.0f/60000.0f);
                float lb=(float)(tq0-tk1)*(1.0f/60000.0f);
                float sa=9.0f-__fdividef(1.0f,fmaxf(la,0.0f)+1.0f);
                float sbb=9.0f-__fdividef(1.0f,fmaxf(lb,0.0f)+1.0f);
                sacc[nt][0]=__fdividef(sacc[nt][0],sa)+pb.x;
                sacc[nt][1]=__fdividef(sacc[nt][1],sbb)+pb.y;
            }
            {
                float2 pb=*(const float2*)&pbias[((size_t)(h*Ss+qi1))*Ss+kc];
                float la=(float)(tq1-tk0)*(1.0f/60000.0f);
                float lb=(float)(tq1-tk1)*(1.0f/60000.0f);
                float sa=9.0f-__fdividef(1.0f,fmaxf(la,0.0f)+1.0f);
                float sbb=9.0f-__fdividef(1.0f,fmaxf(lb,0.0f)+1.0f);
                sacc[nt][2]=__fdividef(sacc[nt][2],sa)+pb.x;
                sacc[nt][3]=__fdividef(sacc[nt][3],sbb)+pb.y;
            }
        }
        float tm0=-1e30f, tm1=-1e30f;
        #pragma unroll
        for(int nt=0;nt<8;nt++){
            tm0=fmaxf(tm0,fmaxf(sacc[nt][0],sacc[nt][1]));
            tm1=fmaxf(tm1,fmaxf(sacc[nt][2],sacc[nt][3]));
        }
        tm0=fmaxf(tm0,__shfl_xor_sync(0xffffffffu,tm0,1));
        tm0=fmaxf(tm0,__shfl_xor_sync(0xffffffffu,tm0,2));
        tm1=fmaxf(tm1,__shfl_xor_sync(0xffffffffu,tm1,1));
        tm1=fmaxf(tm1,__shfl_xor_sync(0xffffffffu,tm1,2));
        float mn0=fmaxf(m0_,tm0), mn1=fmaxf(m1_,tm1);
        float al0=__expf(m0_-mn0), al1=__expf(m1_-mn1);
        m0_=mn0; m1_=mn1;
        float s0=0.0f, s1=0.0f;
        #pragma unroll
        for(int nt=0;nt<8;nt++){
            sacc[nt][0]=__expf(sacc[nt][0]-mn0); s0+=sacc[nt][0];
            sacc[nt][1]=__expf(sacc[nt][1]-mn0); s0+=sacc[nt][1];
            sacc[nt][2]=__expf(sacc[nt][2]-mn1); s1+=sacc[nt][2];
            sacc[nt][3]=__expf(sacc[nt][3]-mn1); s1+=sacc[nt][3];
        }
        s0+=__shfl_xor_sync(0xffffffffu,s0,1); s0+=__shfl_xor_sync(0xffffffffu,s0,2);
        s1+=__shfl_xor_sync(0xffffffffu,s1,1); s1+=__shfl_xor_sync(0xffffffffu,s1,2);
        l0_=l0_*al0+s0; l1_=l1_*al1+s1;
        #pragma unroll
        for(int nt=0;nt<8;nt++){
            oacc[nt][0]*=al0; oacc[nt][1]*=al0;
            oacc[nt][2]*=al1; oacc[nt][3]*=al1;
        }
        uint32_t ph_[4][4], pl_[4][4];
        #pragma unroll
        for(int kt=0;kt<4;kt++){
            ph_[kt][0]=packhi(sacc[2*kt][0],  sacc[2*kt][1],  pl_[kt][0]);
            ph_[kt][1]=packhi(sacc[2*kt][2],  sacc[2*kt][3],  pl_[kt][1]);
            ph_[kt][2]=packhi(sacc[2*kt+1][0],sacc[2*kt+1][1],pl_[kt][2]);
            ph_[kt][3]=packhi(sacc[2*kt+1][2],sacc[2*kt+1][3],pl_[kt][3]);
        }
        #pragma unroll
        for(int kt=0;kt<4;kt++){
            #pragma unroll
            for(int dg=0;dg<4;dg++){
                int row=kt*16+((lane>>3)&1)*8+(lane&7);
                int ch_=dg*2+(lane>>4);
                uint32_t ad=stv+8192+row*128+((ch_^(row&7))*16);
                uint32_t vh_[4];
                LDSM4T(vh_[0],vh_[1],vh_[2],vh_[3],ad);
                #pragma unroll
                for(int p=0;p<2;p++){
                    int nt=dg*2+p;
                    MMA(oacc[nt],ph_[kt],vh_[p*2],vh_[p*2+1]);
                    MMA(oacc[nt],pl_[kt],vh_[p*2],vh_[p*2+1]);
                }
            }
        }
        __syncthreads();
        if(t<6) loadkv(t&1,(t+2)*64);
    }
    float inv0=__fdividef(1.0f,l0_), inv1=__fdividef(1.0f,l1_);
    #pragma unroll
    for(int nt=0;nt<8;nt++){
        int dh=nt*8+j2;
        *(uint32_t*)&Ch[((size_t)(b*Ss+qi0))*Dd+h*DH+dh]=pack2(oacc[nt][0]*inv0,oacc[nt][1]*inv0);
        *(uint32_t*)&Ch[((size_t)(b*Ss+qi1))*Dd+h*DH+dh]=pack2(oacc[nt][2]*inv1,oacc[nt][3]*inv1);
    }
}

// ================= LayerNorm: fp32 out + fp16 hi out ============================
__global__ void ln_k(const float* __restrict__ in,const float* __restrict__ g,
                     const float* __restrict__ bt,float* __restrict__ out,
                     hf* __restrict__ oh){
    const size_t row=blockIdx.x;
    const int tid=threadIdx.x, lane=tid&31, wid=tid>>5;
    __shared__ float red[4];
    float4 v=*(const float4*)&in[row*Dd+tid*4];
    float s=v.x+v.y+v.z+v.w;
    #pragma unroll
    for(int o=16;o;o>>=1)s+=__shfl_xor_sync(0xffffffffu,s,o);
    if(lane==0)red[wid]=s;
    __syncthreads();
    float mu=(red[0]+red[1]+red[2]+red[3])*(1.0f/512.0f);
    __syncthreads();
    float dx=v.x-mu,dy=v.y-mu,dz=v.z-mu,dw=v.w-mu;
    float s2=dx*dx+dy*dy+dz*dz+dw*dw;
    #pragma unroll
    for(int o=16;o;o>>=1)s2+=__shfl_xor_sync(0xffffffffu,s2,o);
    if(lane==0)red[wid]=s2;
    __syncthreads();
    float var=(red[0]+red[1]+red[2]+red[3])*(1.0f/512.0f);
    float inv=rsqrtf(var+1e-12f);
    float4 gv=*(const float4*)&g[tid*4];
    float4 bv=*(const float4*)&bt[tid*4];
    float4 o;
    o.x=dx*inv*gv.x+bv.x; o.y=dy*inv*gv.y+bv.y;
    o.z=dz*inv*gv.z+bv.z; o.w=dw*inv*gv.w+bv.w;
    *(float4*)&out[row*Dd+tid*4]=o;
    ((uint32_t*)(oh+row*Dd+tid*4))[0]=pack2(o.x,o.y);
    ((uint32_t*)(oh+row*Dd+tid*4))[1]=pack2(o.z,o.w);
}

__global__ void split_k(const float* __restrict__ s,hf* __restrict__ hi,int n4){
    int i=blockIdx.x*256+threadIdx.x;
    if(i>=n4)return;
    float4 v=((const float4*)s)[i];
    ((uint32_t*)hi)[i*2+0]=pack2(v.x,v.y);
    ((uint32_t*)hi)[i*2+1]=pack2(v.z,v.w);
}

// ======= weight prep: transpose, single fp16 =====================================
__global__ void wprep_k(const float* __restrict__ Wq,const float* __restrict__ Wk,
                        const float* __restrict__ Wv,const float* __restrict__ Wo,
                        const float* __restrict__ Wi,const float* __restrict__ Wf,
                        hf* __restrict__ wh){
    __shared__ float t[32][33];
    int tile=blockIdx.x;
    int l=tile/3072, r=tile%3072;
    const float* src; size_t off; int K,N;
    if(r<1024){
        int m=r>>8; r&=255;
        src=(m==0?Wq:m==1?Wk:m==2?Wv:Wo)+(size_t)l*Dd*Dd;
        off=(size_t)m*Dd*Dd; K=Dd; N=Dd;
    }else if(r<2048){
        r-=1024; src=Wi+(size_t)l*Dd*Ff; off=4*Dd*Dd; K=Dd; N=Ff;
    }else{
        r-=2048; src=Wf+(size_t)l*Ff*Dd; off=4*Dd*Dd+(size_t)Dd*Ff; K=Ff; N=Dd;
    }
    hf* dh=wh+(size_t)l*LWc+off;
    int ntk=K>>5;
    int n0=(r/ntk)*32, k0=(r%ntk)*32;
    int x=threadIdx.x, y0=threadIdx.y;
    for(int j=y0;j<32;j+=8) t[j][x]=src[(size_t)(k0+j)*N+n0+x];
    __syncthreads();
    for(int j=y0;j<32;j+=8)
        dh[(size_t)(n0+j)*K+k0+x]=__float2half_rn(t[x][j]);
}

__global__ void catb_k(const float* bq,const float* bk,const float* bv,float* o){
    int i=blockIdx.x*256+threadIdx.x;
    if(i>=Ll*3*Dd)return;
    int l=i/(3*Dd), r=i%(3*Dd);
    o[i]= r<Dd ? bq[l*Dd+r] : (r<2*Dd ? bk[l*Dd+r-Dd] : bv[l*Dd+r-2*Dd]);
}

extern "C" void kernel_launch(void* const* d_in, const int* in_sizes, int n_in,
                              void* d_out, int out_size){
    const float* hidden=(const float*)d_in[0];
    const float* pbias=(const float*)d_in[1];
    const long long* ts=(const long long*)d_in[2];
    const float* Wq=(const float*)d_in[3];  const float* bq=(const float*)d_in[4];
    const float* Wk=(const float*)d_in[5];  const float* bk=(const float*)d_in[6];
    const float* Wv=(const float*)d_in[7];  const float* bv=(const float*)d_in[8];
    const float* Wo=(const float*)d_in[9];  const float* bo=(const float*)d_in[10];
    const float* l1g=(const float*)d_in[11];const float* l1b=(const float*)d_in[12];
    const float* Wi=(const float*)d_in[13]; const float* bi=(const float*)d_in[14];
    const float* Wf=(const float*)d_in[15]; const float* bfp=(const float*)d_in[16];
    const float* l2g=(const float*)d_in[17];const float* l2b=(const float*)d_in[18];

    float *px,*pattn,*ptmp,*pcatb;
    cudaGetSymbolAddress((void**)&px,g_x);     cudaGetSymbolAddress((void**)&pattn,g_attn);
    cudaGetSymbolAddress((void**)&ptmp,g_tmp); cudaGetSymbolAddress((void**)&pcatb,g_catb);
    hf *xh,*qkh,*qkl,*ch,*ah,*fh,*wh;
    cudaGetSymbolAddress((void**)&xh,g_xh);
    cudaGetSymbolAddress((void**)&qkh,g_qkvh);cudaGetSymbolAddress((void**)&qkl,g_qkvl);
    cudaGetSymbolAddress((void**)&ch,g_ch);
    cudaGetSymbolAddress((void**)&ah,g_ah);
    cudaGetSymbolAddress((void**)&fh,g_fh);
    cudaGetSymbolAddress((void**)&wh,g_wh);

    cudaFuncSetAttribute(gemm_mma<0,false,1,512>, cudaFuncAttributeMaxDynamicSharedMemorySize,GSMEM);
    cudaFuncSetAttribute(gemm_mma<0,true,0,512>,  cudaFuncAttributeMaxDynamicSharedMemorySize,GSMEM);
    cudaFuncSetAttribute(gemm_mma<1,false,2,512>, cudaFuncAttributeMaxDynamicSharedMemorySize,GSMEM);
    cudaFuncSetAttribute(gemm_mma<0,true,0,2048>, cudaFuncAttributeMaxDynamicSharedMemorySize,GSMEM);
    cudaFuncSetAttribute(flash_k,cudaFuncAttributeMaxDynamicSharedMemorySize,FLSM);

    wprep_k<<<Ll*3072,dim3(32,8)>>>(Wq,Wk,Wv,Wo,Wi,Wf,wh);
    catb_k<<<(Ll*3*Dd+255)/256,256>>>(bq,bk,bv,pcatb);
    const int nD4=Mrows*Dd/4;
    split_k<<<(nD4+255)/256,256>>>(hidden,xh,nD4);

    const dim3 gDD(Dd/128,Mrows/128), gQKV(3*Dd/128,Mrows/128), gDF(Ff/128,Mrows/128);
    const float* X=hidden;
    for(int l=0;l<Ll;l++){
        hf* bh_=wh+(size_t)l*LWc;
        hf* wih=bh_+4*Dd*Dd;
        hf* wfh=wih+(size_t)Dd*Ff;

        gemm_mma<0,false,1,512><<<gQKV,256,GSMEM>>>(xh,bh_,pcatb+l*3*Dd,nullptr,nullptr,qkh,qkl,3*Dd);
        flash_k<<<dim3(4,Bb*Hh),256,FLSM>>>(qkh,qkl,pbias,ts,ch);

        gemm_mma<0,true,0,512><<<gDD,256,GSMEM>>>(ch,bh_+3*Dd*Dd,bo+l*Dd,X,ptmp,nullptr,nullptr,Dd);
        ln_k<<<Mrows,128>>>(ptmp,l1g+l*Dd,l1b+l*Dd,pattn,ah);

        gemm_mma<1,false,2,512><<<gDF,256,GSMEM>>>(ah,wih,bi+l*Ff,nullptr,nullptr,fh,nullptr,Ff);
        gemm_mma<0,true,0,2048><<<gDD,256,GSMEM>>>(fh,wfh,bfp+l*Dd,pattn,ptmp,nullptr,nullptr,Dd);
        ln_k<<<Mrows,128>>>(ptmp,l2g+l*Dd,l2b+l*Dd,px,xh);
        X=px;
    }
    cudaMemcpyAsync(d_out,px,(size_t)Mrows*Dd*sizeof(float),cudaMemcpyDeviceToDevice,0);
}

// round 12
// speedup vs baseline: 5.8244x; 1.0680x over previous
#include <cuda_runtime.h>
#include <cuda_fp16.h>
#include <math.h>
#include <stdint.h>

#define Bb 32
#define Ss 512
#define Dd 512
#define Hh 8
#define Ff 2048
#define Ll 4
#define DH 64
#define Mrows (Bb*Ss)
#define LWc ((size_t)(4*Dd*Dd+2*Dd*Ff))

typedef __half hf;

__device__ float g_x[Mrows*Dd];
__device__ float g_attn[Mrows*Dd];
__device__ float g_tmp[Mrows*Dd];
__device__ hf g_xh[Mrows*Dd];
__device__ hf g_qkvh[(size_t)Mrows*3*Dd], g_qkvl[(size_t)Mrows*3*Dd];
__device__ hf g_ch[Mrows*Dd];
__device__ hf g_ah[Mrows*Dd];
__device__ hf g_fh[(size_t)Mrows*Ff];
__device__ hf g_wh[Ll*LWc];
__device__ float g_catb[Ll*3*Dd];

__device__ __forceinline__ float gelu_e(float x){return 0.5f*x*(1.0f+erff(x*0.70710678118654752f));}
__device__ __forceinline__ void cp16(uint32_t d,const void* s){
    asm volatile("cp.async.cg.shared.global [%0], [%1], 16;"::"r"(d),"l"(s));
}
#define CPC() asm volatile("cp.async.commit_group;":::"memory")
#define LDSM4(r0,r1,r2,r3,a) asm volatile("ldmatrix.sync.aligned.m8n8.x4.shared.b16 {%0,%1,%2,%3},[%4];":"=r"(r0),"=r"(r1),"=r"(r2),"=r"(r3):"r"(a))
#define LDSM4T(r0,r1,r2,r3,a) asm volatile("ldmatrix.sync.aligned.m8n8.x4.trans.shared.b16 {%0,%1,%2,%3},[%4];":"=r"(r0),"=r"(r1),"=r"(r2),"=r"(r3):"r"(a))
#define MMA(d,a,b0,b1) asm volatile( \
    "mma.sync.aligned.m16n8k16.row.col.f32.f16.f16.f32 {%0,%1,%2,%3},{%4,%5,%6,%7},{%8,%9},{%0,%1,%2,%3};" \
    :"+f"((d)[0]),"+f"((d)[1]),"+f"((d)[2]),"+f"((d)[3]) \
    :"r"((a)[0]),"r"((a)[1]),"r"((a)[2]),"r"((a)[3]),"r"(b0),"r"(b1))

__device__ __forceinline__ void wsplit(float v, hf& h, hf& l){
    h=__float2half_rn(v); l=__float2half_rn(v-__half2float(h));
}
__device__ __forceinline__ uint32_t packhi(float a,float b,uint32_t& lo){
    hf h0,l0,h1,l1; wsplit(a,h0,l0); wsplit(b,h1,l1);
    __half2 L=__halves2half2(l0,l1); lo=*(uint32_t*)&L;
    __half2 H=__halves2half2(h0,h1); return *(uint32_t*)&H;
}
__device__ __forceinline__ uint32_t pack2(float a,float b){
    __half2 H=__halves2half2(__float2half_rn(a),__float2half_rn(b));
    return *(uint32_t*)&H;
}

// ============== GEMM: pure fp16, BK=64, 3-stage =================================
#define STB2 32768
#define GSMEM (3*STB2)
__device__ __forceinline__ void load_stage(uint32_t st,int tid,
    const hf* Ah,const hf* Bh,int m0,int n0,int k0,int K){
    #pragma unroll
    for(int i=0;i<8;i++){
        int id=i*256+tid;
        int reg=id>>10, rid=id&1023, row=rid>>3, c=rid&7;
        const hf* src=reg? Bh+(size_t)(n0+row)*K+k0+c*8 : Ah+(size_t)(m0+row)*K+k0+c*8;
        cp16(st+reg*16384+row*128+((c^(row&7))*16),src);
    }
    CPC();
}

// OUT: 0=fp32, 1=fp16 hi (+lo for col<Dd), 2=fp16 hi only
template<int ACT, bool RES, int OUT, int KT>
__global__ void __launch_bounds__(256,2)
gemm_mma(const hf* __restrict__ Ah,const hf* __restrict__ Bh,
         const float* __restrict__ bias,const float* __restrict__ res,
         float* __restrict__ C,hf* __restrict__ Ch,hf* __restrict__ Cl,
         int N){
    extern __shared__ char sm[];
    uint32_t sb=(uint32_t)__cvta_generic_to_shared(sm);
    const int tid=threadIdx.x, wid=tid>>5, lane=tid&31;
    const int n0=blockIdx.x*128, m0=blockIdx.y*128;
    const int wm=(wid>>2)*64, wn=(wid&3)*32;
    constexpr int chunks=KT>>6;
    float acc[4][4][4];
    #pragma unroll
    for(int i=0;i<4;i++)
        #pragma unroll
        for(int j=0;j<4;j++){acc[i][j][0]=0;acc[i][j][1]=0;acc[i][j][2]=0;acc[i][j][3]=0;}
    load_stage(sb,tid,Ah,Bh,m0,n0,0,KT);
    load_stage(sb+STB2,tid,Ah,Bh,m0,n0,64,KT);
    const int arow=lane&15, ah8=lane>>4;
    int s2=2;
    for(int c=0;c<chunks;c++){
        uint32_t st=sb+(c%3)*STB2;
        if(c<chunks-1) asm volatile("cp.async.wait_group 1;":::"memory");
        else           asm volatile("cp.async.wait_group 0;":::"memory");
        __syncthreads();
        if(c+2<chunks){
            load_stage(sb+s2*STB2,tid,Ah,Bh,m0,n0,(c+2)*64,KT);
            s2++; if(s2==3)s2=0;
        }
        #pragma unroll
        for(int s=0;s<4;s++){
            uint32_t bhf[2][4];
            #pragma unroll
            for(int nq=0;nq<2;nq++){
                int row=wn+nq*16+arow;
                uint32_t ad=st+16384+row*128+(((s*2+ah8)^(row&7))*16);
                LDSM4(bhf[nq][0],bhf[nq][1],bhf[nq][2],bhf[nq][3],ad);
            }
            #pragma unroll
            for(int mi=0;mi<4;mi++){
                uint32_t ahf[4];
                int row=wm+mi*16+arow;
                uint32_t ad=st+row*128+(((s*2+ah8)^(row&7))*16);
                LDSM4(ahf[0],ahf[1],ahf[2],ahf[3],ad);
                #pragma unroll
                for(int nq=0;nq<2;nq++)
                    #pragma unroll
                    for(int p=0;p<2;p++)
                        MMA(acc[mi][nq*2+p],ahf,bhf[nq][p],bhf[nq][p+2]);
            }
        }
    }
    const int r4=lane>>2, c2=(lane&3)*2;
    #pragma unroll
    for(int mi=0;mi<4;mi++)
        #pragma unroll
        for(int nt=0;nt<4;nt++){
            int col=n0+wn+nt*8+c2;
            float2 bv=*(const float2*)&bias[col];
            #pragma unroll
            for(int hr=0;hr<2;hr++){
                int row=m0+wm+mi*16+r4+hr*8;
                float2 o;
                o.x=acc[mi][nt][hr*2+0]+bv.x;
                o.y=acc[mi][nt][hr*2+1]+bv.y;
                if(RES){float2 rv=*(const float2*)&res[(size_t)row*N+col]; o.x+=rv.x;o.y+=rv.y;}
                if(ACT==1){o.x=gelu_e(o.x);o.y=gelu_e(o.y);}
                if(OUT==0){
                    *(float2*)&C[(size_t)row*N+col]=o;
                }else if(OUT==1){
                    uint32_t lo,hi=packhi(o.x,o.y,lo);
                    *(uint32_t*)&Ch[(size_t)row*N+col]=hi;
                    if(col<Dd) *(uint32_t*)&Cl[(size_t)row*N+col]=lo;
                }else{
                    *(uint32_t*)&Ch[(size_t)row*N+col]=pack2(o.x,o.y);
                }
            }
        }
}

// ===== flash attention: Q=hi+lo, K=hi, V=hi; P=hi. QK 2-MMA, PV 1-MMA ===========
#define FLSM (32768 + 2*16384)
__global__ void __launch_bounds__(256,2)
flash_k(const hf* __restrict__ qkvh,const hf* __restrict__ qkvl,
        const float* __restrict__ pbias,const long long* __restrict__ ts,
        hf* __restrict__ Ch){
    extern __shared__ char sm[];
    uint32_t sb=(uint32_t)__cvta_generic_to_shared(sm);
    const int tid=threadIdx.x, wid=tid>>5, lane=tid&31;
    const int bh=blockIdx.y, b=bh>>3, h=bh&7;
    const int q0=blockIdx.x*128;
    const int wm=wid*16;
    const int arow=lane&15, ah8=lane>>4, r4=lane>>2, j2=(lane&3)*2;

    #pragma unroll
    for(int i=0;i<8;i++){
        int id=i*256+tid;
        int reg=id>>10, rid=id&1023, row=rid>>3, c=rid&7;
        const hf* src=(reg?qkvl:qkvh)+(size_t)(b*Ss+q0+row)*1536+h*DH+c*8;
        cp16(sb+reg*16384+row*128+((c^(row&7))*16),src);
    }
    CPC();

    auto loadkv=[&](int st,int k0){
        #pragma unroll
        for(int i=0;i<4;i++){
            int id=i*256+tid;
            int part=id>>9, rid=id&511, row=rid>>3, c=rid&7;
            int colb=part? (2*Dd+h*DH) : (Dd+h*DH);
            const hf* src=qkvh+(size_t)(b*Ss+k0+row)*1536+colb+c*8;
            cp16(sb+32768+st*16384+part*8192+row*128+((c^(row&7))*16),src);
        }
        CPC();
    };
    loadkv(0,0); loadkv(1,64);

    float m0_=-1e30f, m1_=-1e30f, l0_=0.0f, l1_=0.0f;
    float oacc[8][4];
    #pragma unroll
    for(int i=0;i<8;i++){oacc[i][0]=0;oacc[i][1]=0;oacc[i][2]=0;oacc[i][3]=0;}
    const long long tq0=ts[b*Ss+q0+wm+r4], tq1=ts[b*Ss+q0+wm+r4+8];
    const int qi0=q0+wm+r4, qi1=qi0+8;

    for(int t=0;t<8;t++){
        uint32_t stv=sb+32768+(t&1)*16384;
        if(t<6) asm volatile("cp.async.wait_group 1;":::"memory");
        else    asm volatile("cp.async.wait_group 0;":::"memory");
        __syncthreads();

        float sacc[8][4];
        #pragma unroll
        for(int i=0;i<8;i++){sacc[i][0]=0;sacc[i][1]=0;sacc[i][2]=0;sacc[i][3]=0;}
        #pragma unroll
        for(int kt=0;kt<4;kt++){
            uint32_t qh_[4],ql_[4];
            {
                int row=wm+arow;
                uint32_t ad=sb+row*128+(((kt*2+ah8)^(row&7))*16);
                LDSM4(qh_[0],qh_[1],qh_[2],qh_[3],ad);
                LDSM4(ql_[0],ql_[1],ql_[2],ql_[3],ad+16384);
            }
            #pragma unroll
            for(int nq=0;nq<4;nq++){
                int row=nq*16+arow;
                uint32_t ad=stv+row*128+(((kt*2+ah8)^(row&7))*16);
                uint32_t kh_[4];
                LDSM4(kh_[0],kh_[1],kh_[2],kh_[3],ad);
                #pragma unroll
                for(int p=0;p<2;p++){
                    int nt=nq*2+p;
                    MMA(sacc[nt],qh_,kh_[p],kh_[p+2]);
                    MMA(sacc[nt],ql_,kh_[p],kh_[p+2]);
                }
            }
        }
        int k0=t*64;
        #pragma unroll
        for(int nt=0;nt<8;nt++){
            int kc=k0+nt*8+j2;
            long long tk0=ts[b*Ss+kc], tk1=ts[b*Ss+kc+1];
            {
                float2 pb=*(const float2*)&pbias[((size_t)(h*Ss+qi0))*Ss+kc];
                float la=(float)(tq0-tk0)*(1.0f/60000.0f);
                float lb=(float)(tq0-tk1)*(1.0f/60000.0f);
                float sa=9.0f-__fdividef(1.0f,fmaxf(la,0.0f)+1.0f);
                float sbb=9.0f-__fdividef(1.0f,fmaxf(lb,0.0f)+1.0f);
                sacc[nt][0]=__fdividef(sacc[nt][0],sa)+pb.x;
                sacc[nt][1]=__fdividef(sacc[nt][1],sbb)+pb.y;
            }
            {
                float2 pb=*(const float2*)&pbias[((size_t)(h*Ss+qi1))*Ss+kc];
                float la=(float)(tq1-tk0)*(1.0f/60000.0f);
                float lb=(float)(tq1-tk1)*(1.0f/60000.0f);
                float sa=9.0f-__fdividef(1.0f,fmaxf(la,0.0f)+1.0f);
                float sbb=9.0f-__fdividef(1.0f,fmaxf(lb,0.0f)+1.0f);
                sacc[nt][2]=__fdividef(sacc[nt][2],sa)+pb.x;
                sacc[nt][3]=__fdividef(sacc[nt][3],sbb)+pb.y;
            }
        }
        float tm0=-1e30f, tm1=-1e30f;
        #pragma unroll
        for(int nt=0;nt<8;nt++){
            tm0=fmaxf(tm0,fmaxf(sacc[nt][0],sacc[nt][1]));
            tm1=fmaxf(tm1,fmaxf(sacc[nt][2],sacc[nt][3]));
        }
        tm0=fmaxf(tm0,__shfl_xor_sync(0xffffffffu,tm0,1));
        tm0=fmaxf(tm0,__shfl_xor_sync(0xffffffffu,tm0,2));
        tm1=fmaxf(tm1,__shfl_xor_sync(0xffffffffu,tm1,1));
        tm1=fmaxf(tm1,__shfl_xor_sync(0xffffffffu,tm1,2));
        float mn0=fmaxf(m0_,tm0), mn1=fmaxf(m1_,tm1);
        float al0=__expf(m0_-mn0), al1=__expf(m1_-mn1);
        m0_=mn0; m1_=mn1;
        float s0=0.0f, s1=0.0f;
        #pragma unroll
        for(int nt=0;nt<8;nt++){
            sacc[nt][0]=__expf(sacc[nt][0]-mn0); s0+=sacc[nt][0];
            sacc[nt][1]=__expf(sacc[nt][1]-mn0); s0+=sacc[nt][1];
            sacc[nt][2]=__expf(sacc[nt][2]-mn1); s1+=sacc[nt][2];
            sacc[nt][3]=__expf(sacc[nt][3]-mn1); s1+=sacc[nt][3];
        }
        s0+=__shfl_xor_sync(0xffffffffu,s0,1); s0+=__shfl_xor_sync(0xffffffffu,s0,2);
        s1+=__shfl_xor_sync(0xffffffffu,s1,1); s1+=__shfl_xor_sync(0xffffffffu,s1,2);
        l0_=l0_*al0+s0; l1_=l1_*al1+s1;
        #pragma unroll
        for(int nt=0;nt<8;nt++){
            oacc[nt][0]*=al0; oacc[nt][1]*=al0;
            oacc[nt][2]*=al1; oacc[nt][3]*=al1;
        }
        uint32_t ph_[4][4];
        #pragma unroll
        for(int kt=0;kt<4;kt++){
            ph_[kt][0]=pack2(sacc[2*kt][0],  sacc[2*kt][1]);
            ph_[kt][1]=pack2(sacc[2*kt][2],  sacc[2*kt][3]);
            ph_[kt][2]=pack2(sacc[2*kt+1][0],sacc[2*kt+1][1]);
            ph_[kt][3]=pack2(sacc[2*kt+1][2],sacc[2*kt+1][3]);
        }
        #pragma unroll
        for(int kt=0;kt<4;kt++){
            #pragma unroll
            for(int dg=0;dg<4;dg++){
                int row=kt*16+((lane>>3)&1)*8+(lane&7);
                int ch_=dg*2+(lane>>4);
                uint32_t ad=stv+8192+row*128+((ch_^(row&7))*16);
                uint32_t vh_[4];
                LDSM4T(vh_[0],vh_[1],vh_[2],vh_[3],ad);
                #pragma unroll
                for(int p=0;p<2;p++)
                    MMA(oacc[dg*2+p],ph_[kt],vh_[p*2],vh_[p*2+1]);
            }
        }
        __syncthreads();
        if(t<6) loadkv(t&1,(t+2)*64);
    }
    float inv0=__fdividef(1.0f,l0_), inv1=__fdividef(1.0f,l1_);
    #pragma unroll
    for(int nt=0;nt<8;nt++){
        int dh=nt*8+j2;
        *(uint32_t*)&Ch[((size_t)(b*Ss+qi0))*Dd+h*DH+dh]=pack2(oacc[nt][0]*inv0,oacc[nt][1]*inv0);
        *(uint32_t*)&Ch[((size_t)(b*Ss+qi1))*Dd+h*DH+dh]=pack2(oacc[nt][2]*inv1,oacc[nt][3]*inv1);
    }
}

// ================= LayerNorm: fp32 out + fp16 hi out ============================
__global__ void ln_k(const float* __restrict__ in,const float* __restrict__ g,
                     const float* __restrict__ bt,float* __restrict__ out,
                     hf* __restrict__ oh){
    const size_t row=blockIdx.x;
    const int tid=threadIdx.x, lane=tid&31, wid=tid>>5;
    __shared__ float red[4];
    float4 v=*(const float4*)&in[row*Dd+tid*4];
    float s=v.x+v.y+v.z+v.w;
    #pragma unroll
    for(int o=16;o;o>>=1)s+=__shfl_xor_sync(0xffffffffu,s,o);
    if(lane==0)red[wid]=s;
    __syncthreads();
    float mu=(red[0]+red[1]+red[2]+red[3])*(1.0f/512.0f);
    __syncthreads();
    float dx=v.x-mu,dy=v.y-mu,dz=v.z-mu,dw=v.w-mu;
    float s2=dx*dx+dy*dy+dz*dz+dw*dw;
    #pragma unroll
    for(int o=16;o;o>>=1)s2+=__shfl_xor_sync(0xffffffffu,s2,o);
    if(lane==0)red[wid]=s2;
    __syncthreads();
    float var=(red[0]+red[1]+red[2]+red[3])*(1.0f/512.0f);
    float inv=rsqrtf(var+1e-12f);
    float4 gv=*(const float4*)&g[tid*4];
    float4 bv=*(const float4*)&bt[tid*4];
    float4 o;
    o.x=dx*inv*gv.x+bv.x; o.y=dy*inv*gv.y+bv.y;
    o.z=dz*inv*gv.z+bv.z; o.w=dw*inv*gv.w+bv.w;
    *(float4*)&out[row*Dd+tid*4]=o;
    ((uint32_t*)(oh+row*Dd+tid*4))[0]=pack2(o.x,o.y);
    ((uint32_t*)(oh+row*Dd+tid*4))[1]=pack2(o.z,o.w);
}

__global__ void split_k(const float* __restrict__ s,hf* __restrict__ hi,int n4){
    int i=blockIdx.x*256+threadIdx.x;
    if(i>=n4)return;
    float4 v=((const float4*)s)[i];
    ((uint32_t*)hi)[i*2+0]=pack2(v.x,v.y);
    ((uint32_t*)hi)[i*2+1]=pack2(v.z,v.w);
}

__global__ void wprep_k(const float* __restrict__ Wq,const float* __restrict__ Wk,
                        const float* __restrict__ Wv,const float* __restrict__ Wo,
                        const float* __restrict__ Wi,const float* __restrict__ Wf,
                        hf* __restrict__ wh){
    __shared__ float t[32][33];
    int tile=blockIdx.x;
    int l=tile/3072, r=tile%3072;
    const float* src; size_t off; int K,N;
    if(r<1024){
        int m=r>>8; r&=255;
        src=(m==0?Wq:m==1?Wk:m==2?Wv:Wo)+(size_t)l*Dd*Dd;
        off=(size_t)m*Dd*Dd; K=Dd; N=Dd;
    }else if(r<2048){
        r-=1024; src=Wi+(size_t)l*Dd*Ff; off=4*Dd*Dd; K=Dd; N=Ff;
    }else{
        r-=2048; src=Wf+(size_t)l*Ff*Dd; off=4*Dd*Dd+(size_t)Dd*Ff; K=Ff; N=Dd;
    }
    hf* dh=wh+(size_t)l*LWc+off;
    int ntk=K>>5;
    int n0=(r/ntk)*32, k0=(r%ntk)*32;
    int x=threadIdx.x, y0=threadIdx.y;
    for(int j=y0;j<32;j+=8) t[j][x]=src[(size_t)(k0+j)*N+n0+x];
    __syncthreads();
    for(int j=y0;j<32;j+=8)
        dh[(size_t)(n0+j)*K+k0+x]=__float2half_rn(t[x][j]);
}

__global__ void catb_k(const float* bq,const float* bk,const float* bv,float* o){
    int i=blockIdx.x*256+threadIdx.x;
    if(i>=Ll*3*Dd)return;
    int l=i/(3*Dd), r=i%(3*Dd);
    o[i]= r<Dd ? bq[l*Dd+r] : (r<2*Dd ? bk[l*Dd+r-Dd] : bv[l*Dd+r-2*Dd]);
}

extern "C" void kernel_launch(void* const* d_in, const int* in_sizes, int n_in,
                              void* d_out, int out_size){
    const float* hidden=(const float*)d_in[0];
    const float* pbias=(const float*)d_in[1];
    const long long* ts=(const long long*)d_in[2];
    const float* Wq=(const float*)d_in[3];  const float* bq=(const float*)d_in[4];
    const float* Wk=(const float*)d_in[5];  const float* bk=(const float*)d_in[6];
    const float* Wv=(const float*)d_in[7];  const float* bv=(const float*)d_in[8];
    const float* Wo=(const float*)d_in[9];  const float* bo=(const float*)d_in[10];
    const float* l1g=(const float*)d_in[11];const float* l1b=(const float*)d_in[12];
    const float* Wi=(const float*)d_in[13]; const float* bi=(const float*)d_in[14];
    const float* Wf=(const float*)d_in[15]; const float* bfp=(const float*)d_in[16];
    const float* l2g=(const float*)d_in[17];const float* l2b=(const float*)d_in[18];

    float *px,*pattn,*ptmp,*pcatb;
    cudaGetSymbolAddress((void**)&px,g_x);     cudaGetSymbolAddress((void**)&pattn,g_attn);
    cudaGetSymbolAddress((void**)&ptmp,g_tmp); cudaGetSymbolAddress((void**)&pcatb,g_catb);
    hf *xh,*qkh,*qkl,*ch,*ah,*fh,*wh;
    cudaGetSymbolAddress((void**)&xh,g_xh);
    cudaGetSymbolAddress((void**)&qkh,g_qkvh);cudaGetSymbolAddress((void**)&qkl,g_qkvl);
    cudaGetSymbolAddress((void**)&ch,g_ch);
    cudaGetSymbolAddress((void**)&ah,g_ah);
    cudaGetSymbolAddress((void**)&fh,g_fh);
    cudaGetSymbolAddress((void**)&wh,g_wh);

    cudaFuncSetAttribute(gemm_mma<0,false,1,512>, cudaFuncAttributeMaxDynamicSharedMemorySize,GSMEM);
    cudaFuncSetAttribute(gemm_mma<0,true,0,512>,  cudaFuncAttributeMaxDynamicSharedMemorySize,GSMEM);
    cudaFuncSetAttribute(gemm_mma<1,false,2,512>, cudaFuncAttributeMaxDynamicSharedMemorySize,GSMEM);
    cudaFuncSetAttribute(gemm_mma<0,true,0,2048>, cudaFuncAttributeMaxDynamicSharedMemorySize,GSMEM);
    cudaFuncSetAttribute(flash_k,cudaFuncAttributeMaxDynamicSharedMemorySize,FLSM);

    wprep_k<<<Ll*3072,dim3(32,8)>>>(Wq,Wk,Wv,Wo,Wi,Wf,wh);
    catb_k<<<(Ll*3*Dd+255)/256,256>>>(bq,bk,bv,pcatb);
    const int nD4=Mrows*Dd/4;
    split_k<<<(nD4+255)/256,256>>>(hidden,xh,nD4);

    const dim3 gDD(Dd/128,Mrows/128), gQKV(3*Dd/128,Mrows/128), gDF(Ff/128,Mrows/128);
    const float* X=hidden;
    for(int l=0;l<Ll;l++){
        hf* bh_=wh+(size_t)l*LWc;
        hf* wih=bh_+4*Dd*Dd;
        hf* wfh=wih+(size_t)Dd*Ff;

        gemm_mma<0,false,1,512><<<gQKV,256,GSMEM>>>(xh,bh_,pcatb+l*3*Dd,nullptr,nullptr,qkh,qkl,3*Dd);
        flash_k<<<dim3(4,Bb*Hh),256,FLSM>>>(qkh,qkl,pbias,ts,ch);

        gemm_mma<0,true,0,512><<<gDD,256,GSMEM>>>(ch,bh_+3*Dd*Dd,bo+l*Dd,X,ptmp,nullptr,nullptr,Dd);
        ln_k<<<Mrows,128>>>(ptmp,l1g+l*Dd,l1b+l*Dd,pattn,ah);

        gemm_mma<1,false,2,512><<<gDF,256,GSMEM>>>(ah,wih,bi+l*Ff,nullptr,nullptr,fh,nullptr,Ff);
        gemm_mma<0,true,0,2048><<<gDD,256,GSMEM>>>(fh,wfh,bfp+l*Dd,pattn,ptmp,nullptr,nullptr,Dd);
        ln_k<<<Mrows,128>>>(ptmp,l2g+l*Dd,l2b+l*Dd,px,xh);
        X=px;
    }
    cudaMemcpyAsync(d_out,px,(size_t)Mrows*Dd*sizeof(float),cudaMemcpyDeviceToDevice,0);
}

// round 13
// speedup vs baseline: 5.9299x; 1.0181x over previous
#include <cuda_runtime.h>
#include <cuda_fp16.h>
#include <math.h>
#include <stdint.h>

#define Bb 32
#define Ss 512
#define Dd 512
#define Hh 8
#define Ff 2048
#define Ll 4
#define DH 64
#define Mrows (Bb*Ss)
#define LWc ((size_t)(4*Dd*Dd+2*Dd*Ff))

typedef __half hf;

__device__ float g_x[Mrows*Dd];
__device__ float g_attn[Mrows*Dd];
__device__ float g_tmp[Mrows*Dd];
__device__ hf g_xh[Mrows*Dd];
__device__ hf g_qkvh[(size_t)Mrows*3*Dd];
__device__ hf g_ch[Mrows*Dd];
__device__ hf g_ah[Mrows*Dd];
__device__ hf g_fh[(size_t)Mrows*Ff];
__device__ hf g_wh[Ll*LWc];
__device__ float g_catb[Ll*3*Dd];

__device__ __forceinline__ float gelu_e(float x){return 0.5f*x*(1.0f+erff(x*0.70710678118654752f));}
__device__ __forceinline__ void cp16(uint32_t d,const void* s){
    asm volatile("cp.async.cg.shared.global [%0], [%1], 16;"::"r"(d),"l"(s));
}
#define CPC() asm volatile("cp.async.commit_group;":::"memory")
#define LDSM4(r0,r1,r2,r3,a) asm volatile("ldmatrix.sync.aligned.m8n8.x4.shared.b16 {%0,%1,%2,%3},[%4];":"=r"(r0),"=r"(r1),"=r"(r2),"=r"(r3):"r"(a))
#define LDSM4T(r0,r1,r2,r3,a) asm volatile("ldmatrix.sync.aligned.m8n8.x4.trans.shared.b16 {%0,%1,%2,%3},[%4];":"=r"(r0),"=r"(r1),"=r"(r2),"=r"(r3):"r"(a))
#define MMA(d,a,b0,b1) asm volatile( \
    "mma.sync.aligned.m16n8k16.row.col.f32.f16.f16.f32 {%0,%1,%2,%3},{%4,%5,%6,%7},{%8,%9},{%0,%1,%2,%3};" \
    :"+f"((d)[0]),"+f"((d)[1]),"+f"((d)[2]),"+f"((d)[3]) \
    :"r"((a)[0]),"r"((a)[1]),"r"((a)[2]),"r"((a)[3]),"r"(b0),"r"(b1))

__device__ __forceinline__ uint32_t pack2(float a,float b){
    __half2 H=__halves2half2(__float2half_rn(a),__float2half_rn(b));
    return *(uint32_t*)&H;
}

// ============== GEMM: pure fp16, BK=64, 3-stage =================================
#define STB2 32768
#define GSMEM (3*STB2)
__device__ __forceinline__ void load_stage(uint32_t st,int tid,
    const hf* Ah,const hf* Bh,int m0,int n0,int k0,int K){
    #pragma unroll
    for(int i=0;i<8;i++){
        int id=i*256+tid;
        int reg=id>>10, rid=id&1023, row=rid>>3, c=rid&7;
        const hf* src=reg? Bh+(size_t)(n0+row)*K+k0+c*8 : Ah+(size_t)(m0+row)*K+k0+c*8;
        cp16(st+reg*16384+row*128+((c^(row&7))*16),src);
    }
    CPC();
}

// OUT: 0=fp32, 2=fp16 hi
template<int ACT, bool RES, int OUT, int KT>
__global__ void __launch_bounds__(256,2)
gemm_mma(const hf* __restrict__ Ah,const hf* __restrict__ Bh,
         const float* __restrict__ bias,const float* __restrict__ res,
         float* __restrict__ C,hf* __restrict__ Ch,
         int N){
    extern __shared__ char sm[];
    uint32_t sb=(uint32_t)__cvta_generic_to_shared(sm);
    const int tid=threadIdx.x, wid=tid>>5, lane=tid&31;
    const int n0=blockIdx.x*128, m0=blockIdx.y*128;
    const int wm=(wid>>2)*64, wn=(wid&3)*32;
    constexpr int chunks=KT>>6;
    float acc[4][4][4];
    #pragma unroll
    for(int i=0;i<4;i++)
        #pragma unroll
        for(int j=0;j<4;j++){acc[i][j][0]=0;acc[i][j][1]=0;acc[i][j][2]=0;acc[i][j][3]=0;}
    load_stage(sb,tid,Ah,Bh,m0,n0,0,KT);
    load_stage(sb+STB2,tid,Ah,Bh,m0,n0,64,KT);
    const int arow=lane&15, ah8=lane>>4;
    int s2=2;
    for(int c=0;c<chunks;c++){
        uint32_t st=sb+(c%3)*STB2;
        if(c<chunks-1) asm volatile("cp.async.wait_group 1;":::"memory");
        else           asm volatile("cp.async.wait_group 0;":::"memory");
        __syncthreads();
        if(c+2<chunks){
            load_stage(sb+s2*STB2,tid,Ah,Bh,m0,n0,(c+2)*64,KT);
            s2++; if(s2==3)s2=0;
        }
        #pragma unroll
        for(int s=0;s<4;s++){
            uint32_t bhf[2][4];
            #pragma unroll
            for(int nq=0;nq<2;nq++){
                int row=wn+nq*16+arow;
                uint32_t ad=st+16384+row*128+(((s*2+ah8)^(row&7))*16);
                LDSM4(bhf[nq][0],bhf[nq][1],bhf[nq][2],bhf[nq][3],ad);
            }
            #pragma unroll
            for(int mi=0;mi<4;mi++){
                uint32_t ahf[4];
                int row=wm+mi*16+arow;
                uint32_t ad=st+row*128+(((s*2+ah8)^(row&7))*16);
                LDSM4(ahf[0],ahf[1],ahf[2],ahf[3],ad);
                #pragma unroll
                for(int nq=0;nq<2;nq++)
                    #pragma unroll
                    for(int p=0;p<2;p++)
                        MMA(acc[mi][nq*2+p],ahf,bhf[nq][p],bhf[nq][p+2]);
            }
        }
    }
    const int r4=lane>>2, c2=(lane&3)*2;
    #pragma unroll
    for(int mi=0;mi<4;mi++)
        #pragma unroll
        for(int nt=0;nt<4;nt++){
            int col=n0+wn+nt*8+c2;
            float2 bv=*(const float2*)&bias[col];
            #pragma unroll
            for(int hr=0;hr<2;hr++){
                int row=m0+wm+mi*16+r4+hr*8;
                float2 o;
                o.x=acc[mi][nt][hr*2+0]+bv.x;
                o.y=acc[mi][nt][hr*2+1]+bv.y;
                if(RES){float2 rv=*(const float2*)&res[(size_t)row*N+col]; o.x+=rv.x;o.y+=rv.y;}
                if(ACT==1){o.x=gelu_e(o.x);o.y=gelu_e(o.y);}
                if(OUT==0) *(float2*)&C[(size_t)row*N+col]=o;
                else       *(uint32_t*)&Ch[(size_t)row*N+col]=pack2(o.x,o.y);
            }
        }
}

// ===== flash attention: all fp16 operands, fp32 accum ===========================
#define FLSM (16384 + 2*16384)
__global__ void __launch_bounds__(256,2)
flash_k(const hf* __restrict__ qkvh,
        const float* __restrict__ pbias,const long long* __restrict__ ts,
        hf* __restrict__ Ch){
    extern __shared__ char sm[];
    uint32_t sb=(uint32_t)__cvta_generic_to_shared(sm);
    const int tid=threadIdx.x, wid=tid>>5, lane=tid&31;
    const int bh=blockIdx.y, b=bh>>3, h=bh&7;
    const int q0=blockIdx.x*128;
    const int wm=wid*16;
    const int arow=lane&15, ah8=lane>>4, r4=lane>>2, j2=(lane&3)*2;

    // Q hi (16KB)
    #pragma unroll
    for(int i=0;i<4;i++){
        int id=i*256+tid;
        int row=id>>3, c=id&7;
        const hf* src=qkvh+(size_t)(b*Ss+q0+row)*1536+h*DH+c*8;
        cp16(sb+row*128+((c^(row&7))*16),src);
    }
    CPC();

    auto loadkv=[&](int st,int k0){
        #pragma unroll
        for(int i=0;i<4;i++){
            int id=i*256+tid;
            int part=id>>9, rid=id&511, row=rid>>3, c=rid&7;
            int colb=part? (2*Dd+h*DH) : (Dd+h*DH);
            const hf* src=qkvh+(size_t)(b*Ss+k0+row)*1536+colb+c*8;
            cp16(sb+16384+st*16384+part*8192+row*128+((c^(row&7))*16),src);
        }
        CPC();
    };
    loadkv(0,0); loadkv(1,64);

    float m0_=-1e30f, m1_=-1e30f, l0_=0.0f, l1_=0.0f;
    float oacc[8][4];
    #pragma unroll
    for(int i=0;i<8;i++){oacc[i][0]=0;oacc[i][1]=0;oacc[i][2]=0;oacc[i][3]=0;}
    const long long tq0=ts[b*Ss+q0+wm+r4], tq1=ts[b*Ss+q0+wm+r4+8];
    const int qi0=q0+wm+r4, qi1=qi0+8;

    for(int t=0;t<8;t++){
        uint32_t stv=sb+16384+(t&1)*16384;
        if(t<6) asm volatile("cp.async.wait_group 1;":::"memory");
        else    asm volatile("cp.async.wait_group 0;":::"memory");
        __syncthreads();

        float sacc[8][4];
        #pragma unroll
        for(int i=0;i<8;i++){sacc[i][0]=0;sacc[i][1]=0;sacc[i][2]=0;sacc[i][3]=0;}
        #pragma unroll
        for(int kt=0;kt<4;kt++){
            uint32_t qh_[4];
            {
                int row=wm+arow;
                uint32_t ad=sb+row*128+(((kt*2+ah8)^(row&7))*16);
                LDSM4(qh_[0],qh_[1],qh_[2],qh_[3],ad);
            }
            #pragma unroll
            for(int nq=0;nq<4;nq++){
                int row=nq*16+arow;
                uint32_t ad=stv+row*128+(((kt*2+ah8)^(row&7))*16);
                uint32_t kh_[4];
                LDSM4(kh_[0],kh_[1],kh_[2],kh_[3],ad);
                #pragma unroll
                for(int p=0;p<2;p++)
                    MMA(sacc[nq*2+p],qh_,kh_[p],kh_[p+2]);
            }
        }
        int k0=t*64;
        #pragma unroll
        for(int nt=0;nt<8;nt++){
            int kc=k0+nt*8+j2;
            long long tk0=ts[b*Ss+kc], tk1=ts[b*Ss+kc+1];
            float la0=(float)(tq0-tk0)*(1.0f/60000.0f);
            float lb0=(float)(tq0-tk1)*(1.0f/60000.0f);
            float la1=(float)(tq1-tk0)*(1.0f/60000.0f);
            float lb1=(float)(tq1-tk1)*(1.0f/60000.0f);
            float2 pb0=*(const float2*)&pbias[((size_t)(h*Ss+qi0))*Ss+kc];
            float2 pb1=*(const float2*)&pbias[((size_t)(h*Ss+qi1))*Ss+kc];
            sacc[nt][0]=__fdividef(sacc[nt][0],9.0f-__fdividef(1.0f,fmaxf(la0,0.0f)+1.0f))+pb0.x;
            sacc[nt][1]=__fdividef(sacc[nt][1],9.0f-__fdividef(1.0f,fmaxf(lb0,0.0f)+1.0f))+pb0.y;
            sacc[nt][2]=__fdividef(sacc[nt][2],9.0f-__fdividef(1.0f,fmaxf(la1,0.0f)+1.0f))+pb1.x;
            sacc[nt][3]=__fdividef(sacc[nt][3],9.0f-__fdividef(1.0f,fmaxf(lb1,0.0f)+1.0f))+pb1.y;
        }
        float tm0=-1e30f, tm1=-1e30f;
        #pragma unroll
        for(int nt=0;nt<8;nt++){
            tm0=fmaxf(tm0,fmaxf(sacc[nt][0],sacc[nt][1]));
            tm1=fmaxf(tm1,fmaxf(sacc[nt][2],sacc[nt][3]));
        }
        tm0=fmaxf(tm0,__shfl_xor_sync(0xffffffffu,tm0,1));
        tm0=fmaxf(tm0,__shfl_xor_sync(0xffffffffu,tm0,2));
        tm1=fmaxf(tm1,__shfl_xor_sync(0xffffffffu,tm1,1));
        tm1=fmaxf(tm1,__shfl_xor_sync(0xffffffffu,tm1,2));
        float mn0=fmaxf(m0_,tm0), mn1=fmaxf(m1_,tm1);
        float al0=__expf(m0_-mn0), al1=__expf(m1_-mn1);
        m0_=mn0; m1_=mn1;
        float s0=0.0f, s1=0.0f;
        #pragma unroll
        for(int nt=0;nt<8;nt++){
            sacc[nt][0]=__expf(sacc[nt][0]-mn0); s0+=sacc[nt][0];
            sacc[nt][1]=__expf(sacc[nt][1]-mn0); s0+=sacc[nt][1];
            sacc[nt][2]=__expf(sacc[nt][2]-mn1); s1+=sacc[nt][2];
            sacc[nt][3]=__expf(sacc[nt][3]-mn1); s1+=sacc[nt][3];
        }
        s0+=__shfl_xor_sync(0xffffffffu,s0,1); s0+=__shfl_xor_sync(0xffffffffu,s0,2);
        s1+=__shfl_xor_sync(0xffffffffu,s1,1); s1+=__shfl_xor_sync(0xffffffffu,s1,2);
        l0_=l0_*al0+s0; l1_=l1_*al1+s1;
        #pragma unroll
        for(int nt=0;nt<8;nt++){
            oacc[nt][0]*=al0; oacc[nt][1]*=al0;
            oacc[nt][2]*=al1; oacc[nt][3]*=al1;
        }
        uint32_t ph_[4][4];
        #pragma unroll
        for(int kt=0;kt<4;kt++){
            ph_[kt][0]=pack2(sacc[2*kt][0],  sacc[2*kt][1]);
            ph_[kt][1]=pack2(sacc[2*kt][2],  sacc[2*kt][3]);
            ph_[kt][2]=pack2(sacc[2*kt+1][0],sacc[2*kt+1][1]);
            ph_[kt][3]=pack2(sacc[2*kt+1][2],sacc[2*kt+1][3]);
        }
        #pragma unroll
        for(int kt=0;kt<4;kt++){
            #pragma unroll
            for(int dg=0;dg<4;dg++){
                int row=kt*16+((lane>>3)&1)*8+(lane&7);
                int ch_=dg*2+(lane>>4);
                uint32_t ad=stv+8192+row*128+((ch_^(row&7))*16);
                uint32_t vh_[4];
                LDSM4T(vh_[0],vh_[1],vh_[2],vh_[3],ad);
                #pragma unroll
                for(int p=0;p<2;p++)
                    MMA(oacc[dg*2+p],ph_[kt],vh_[p*2],vh_[p*2+1]);
            }
        }
        __syncthreads();
        if(t<6) loadkv(t&1,(t+2)*64);
    }
    float inv0=__fdividef(1.0f,l0_), inv1=__fdividef(1.0f,l1_);
    #pragma unroll
    for(int nt=0;nt<8;nt++){
        int dh=nt*8+j2;
        *(uint32_t*)&Ch[((size_t)(b*Ss+qi0))*Dd+h*DH+dh]=pack2(oacc[nt][0]*inv0,oacc[nt][1]*inv0);
        *(uint32_t*)&Ch[((size_t)(b*Ss+qi1))*Dd+h*DH+dh]=pack2(oacc[nt][2]*inv1,oacc[nt][3]*inv1);
    }
}

// ================= LayerNorm: fp32 out + fp16 hi out ============================
__global__ void ln_k(const float* __restrict__ in,const float* __restrict__ g,
                     const float* __restrict__ bt,float* __restrict__ out,
                     hf* __restrict__ oh){
    const size_t row=blockIdx.x;
    const int tid=threadIdx.x, lane=tid&31, wid=tid>>5;
    __shared__ float red[4];
    float4 v=*(const float4*)&in[row*Dd+tid*4];
    float s=v.x+v.y+v.z+v.w;
    #pragma unroll
    for(int o=16;o;o>>=1)s+=__shfl_xor_sync(0xffffffffu,s,o);
    if(lane==0)red[wid]=s;
    __syncthreads();
    float mu=(red[0]+red[1]+red[2]+red[3])*(1.0f/512.0f);
    __syncthreads();
    float dx=v.x-mu,dy=v.y-mu,dz=v.z-mu,dw=v.w-mu;
    float s2=dx*dx+dy*dy+dz*dz+dw*dw;
    #pragma unroll
    for(int o=16;o;o>>=1)s2+=__shfl_xor_sync(0xffffffffu,s2,o);
    if(lane==0)red[wid]=s2;
    __syncthreads();
    float var=(red[0]+red[1]+red[2]+red[3])*(1.0f/512.0f);
    float inv=rsqrtf(var+1e-12f);
    float4 gv=*(const float4*)&g[tid*4];
    float4 bv=*(const float4*)&bt[tid*4];
    float4 o;
    o.x=dx*inv*gv.x+bv.x; o.y=dy*inv*gv.y+bv.y;
    o.z=dz*inv*gv.z+bv.z; o.w=dw*inv*gv.w+bv.w;
    *(float4*)&out[row*Dd+tid*4]=o;
    ((uint32_t*)(oh+row*Dd+tid*4))[0]=pack2(o.x,o.y);
    ((uint32_t*)(oh+row*Dd+tid*4))[1]=pack2(o.z,o.w);
}

__global__ void split_k(const float* __restrict__ s,hf* __restrict__ hi,int n4){
    int i=blockIdx.x*256+threadIdx.x;
    if(i>=n4)return;
    float4 v=((const float4*)s)[i];
    ((uint32_t*)hi)[i*2+0]=pack2(v.x,v.y);
    ((uint32_t*)hi)[i*2+1]=pack2(v.z,v.w);
}

__global__ void wprep_k(const float* __restrict__ Wq,const float* __restrict__ Wk,
                        const float* __restrict__ Wv,const float* __restrict__ Wo,
                        const float* __restrict__ Wi,const float* __restrict__ Wf,
                        hf* __restrict__ wh){
    __shared__ float t[32][33];
    int tile=blockIdx.x;
    int l=tile/3072, r=tile%3072;
    const float* src; size_t off; int K,N;
    if(r<1024){
        int m=r>>8; r&=255;
        src=(m==0?Wq:m==1?Wk:m==2?Wv:Wo)+(size_t)l*Dd*Dd;
        off=(size_t)m*Dd*Dd; K=Dd; N=Dd;
    }else if(r<2048){
        r-=1024; src=Wi+(size_t)l*Dd*Ff; off=4*Dd*Dd; K=Dd; N=Ff;
    }else{
        r-=2048; src=Wf+(size_t)l*Ff*Dd; off=4*Dd*Dd+(size_t)Dd*Ff; K=Ff; N=Dd;
    }
    hf* dh=wh+(size_t)l*LWc+off;
    int ntk=K>>5;
    int n0=(r/ntk)*32, k0=(r%ntk)*32;
    int x=threadIdx.x, y0=threadIdx.y;
    for(int j=y0;j<32;j+=8) t[j][x]=src[(size_t)(k0+j)*N+n0+x];
    __syncthreads();
    for(int j=y0;j<32;j+=8)
        dh[(size_t)(n0+j)*K+k0+x]=__float2half_rn(t[x][j]);
}

__global__ void catb_k(const float* bq,const float* bk,const float* bv,float* o){
    int i=blockIdx.x*256+threadIdx.x;
    if(i>=Ll*3*Dd)return;
    int l=i/(3*Dd), r=i%(3*Dd);
    o[i]= r<Dd ? bq[l*Dd+r] : (r<2*Dd ? bk[l*Dd+r-Dd] : bv[l*Dd+r-2*Dd]);
}

extern "C" void kernel_launch(void* const* d_in, const int* in_sizes, int n_in,
                              void* d_out, int out_size){
    const float* hidden=(const float*)d_in[0];
    const float* pbias=(const float*)d_in[1];
    const long long* ts=(const long long*)d_in[2];
    const float* Wq=(const float*)d_in[3];  const float* bq=(const float*)d_in[4];
    const float* Wk=(const float*)d_in[5];  const float* bk=(const float*)d_in[6];
    const float* Wv=(const float*)d_in[7];  const float* bv=(const float*)d_in[8];
    const float* Wo=(const float*)d_in[9];  const float* bo=(const float*)d_in[10];
    const float* l1g=(const float*)d_in[11];const float* l1b=(const float*)d_in[12];
    const float* Wi=(const float*)d_in[13]; const float* bi=(const float*)d_in[14];
    const float* Wf=(const float*)d_in[15]; const float* bfp=(const float*)d_in[16];
    const float* l2g=(const float*)d_in[17];const float* l2b=(const float*)d_in[18];

    float *px,*pattn,*ptmp,*pcatb;
    cudaGetSymbolAddress((void**)&px,g_x);     cudaGetSymbolAddress((void**)&pattn,g_attn);
    cudaGetSymbolAddress((void**)&ptmp,g_tmp); cudaGetSymbolAddress((void**)&pcatb,g_catb);
    hf *xh,*qkh,*ch,*ah,*fh,*wh;
    cudaGetSymbolAddress((void**)&xh,g_xh);
    cudaGetSymbolAddress((void**)&qkh,g_qkvh);
    cudaGetSymbolAddress((void**)&ch,g_ch);
    cudaGetSymbolAddress((void**)&ah,g_ah);
    cudaGetSymbolAddress((void**)&fh,g_fh);
    cudaGetSymbolAddress((void**)&wh,g_wh);

    cudaFuncSetAttribute(gemm_mma<0,false,2,512>, cudaFuncAttributeMaxDynamicSharedMemorySize,GSMEM);
    cudaFuncSetAttribute(gemm_mma<0,true,0,512>,  cudaFuncAttributeMaxDynamicSharedMemorySize,GSMEM);
    cudaFuncSetAttribute(gemm_mma<1,false,2,512>, cudaFuncAttributeMaxDynamicSharedMemorySize,GSMEM);
    cudaFuncSetAttribute(gemm_mma<0,true,0,2048>, cudaFuncAttributeMaxDynamicSharedMemorySize,GSMEM);
    cudaFuncSetAttribute(flash_k,cudaFuncAttributeMaxDynamicSharedMemorySize,FLSM);

    wprep_k<<<Ll*3072,dim3(32,8)>>>(Wq,Wk,Wv,Wo,Wi,Wf,wh);
    catb_k<<<(Ll*3*Dd+255)/256,256>>>(bq,bk,bv,pcatb);
    const int nD4=Mrows*Dd/4;
    split_k<<<(nD4+255)/256,256>>>(hidden,xh,nD4);

    const dim3 gDD(Dd/128,Mrows/128), gQKV(3*Dd/128,Mrows/128), gDF(Ff/128,Mrows/128);
    const float* X=hidden;
    for(int l=0;l<Ll;l++){
        hf* bh_=wh+(size_t)l*LWc;
        hf* wih=bh_+4*Dd*Dd;
        hf* wfh=wih+(size_t)Dd*Ff;

        gemm_mma<0,false,2,512><<<gQKV,256,GSMEM>>>(xh,bh_,pcatb+l*3*Dd,nullptr,nullptr,qkh,3*Dd);
        flash_k<<<dim3(4,Bb*Hh),256,FLSM>>>(qkh,pbias,ts,ch);

        gemm_mma<0,true,0,512><<<gDD,256,GSMEM>>>(ch,bh_+3*Dd*Dd,bo+l*Dd,X,ptmp,nullptr,Dd);
        ln_k<<<Mrows,128>>>(ptmp,l1g+l*Dd,l1b+l*Dd,pattn,ah);

        gemm_mma<1,false,2,512><<<gDF,256,GSMEM>>>(ah,wih,bi+l*Ff,nullptr,nullptr,fh,Ff);
        gemm_mma<0,true,0,2048><<<gDD,256,GSMEM>>>(fh,wfh,bfp+l*Dd,pattn,ptmp,nullptr,Dd);
        ln_k<<<Mrows,128>>>(ptmp,l2g+l*Dd,l2b+l*Dd,px,xh);
        X=px;
    }
    cudaMemcpyAsync(d_out,px,(size_t)Mrows*Dd*sizeof(float),cudaMemcpyDeviceToDevice,0);
}

// round 14
// speedup vs baseline: 6.0325x; 1.0173x over previous
#include <cuda_runtime.h>
#include <cuda_fp16.h>
#include <math.h>
#include <stdint.h>

#define Bb 32
#define Ss 512
#define Dd 512
#define Hh 8
#define Ff 2048
#define Ll 4
#define DH 64
#define Mrows (Bb*Ss)
#define LWc ((size_t)(4*Dd*Dd+2*Dd*Ff))

typedef __half hf;

__device__ float g_x[Mrows*Dd];
__device__ float g_attn[Mrows*Dd];
__device__ float g_tmp[Mrows*Dd];
__device__ hf g_xh[Mrows*Dd];
__device__ hf g_qkvh[(size_t)Mrows*3*Dd];
__device__ hf g_ch[Mrows*Dd];
__device__ hf g_ah[Mrows*Dd];
__device__ hf g_fh[(size_t)Mrows*Ff];
__device__ hf g_wh[Ll*LWc];
__device__ hf g_pbh[(size_t)Hh*Ss*Ss];
__device__ float g_catb[Ll*3*Dd];

__device__ __forceinline__ float gelu_e(float x){return 0.5f*x*(1.0f+erff(x*0.70710678118654752f));}
__device__ __forceinline__ void cp16(uint32_t d,const void* s){
    asm volatile("cp.async.cg.shared.global [%0], [%1], 16;"::"r"(d),"l"(s));
}
#define CPC() asm volatile("cp.async.commit_group;":::"memory")
#define LDSM4(r0,r1,r2,r3,a) asm volatile("ldmatrix.sync.aligned.m8n8.x4.shared.b16 {%0,%1,%2,%3},[%4];":"=r"(r0),"=r"(r1),"=r"(r2),"=r"(r3):"r"(a))
#define LDSM4T(r0,r1,r2,r3,a) asm volatile("ldmatrix.sync.aligned.m8n8.x4.trans.shared.b16 {%0,%1,%2,%3},[%4];":"=r"(r0),"=r"(r1),"=r"(r2),"=r"(r3):"r"(a))
#define MMA(d,a,b0,b1) asm volatile( \
    "mma.sync.aligned.m16n8k16.row.col.f32.f16.f16.f32 {%0,%1,%2,%3},{%4,%5,%6,%7},{%8,%9},{%0,%1,%2,%3};" \
    :"+f"((d)[0]),"+f"((d)[1]),"+f"((d)[2]),"+f"((d)[3]) \
    :"r"((a)[0]),"r"((a)[1]),"r"((a)[2]),"r"((a)[3]),"r"(b0),"r"(b1))

__device__ __forceinline__ uint32_t pack2(float a,float b){
    __half2 H=__halves2half2(__float2half_rn(a),__float2half_rn(b));
    return *(uint32_t*)&H;
}

// ============== GEMM: pure fp16, BK=64, 3-stage =================================
#define STB2 32768
#define GSMEM (3*STB2)
__device__ __forceinline__ void load_stage(uint32_t st,int tid,
    const hf* Ah,const hf* Bh,int m0,int n0,int k0,int K){
    #pragma unroll
    for(int i=0;i<8;i++){
        int id=i*256+tid;
        int reg=id>>10, rid=id&1023, row=rid>>3, c=rid&7;
        const hf* src=reg? Bh+(size_t)(n0+row)*K+k0+c*8 : Ah+(size_t)(m0+row)*K+k0+c*8;
        cp16(st+reg*16384+row*128+((c^(row&7))*16),src);
    }
    CPC();
}

// OUT: 0=fp32, 2=fp16 hi
template<int ACT, bool RES, int OUT, int KT>
__global__ void __launch_bounds__(256,2)
gemm_mma(const hf* __restrict__ Ah,const hf* __restrict__ Bh,
         const float* __restrict__ bias,const float* __restrict__ res,
         float* __restrict__ C,hf* __restrict__ Ch,
         int N){
    extern __shared__ char sm[];
    uint32_t sb=(uint32_t)__cvta_generic_to_shared(sm);
    const int tid=threadIdx.x, wid=tid>>5, lane=tid&31;
    const int n0=blockIdx.x*128, m0=blockIdx.y*128;
    const int wm=(wid>>2)*64, wn=(wid&3)*32;
    constexpr int chunks=KT>>6;
    float acc[4][4][4];
    #pragma unroll
    for(int i=0;i<4;i++)
        #pragma unroll
        for(int j=0;j<4;j++){acc[i][j][0]=0;acc[i][j][1]=0;acc[i][j][2]=0;acc[i][j][3]=0;}
    load_stage(sb,tid,Ah,Bh,m0,n0,0,KT);
    load_stage(sb+STB2,tid,Ah,Bh,m0,n0,64,KT);
    const int arow=lane&15, ah8=lane>>4;
    int s2=2;
    for(int c=0;c<chunks;c++){
        uint32_t st=sb+(c%3)*STB2;
        if(c<chunks-1) asm volatile("cp.async.wait_group 1;":::"memory");
        else           asm volatile("cp.async.wait_group 0;":::"memory");
        __syncthreads();
        if(c+2<chunks){
            load_stage(sb+s2*STB2,tid,Ah,Bh,m0,n0,(c+2)*64,KT);
            s2++; if(s2==3)s2=0;
        }
        #pragma unroll
        for(int s=0;s<4;s++){
            uint32_t bhf[2][4];
            #pragma unroll
            for(int nq=0;nq<2;nq++){
                int row=wn+nq*16+arow;
                uint32_t ad=st+16384+row*128+(((s*2+ah8)^(row&7))*16);
                LDSM4(bhf[nq][0],bhf[nq][1],bhf[nq][2],bhf[nq][3],ad);
            }
            #pragma unroll
            for(int mi=0;mi<4;mi++){
                uint32_t ahf[4];
                int row=wm+mi*16+arow;
                uint32_t ad=st+row*128+(((s*2+ah8)^(row&7))*16);
                LDSM4(ahf[0],ahf[1],ahf[2],ahf[3],ad);
                #pragma unroll
                for(int nq=0;nq<2;nq++)
                    #pragma unroll
                    for(int p=0;p<2;p++)
                        MMA(acc[mi][nq*2+p],ahf,bhf[nq][p],bhf[nq][p+2]);
            }
        }
    }
    const int r4=lane>>2, c2=(lane&3)*2;
    #pragma unroll
    for(int mi=0;mi<4;mi++)
        #pragma unroll
        for(int nt=0;nt<4;nt++){
            int col=n0+wn+nt*8+c2;
            float2 bv=*(const float2*)&bias[col];
            #pragma unroll
            for(int hr=0;hr<2;hr++){
                int row=m0+wm+mi*16+r4+hr*8;
                float2 o;
                o.x=acc[mi][nt][hr*2+0]+bv.x;
                o.y=acc[mi][nt][hr*2+1]+bv.y;
                if(RES){float2 rv=*(const float2*)&res[(size_t)row*N+col]; o.x+=rv.x;o.y+=rv.y;}
                if(ACT==1){o.x=gelu_e(o.x);o.y=gelu_e(o.y);}
                if(OUT==0) *(float2*)&C[(size_t)row*N+col]=o;
                else       *(uint32_t*)&Ch[(size_t)row*N+col]=pack2(o.x,o.y);
            }
        }
}

// ===== flash attention: fp16 operands, 3-stage KV ring, rational scale ==========
#define FLSM (16384 + 3*16384)
__global__ void __launch_bounds__(256,2)
flash_k(const hf* __restrict__ qkvh,
        const hf* __restrict__ pbh,const long long* __restrict__ ts,
        hf* __restrict__ Ch){
    extern __shared__ char sm[];
    uint32_t sb=(uint32_t)__cvta_generic_to_shared(sm);
    const int tid=threadIdx.x, wid=tid>>5, lane=tid&31;
    const int bh=blockIdx.y, b=bh>>3, h=bh&7;
    const int q0=blockIdx.x*128;
    const int wm=wid*16;
    const int arow=lane&15, ah8=lane>>4, r4=lane>>2, j2=(lane&3)*2;

    // Q (16KB)
    #pragma unroll
    for(int i=0;i<4;i++){
        int id=i*256+tid;
        int row=id>>3, c=id&7;
        const hf* src=qkvh+(size_t)(b*Ss+q0+row)*1536+h*DH+c*8;
        cp16(sb+row*128+((c^(row&7))*16),src);
    }
    CPC();

    auto loadkv=[&](int st,int k0){
        #pragma unroll
        for(int i=0;i<4;i++){
            int id=i*256+tid;
            int part=id>>9, rid=id&511, row=rid>>3, c=rid&7;
            int colb=part? (2*Dd+h*DH) : (Dd+h*DH);
            const hf* src=qkvh+(size_t)(b*Ss+k0+row)*1536+colb+c*8;
            cp16(sb+16384+st*16384+part*8192+row*128+((c^(row&7))*16),src);
        }
        CPC();
    };
    loadkv(0,0); loadkv(1,64);

    float m0_=-1e30f, m1_=-1e30f, l0_=0.0f, l1_=0.0f;
    float oacc[8][4];
    #pragma unroll
    for(int i=0;i<8;i++){oacc[i][0]=0;oacc[i][1]=0;oacc[i][2]=0;oacc[i][3]=0;}
    const long long tq0=ts[b*Ss+q0+wm+r4], tq1=ts[b*Ss+q0+wm+r4+8];
    const int qi0=q0+wm+r4, qi1=qi0+8;
    const hf* pb0p=pbh+(size_t)(h*Ss+qi0)*Ss;
    const hf* pb1p=pbh+(size_t)(h*Ss+qi1)*Ss;
    int s2=2;

    for(int t=0;t<8;t++){
        uint32_t stv=sb+16384+(t%3)*16384;
        if(t<7) asm volatile("cp.async.wait_group 1;":::"memory");
        else    asm volatile("cp.async.wait_group 0;":::"memory");
        __syncthreads();
        if(t+2<8){
            loadkv(s2,(t+2)*64);
            s2++; if(s2==3)s2=0;
        }

        float sacc[8][4];
        #pragma unroll
        for(int i=0;i<8;i++){sacc[i][0]=0;sacc[i][1]=0;sacc[i][2]=0;sacc[i][3]=0;}
        #pragma unroll
        for(int kt=0;kt<4;kt++){
            uint32_t qh_[4];
            {
                int row=wm+arow;
                uint32_t ad=sb+row*128+(((kt*2+ah8)^(row&7))*16);
                LDSM4(qh_[0],qh_[1],qh_[2],qh_[3],ad);
            }
            #pragma unroll
            for(int nq=0;nq<4;nq++){
                int row=nq*16+arow;
                uint32_t ad=stv+row*128+(((kt*2+ah8)^(row&7))*16);
                uint32_t kh_[4];
                LDSM4(kh_[0],kh_[1],kh_[2],kh_[3],ad);
                #pragma unroll
                for(int p=0;p<2;p++)
                    MMA(sacc[nq*2+p],qh_,kh_[p],kh_[p+2]);
            }
        }
        int k0=t*64;
        #pragma unroll
        for(int nt=0;nt<8;nt++){
            int kc=k0+nt*8+j2;
            long long tk0=ts[b*Ss+kc], tk1=ts[b*Ss+kc+1];
            float la0=fmaxf((float)(tq0-tk0)*(1.0f/60000.0f),0.0f);
            float lb0=fmaxf((float)(tq0-tk1)*(1.0f/60000.0f),0.0f);
            float la1=fmaxf((float)(tq1-tk0)*(1.0f/60000.0f),0.0f);
            float lb1=fmaxf((float)(tq1-tk1)*(1.0f/60000.0f),0.0f);
            float2 pb0=__half22float2(*(const __half2*)&pb0p[kc]);
            float2 pb1=__half22float2(*(const __half2*)&pb1p[kc]);
            // s/scale = s*(l+1)/(9l+8)
            sacc[nt][0]=sacc[nt][0]*__fdividef(la0+1.0f,9.0f*la0+8.0f)+pb0.x;
            sacc[nt][1]=sacc[nt][1]*__fdividef(lb0+1.0f,9.0f*lb0+8.0f)+pb0.y;
            sacc[nt][2]=sacc[nt][2]*__fdividef(la1+1.0f,9.0f*la1+8.0f)+pb1.x;
            sacc[nt][3]=sacc[nt][3]*__fdividef(lb1+1.0f,9.0f*lb1+8.0f)+pb1.y;
        }
        float tm0=-1e30f, tm1=-1e30f;
        #pragma unroll
        for(int nt=0;nt<8;nt++){
            tm0=fmaxf(tm0,fmaxf(sacc[nt][0],sacc[nt][1]));
            tm1=fmaxf(tm1,fmaxf(sacc[nt][2],sacc[nt][3]));
        }
        tm0=fmaxf(tm0,__shfl_xor_sync(0xffffffffu,tm0,1));
        tm0=fmaxf(tm0,__shfl_xor_sync(0xffffffffu,tm0,2));
        tm1=fmaxf(tm1,__shfl_xor_sync(0xffffffffu,tm1,1));
        tm1=fmaxf(tm1,__shfl_xor_sync(0xffffffffu,tm1,2));
        float mn0=fmaxf(m0_,tm0), mn1=fmaxf(m1_,tm1);
        float al0=__expf(m0_-mn0), al1=__expf(m1_-mn1);
        m0_=mn0; m1_=mn1;
        float s0=0.0f, s1=0.0f;
        #pragma unroll
        for(int nt=0;nt<8;nt++){
            sacc[nt][0]=__expf(sacc[nt][0]-mn0); s0+=sacc[nt][0];
            sacc[nt][1]=__expf(sacc[nt][1]-mn0); s0+=sacc[nt][1];
            sacc[nt][2]=__expf(sacc[nt][2]-mn1); s1+=sacc[nt][2];
            sacc[nt][3]=__expf(sacc[nt][3]-mn1); s1+=sacc[nt][3];
        }
        s0+=__shfl_xor_sync(0xffffffffu,s0,1); s0+=__shfl_xor_sync(0xffffffffu,s0,2);
        s1+=__shfl_xor_sync(0xffffffffu,s1,1); s1+=__shfl_xor_sync(0xffffffffu,s1,2);
        l0_=l0_*al0+s0; l1_=l1_*al1+s1;
        #pragma unroll
        for(int nt=0;nt<8;nt++){
            oacc[nt][0]*=al0; oacc[nt][1]*=al0;
            oacc[nt][2]*=al1; oacc[nt][3]*=al1;
        }
        uint32_t ph_[4][4];
        #pragma unroll
        for(int kt=0;kt<4;kt++){
            ph_[kt][0]=pack2(sacc[2*kt][0],  sacc[2*kt][1]);
            ph_[kt][1]=pack2(sacc[2*kt][2],  sacc[2*kt][3]);
            ph_[kt][2]=pack2(sacc[2*kt+1][0],sacc[2*kt+1][1]);
            ph_[kt][3]=pack2(sacc[2*kt+1][2],sacc[2*kt+1][3]);
        }
        #pragma unroll
        for(int kt=0;kt<4;kt++){
            #pragma unroll
            for(int dg=0;dg<4;dg++){
                int row=kt*16+((lane>>3)&1)*8+(lane&7);
                int ch_=dg*2+(lane>>4);
                uint32_t ad=stv+8192+row*128+((ch_^(row&7))*16);
                uint32_t vh_[4];
                LDSM4T(vh_[0],vh_[1],vh_[2],vh_[3],ad);
                #pragma unroll
                for(int p=0;p<2;p++)
                    MMA(oacc[dg*2+p],ph_[kt],vh_[p*2],vh_[p*2+1]);
            }
        }
    }
    float inv0=__fdividef(1.0f,l0_), inv1=__fdividef(1.0f,l1_);
    #pragma unroll
    for(int nt=0;nt<8;nt++){
        int dh=nt*8+j2;
        *(uint32_t*)&Ch[((size_t)(b*Ss+qi0))*Dd+h*DH+dh]=pack2(oacc[nt][0]*inv0,oacc[nt][1]*inv0);
        *(uint32_t*)&Ch[((size_t)(b*Ss+qi1))*Dd+h*DH+dh]=pack2(oacc[nt][2]*inv1,oacc[nt][3]*inv1);
    }
}

// ================= LayerNorm: fp32 out + fp16 hi out ============================
__global__ void ln_k(const float* __restrict__ in,const float* __restrict__ g,
                     const float* __restrict__ bt,float* __restrict__ out,
                     hf* __restrict__ oh){
    const size_t row=blockIdx.x;
    const int tid=threadIdx.x, lane=tid&31, wid=tid>>5;
    __shared__ float red[4];
    float4 v=*(const float4*)&in[row*Dd+tid*4];
    float s=v.x+v.y+v.z+v.w;
    #pragma unroll
    for(int o=16;o;o>>=1)s+=__shfl_xor_sync(0xffffffffu,s,o);
    if(lane==0)red[wid]=s;
    __syncthreads();
    float mu=(red[0]+red[1]+red[2]+red[3])*(1.0f/512.0f);
    __syncthreads();
    float dx=v.x-mu,dy=v.y-mu,dz=v.z-mu,dw=v.w-mu;
    float s2=dx*dx+dy*dy+dz*dz+dw*dw;
    #pragma unroll
    for(int o=16;o;o>>=1)s2+=__shfl_xor_sync(0xffffffffu,s2,o);
    if(lane==0)red[wid]=s2;
    __syncthreads();
    float var=(red[0]+red[1]+red[2]+red[3])*(1.0f/512.0f);
    float inv=rsqrtf(var+1e-12f);
    float4 gv=*(const float4*)&g[tid*4];
    float4 bv=*(const float4*)&bt[tid*4];
    float4 o;
    o.x=dx*inv*gv.x+bv.x; o.y=dy*inv*gv.y+bv.y;
    o.z=dz*inv*gv.z+bv.z; o.w=dw*inv*gv.w+bv.w;
    *(float4*)&out[row*Dd+tid*4]=o;
    ((uint32_t*)(oh+row*Dd+tid*4))[0]=pack2(o.x,o.y);
    ((uint32_t*)(oh+row*Dd+tid*4))[1]=pack2(o.z,o.w);
}

__global__ void split_k(const float* __restrict__ s,hf* __restrict__ hi,int n4){
    int i=blockIdx.x*256+threadIdx.x;
    if(i>=n4)return;
    float4 v=((const float4*)s)[i];
    ((uint32_t*)hi)[i*2+0]=pack2(v.x,v.y);
    ((uint32_t*)hi)[i*2+1]=pack2(v.z,v.w);
}

__global__ void wprep_k(const float* __restrict__ Wq,const float* __restrict__ Wk,
                        const float* __restrict__ Wv,const float* __restrict__ Wo,
                        const float* __restrict__ Wi,const float* __restrict__ Wf,
                        hf* __restrict__ wh){
    __shared__ float t[32][33];
    int tile=blockIdx.x;
    int l=tile/3072, r=tile%3072;
    const float* src; size_t off; int K,N;
    if(r<1024){
        int m=r>>8; r&=255;
        src=(m==0?Wq:m==1?Wk:m==2?Wv:Wo)+(size_t)l*Dd*Dd;
        off=(size_t)m*Dd*Dd; K=Dd; N=Dd;
    }else if(r<2048){
        r-=1024; src=Wi+(size_t)l*Dd*Ff; off=4*Dd*Dd; K=Dd; N=Ff;
    }else{
        r-=2048; src=Wf+(size_t)l*Ff*Dd; off=4*Dd*Dd+(size_t)Dd*Ff; K=Ff; N=Dd;
    }
    hf* dh=wh+(size_t)l*LWc+off;
    int ntk=K>>5;
    int n0=(r/ntk)*32, k0=(r%ntk)*32;
    int x=threadIdx.x, y0=threadIdx.y;
    for(int j=y0;j<32;j+=8) t[j][x]=src[(size_t)(k0+j)*N+n0+x];
    __syncthreads();
    for(int j=y0;j<32;j+=8)
        dh[(size_t)(n0+j)*K+k0+x]=__float2half_rn(t[x][j]);
}

__global__ void catb_k(const float* bq,const float* bk,const float* bv,float* o,
                       const float* pb,hf* pbh){
    int i=blockIdx.x*256+threadIdx.x;
    if(i<Ll*3*Dd){
        int l=i/(3*Dd), r=i%(3*Dd);
        o[i]= r<Dd ? bq[l*Dd+r] : (r<2*Dd ? bk[l*Dd+r-Dd] : bv[l*Dd+r-2*Dd]);
    }
    // pbias -> fp16 (2M elements, vectorized x4)
    int n4=(int)((size_t)Hh*Ss*Ss/4);
    for(int j=i;j<n4;j+=gridDim.x*256){
        float4 v=((const float4*)pb)[j];
        ((uint32_t*)pbh)[j*2+0]=pack2(v.x,v.y);
        ((uint32_t*)pbh)[j*2+1]=pack2(v.z,v.w);
    }
}

extern "C" void kernel_launch(void* const* d_in, const int* in_sizes, int n_in,
                              void* d_out, int out_size){
    const float* hidden=(const float*)d_in[0];
    const float* pbias=(const float*)d_in[1];
    const long long* ts=(const long long*)d_in[2];
    const float* Wq=(const float*)d_in[3];  const float* bq=(const float*)d_in[4];
    const float* Wk=(const float*)d_in[5];  const float* bk=(const float*)d_in[6];
    const float* Wv=(const float*)d_in[7];  const float* bv=(const float*)d_in[8];
    const float* Wo=(const float*)d_in[9];  const float* bo=(const float*)d_in[10];
    const float* l1g=(const float*)d_in[11];const float* l1b=(const float*)d_in[12];
    const float* Wi=(const float*)d_in[13]; const float* bi=(const float*)d_in[14];
    const float* Wf=(const float*)d_in[15]; const float* bfp=(const float*)d_in[16];
    const float* l2g=(const float*)d_in[17];const float* l2b=(const float*)d_in[18];

    float *px,*pattn,*ptmp,*pcatb;
    cudaGetSymbolAddress((void**)&px,g_x);     cudaGetSymbolAddress((void**)&pattn,g_attn);
    cudaGetSymbolAddress((void**)&ptmp,g_tmp); cudaGetSymbolAddress((void**)&pcatb,g_catb);
    hf *xh,*qkh,*ch,*ah,*fh,*wh,*pbh;
    cudaGetSymbolAddress((void**)&xh,g_xh);
    cudaGetSymbolAddress((void**)&qkh,g_qkvh);
    cudaGetSymbolAddress((void**)&ch,g_ch);
    cudaGetSymbolAddress((void**)&ah,g_ah);
    cudaGetSymbolAddress((void**)&fh,g_fh);
    cudaGetSymbolAddress((void**)&wh,g_wh);
    cudaGetSymbolAddress((void**)&pbh,g_pbh);

    cudaFuncSetAttribute(gemm_mma<0,false,2,512>, cudaFuncAttributeMaxDynamicSharedMemorySize,GSMEM);
    cudaFuncSetAttribute(gemm_mma<0,true,0,512>,  cudaFuncAttributeMaxDynamicSharedMemorySize,GSMEM);
    cudaFuncSetAttribute(gemm_mma<1,false,2,512>, cudaFuncAttributeMaxDynamicSharedMemorySize,GSMEM);
    cudaFuncSetAttribute(gemm_mma<0,true,0,2048>, cudaFuncAttributeMaxDynamicSharedMemorySize,GSMEM);
    cudaFuncSetAttribute(flash_k,cudaFuncAttributeMaxDynamicSharedMemorySize,FLSM);

    wprep_k<<<Ll*3072,dim3(32,8)>>>(Wq,Wk,Wv,Wo,Wi,Wf,wh);
    catb_k<<<512,256>>>(bq,bk,bv,pcatb,pbias,pbh);
    const int nD4=Mrows*Dd/4;
    split_k<<<(nD4+255)/256,256>>>(hidden,xh,nD4);

    const dim3 gDD(Dd/128,Mrows/128), gQKV(3*Dd/128,Mrows/128), gDF(Ff/128,Mrows/128);
    const float* X=hidden;
    for(int l=0;l<Ll;l++){
        hf* bh_=wh+(size_t)l*LWc;
        hf* wih=bh_+4*Dd*Dd;
        hf* wfh=wih+(size_t)Dd*Ff;

        gemm_mma<0,false,2,512><<<gQKV,256,GSMEM>>>(xh,bh_,pcatb+l*3*Dd,nullptr,nullptr,qkh,3*Dd);
        flash_k<<<dim3(4,Bb*Hh),256,FLSM>>>(qkh,pbh,ts,ch);

        gemm_mma<0,true,0,512><<<gDD,256,GSMEM>>>(ch,bh_+3*Dd*Dd,bo+l*Dd,X,ptmp,nullptr,Dd);
        ln_k<<<Mrows,128>>>(ptmp,l1g+l*Dd,l1b+l*Dd,pattn,ah);

        gemm_mma<1,false,2,512><<<gDF,256,GSMEM>>>(ah,wih,bi+l*Ff,nullptr,nullptr,fh,Ff);
        gemm_mma<0,true,0,2048><<<gDD,256,GSMEM>>>(fh,wfh,bfp+l*Dd,pattn,ptmp,nullptr,Dd);
        ln_k<<<Mrows,128>>>(ptmp,l2g+l*Dd,l2b+l*Dd,px,xh);
        X=px;
    }
    cudaMemcpyAsync(d_out,px,(size_t)Mrows*Dd*sizeof(float),cudaMemcpyDeviceToDevice,0);
}

// round 15
// speedup vs baseline: 6.0622x; 1.0049x over previous
#include <cuda_runtime.h>
#include <cuda_fp16.h>
#include <math.h>
#include <stdint.h>

#define Bb 32
#define Ss 512
#define Dd 512
#define Hh 8
#define Ff 2048
#define Ll 4
#define DH 64
#define Mrows (Bb*Ss)
#define LWc ((size_t)(4*Dd*Dd+2*Dd*Ff))

typedef __half hf;

__device__ float g_x[Mrows*Dd];
__device__ float g_attn[Mrows*Dd];
__device__ hf g_tmph[Mrows*Dd];
__device__ hf g_xh[Mrows*Dd];
__device__ hf g_qkvh[(size_t)Mrows*3*Dd];
__device__ hf g_ch[Mrows*Dd];
__device__ hf g_ah[Mrows*Dd];
__device__ hf g_fh[(size_t)Mrows*Ff];
__device__ hf g_wh[Ll*LWc];
__device__ hf g_pbh[(size_t)Hh*Ss*Ss];
__device__ float g_catb[Ll*3*Dd];

__device__ __forceinline__ float gelu_e(float x){return 0.5f*x*(1.0f+erff(x*0.70710678118654752f));}
__device__ __forceinline__ void cp16(uint32_t d,const void* s){
    asm volatile("cp.async.cg.shared.global [%0], [%1], 16;"::"r"(d),"l"(s));
}
#define CPC() asm volatile("cp.async.commit_group;":::"memory")
#define LDSM4(r0,r1,r2,r3,a) asm volatile("ldmatrix.sync.aligned.m8n8.x4.shared.b16 {%0,%1,%2,%3},[%4];":"=r"(r0),"=r"(r1),"=r"(r2),"=r"(r3):"r"(a))
#define LDSM4T(r0,r1,r2,r3,a) asm volatile("ldmatrix.sync.aligned.m8n8.x4.trans.shared.b16 {%0,%1,%2,%3},[%4];":"=r"(r0),"=r"(r1),"=r"(r2),"=r"(r3):"r"(a))
#define MMA(d,a,b0,b1) asm volatile( \
    "mma.sync.aligned.m16n8k16.row.col.f32.f16.f16.f32 {%0,%1,%2,%3},{%4,%5,%6,%7},{%8,%9},{%0,%1,%2,%3};" \
    :"+f"((d)[0]),"+f"((d)[1]),"+f"((d)[2]),"+f"((d)[3]) \
    :"r"((a)[0]),"r"((a)[1]),"r"((a)[2]),"r"((a)[3]),"r"(b0),"r"(b1))

__device__ __forceinline__ uint32_t pack2(float a,float b){
    __half2 H=__halves2half2(__float2half_rn(a),__float2half_rn(b));
    return *(uint32_t*)&H;
}

// ============== GEMM: pure fp16, BK=64, 3-stage =================================
#define STB2 32768
#define GSMEM (3*STB2)
__device__ __forceinline__ void load_stage(uint32_t st,int tid,
    const hf* Ah,const hf* Bh,int m0,int n0,int k0,int K){
    #pragma unroll
    for(int i=0;i<8;i++){
        int id=i*256+tid;
        int reg=id>>10, rid=id&1023, row=rid>>3, c=rid&7;
        const hf* src=reg? Bh+(size_t)(n0+row)*K+k0+c*8 : Ah+(size_t)(m0+row)*K+k0+c*8;
        cp16(st+reg*16384+row*128+((c^(row&7))*16),src);
    }
    CPC();
}

// OUT: 0=fp32, 2=fp16
template<int ACT, bool RES, int OUT, int KT>
__global__ void __launch_bounds__(256,2)
gemm_mma(const hf* __restrict__ Ah,const hf* __restrict__ Bh,
         const float* __restrict__ bias,const float* __restrict__ res,
         float* __restrict__ C,hf* __restrict__ Ch,
         int N){
    extern __shared__ char sm[];
    uint32_t sb=(uint32_t)__cvta_generic_to_shared(sm);
    const int tid=threadIdx.x, wid=tid>>5, lane=tid&31;
    const int n0=blockIdx.x*128, m0=blockIdx.y*128;
    const int wm=(wid>>2)*64, wn=(wid&3)*32;
    constexpr int chunks=KT>>6;
    float acc[4][4][4];
    #pragma unroll
    for(int i=0;i<4;i++)
        #pragma unroll
        for(int j=0;j<4;j++){acc[i][j][0]=0;acc[i][j][1]=0;acc[i][j][2]=0;acc[i][j][3]=0;}
    load_stage(sb,tid,Ah,Bh,m0,n0,0,KT);
    load_stage(sb+STB2,tid,Ah,Bh,m0,n0,64,KT);
    const int arow=lane&15, ah8=lane>>4;
    int s2=2;
    for(int c=0;c<chunks;c++){
        uint32_t st=sb+(c%3)*STB2;
        if(c<chunks-1) asm volatile("cp.async.wait_group 1;":::"memory");
        else           asm volatile("cp.async.wait_group 0;":::"memory");
        __syncthreads();
        if(c+2<chunks){
            load_stage(sb+s2*STB2,tid,Ah,Bh,m0,n0,(c+2)*64,KT);
            s2++; if(s2==3)s2=0;
        }
        #pragma unroll
        for(int s=0;s<4;s++){
            uint32_t bhf[2][4];
            #pragma unroll
            for(int nq=0;nq<2;nq++){
                int row=wn+nq*16+arow;
                uint32_t ad=st+16384+row*128+(((s*2+ah8)^(row&7))*16);
                LDSM4(bhf[nq][0],bhf[nq][1],bhf[nq][2],bhf[nq][3],ad);
            }
            #pragma unroll
            for(int mi=0;mi<4;mi++){
                uint32_t ahf[4];
                int row=wm+mi*16+arow;
                uint32_t ad=st+row*128+(((s*2+ah8)^(row&7))*16);
                LDSM4(ahf[0],ahf[1],ahf[2],ahf[3],ad);
                #pragma unroll
                for(int nq=0;nq<2;nq++)
                    #pragma unroll
                    for(int p=0;p<2;p++)
                        MMA(acc[mi][nq*2+p],ahf,bhf[nq][p],bhf[nq][p+2]);
            }
        }
    }
    const int r4=lane>>2, c2=(lane&3)*2;
    #pragma unroll
    for(int mi=0;mi<4;mi++)
        #pragma unroll
        for(int nt=0;nt<4;nt++){
            int col=n0+wn+nt*8+c2;
            float2 bv=*(const float2*)&bias[col];
            #pragma unroll
            for(int hr=0;hr<2;hr++){
                int row=m0+wm+mi*16+r4+hr*8;
                float2 o;
                o.x=acc[mi][nt][hr*2+0]+bv.x;
                o.y=acc[mi][nt][hr*2+1]+bv.y;
                if(RES){float2 rv=*(const float2*)&res[(size_t)row*N+col]; o.x+=rv.x;o.y+=rv.y;}
                if(ACT==1){o.x=gelu_e(o.x);o.y=gelu_e(o.y);}
                if(OUT==0) *(float2*)&C[(size_t)row*N+col]=o;
                else       *(uint32_t*)&Ch[(size_t)row*N+col]=pack2(o.x,o.y);
            }
        }
}

// ===== flash attention: fp16 operands, 3-stage KV ring, rational scale ==========
#define FLSM (16384 + 3*16384)
__global__ void __launch_bounds__(256,2)
flash_k(const hf* __restrict__ qkvh,
        const hf* __restrict__ pbh,const long long* __restrict__ ts,
        hf* __restrict__ Ch){
    extern __shared__ char sm[];
    uint32_t sb=(uint32_t)__cvta_generic_to_shared(sm);
    const int tid=threadIdx.x, wid=tid>>5, lane=tid&31;
    const int bh=blockIdx.y, b=bh>>3, h=bh&7;
    const int q0=blockIdx.x*128;
    const int wm=wid*16;
    const int arow=lane&15, ah8=lane>>4, r4=lane>>2, j2=(lane&3)*2;

    #pragma unroll
    for(int i=0;i<4;i++){
        int id=i*256+tid;
        int row=id>>3, c=id&7;
        const hf* src=qkvh+(size_t)(b*Ss+q0+row)*1536+h*DH+c*8;
        cp16(sb+row*128+((c^(row&7))*16),src);
    }
    CPC();

    auto loadkv=[&](int st,int k0){
        #pragma unroll
        for(int i=0;i<4;i++){
            int id=i*256+tid;
            int part=id>>9, rid=id&511, row=rid>>3, c=rid&7;
            int colb=part? (2*Dd+h*DH) : (Dd+h*DH);
            const hf* src=qkvh+(size_t)(b*Ss+k0+row)*1536+colb+c*8;
            cp16(sb+16384+st*16384+part*8192+row*128+((c^(row&7))*16),src);
        }
        CPC();
    };
    loadkv(0,0); loadkv(1,64);

    float m0_=-1e30f, m1_=-1e30f, l0_=0.0f, l1_=0.0f;
    float oacc[8][4];
    #pragma unroll
    for(int i=0;i<8;i++){oacc[i][0]=0;oacc[i][1]=0;oacc[i][2]=0;oacc[i][3]=0;}
    const long long tq0=ts[b*Ss+q0+wm+r4], tq1=ts[b*Ss+q0+wm+r4+8];
    const int qi0=q0+wm+r4, qi1=qi0+8;
    const hf* pb0p=pbh+(size_t)(h*Ss+qi0)*Ss;
    const hf* pb1p=pbh+(size_t)(h*Ss+qi1)*Ss;
    int s2=2;

    for(int t=0;t<8;t++){
        uint32_t stv=sb+16384+(t%3)*16384;
        if(t<7) asm volatile("cp.async.wait_group 1;":::"memory");
        else    asm volatile("cp.async.wait_group 0;":::"memory");
        __syncthreads();
        if(t+2<8){
            loadkv(s2,(t+2)*64);
            s2++; if(s2==3)s2=0;
        }

        float sacc[8][4];
        #pragma unroll
        for(int i=0;i<8;i++){sacc[i][0]=0;sacc[i][1]=0;sacc[i][2]=0;sacc[i][3]=0;}
        #pragma unroll
        for(int kt=0;kt<4;kt++){
            uint32_t qh_[4];
            {
                int row=wm+arow;
                uint32_t ad=sb+row*128+(((kt*2+ah8)^(row&7))*16);
                LDSM4(qh_[0],qh_[1],qh_[2],qh_[3],ad);
            }
            #pragma unroll
            for(int nq=0;nq<4;nq++){
                int row=nq*16+arow;
                uint32_t ad=stv+row*128+(((kt*2+ah8)^(row&7))*16);
                uint32_t kh_[4];
                LDSM4(kh_[0],kh_[1],kh_[2],kh_[3],ad);
                #pragma unroll
                for(int p=0;p<2;p++)
                    MMA(sacc[nq*2+p],qh_,kh_[p],kh_[p+2]);
            }
        }
        int k0=t*64;
        #pragma unroll
        for(int nt=0;nt<8;nt++){
            int kc=k0+nt*8+j2;
            long long tk0=ts[b*Ss+kc], tk1=ts[b*Ss+kc+1];
            float la0=fmaxf((float)(tq0-tk0)*(1.0f/60000.0f),0.0f);
            float lb0=fmaxf((float)(tq0-tk1)*(1.0f/60000.0f),0.0f);
            float la1=fmaxf((float)(tq1-tk0)*(1.0f/60000.0f),0.0f);
            float lb1=fmaxf((float)(tq1-tk1)*(1.0f/60000.0f),0.0f);
            float2 pb0=__half22float2(*(const __half2*)&pb0p[kc]);
            float2 pb1=__half22float2(*(const __half2*)&pb1p[kc]);
            sacc[nt][0]=sacc[nt][0]*__fdividef(la0+1.0f,9.0f*la0+8.0f)+pb0.x;
            sacc[nt][1]=sacc[nt][1]*__fdividef(lb0+1.0f,9.0f*lb0+8.0f)+pb0.y;
            sacc[nt][2]=sacc[nt][2]*__fdividef(la1+1.0f,9.0f*la1+8.0f)+pb1.x;
            sacc[nt][3]=sacc[nt][3]*__fdividef(lb1+1.0f,9.0f*lb1+8.0f)+pb1.y;
        }
        float tm0=-1e30f, tm1=-1e30f;
        #pragma unroll
        for(int nt=0;nt<8;nt++){
            tm0=fmaxf(tm0,fmaxf(sacc[nt][0],sacc[nt][1]));
            tm1=fmaxf(tm1,fmaxf(sacc[nt][2],sacc[nt][3]));
        }
        tm0=fmaxf(tm0,__shfl_xor_sync(0xffffffffu,tm0,1));
        tm0=fmaxf(tm0,__shfl_xor_sync(0xffffffffu,tm0,2));
        tm1=fmaxf(tm1,__shfl_xor_sync(0xffffffffu,tm1,1));
        tm1=fmaxf(tm1,__shfl_xor_sync(0xffffffffu,tm1,2));
        float mn0=fmaxf(m0_,tm0), mn1=fmaxf(m1_,tm1);
        float al0=__expf(m0_-mn0), al1=__expf(m1_-mn1);
        m0_=mn0; m1_=mn1;
        float s0=0.0f, s1=0.0f;
        #pragma unroll
        for(int nt=0;nt<8;nt++){
            sacc[nt][0]=__expf(sacc[nt][0]-mn0); s0+=sacc[nt][0];
            sacc[nt][1]=__expf(sacc[nt][1]-mn0); s0+=sacc[nt][1];
            sacc[nt][2]=__expf(sacc[nt][2]-mn1); s1+=sacc[nt][2];
            sacc[nt][3]=__expf(sacc[nt][3]-mn1); s1+=sacc[nt][3];
        }
        s0+=__shfl_xor_sync(0xffffffffu,s0,1); s0+=__shfl_xor_sync(0xffffffffu,s0,2);
        s1+=__shfl_xor_sync(0xffffffffu,s1,1); s1+=__shfl_xor_sync(0xffffffffu,s1,2);
        l0_=l0_*al0+s0; l1_=l1_*al1+s1;
        #pragma unroll
        for(int nt=0;nt<8;nt++){
            oacc[nt][0]*=al0; oacc[nt][1]*=al0;
            oacc[nt][2]*=al1; oacc[nt][3]*=al1;
        }
        uint32_t ph_[4][4];
        #pragma unroll
        for(int kt=0;kt<4;kt++){
            ph_[kt][0]=pack2(sacc[2*kt][0],  sacc[2*kt][1]);
            ph_[kt][1]=pack2(sacc[2*kt][2],  sacc[2*kt][3]);
            ph_[kt][2]=pack2(sacc[2*kt+1][0],sacc[2*kt+1][1]);
            ph_[kt][3]=pack2(sacc[2*kt+1][2],sacc[2*kt+1][3]);
        }
        #pragma unroll
        for(int kt=0;kt<4;kt++){
            #pragma unroll
            for(int dg=0;dg<4;dg++){
                int row=kt*16+((lane>>3)&1)*8+(lane&7);
                int ch_=dg*2+(lane>>4);
                uint32_t ad=stv+8192+row*128+((ch_^(row&7))*16);
                uint32_t vh_[4];
                LDSM4T(vh_[0],vh_[1],vh_[2],vh_[3],ad);
                #pragma unroll
                for(int p=0;p<2;p++)
                    MMA(oacc[dg*2+p],ph_[kt],vh_[p*2],vh_[p*2+1]);
            }
        }
    }
    float inv0=__fdividef(1.0f,l0_), inv1=__fdividef(1.0f,l1_);
    #pragma unroll
    for(int nt=0;nt<8;nt++){
        int dh=nt*8+j2;
        *(uint32_t*)&Ch[((size_t)(b*Ss+qi0))*Dd+h*DH+dh]=pack2(oacc[nt][0]*inv0,oacc[nt][1]*inv0);
        *(uint32_t*)&Ch[((size_t)(b*Ss+qi1))*Dd+h*DH+dh]=pack2(oacc[nt][2]*inv1,oacc[nt][3]*inv1);
    }
}

// ================= LayerNorm: fp16 in -> fp32 out + fp16 out ====================
__global__ void ln_k(const hf* __restrict__ in,const float* __restrict__ g,
                     const float* __restrict__ bt,float* __restrict__ out,
                     hf* __restrict__ oh){
    const size_t row=blockIdx.x;
    const int tid=threadIdx.x, lane=tid&31, wid=tid>>5;
    __shared__ float red[4];
    uint2 raw=*(const uint2*)&in[row*Dd+tid*4];
    float2 f01=__half22float2(*(__half2*)&raw.x);
    float2 f23=__half22float2(*(__half2*)&raw.y);
    float4 v=make_float4(f01.x,f01.y,f23.x,f23.y);
    float s=v.x+v.y+v.z+v.w;
    #pragma unroll
    for(int o=16;o;o>>=1)s+=__shfl_xor_sync(0xffffffffu,s,o);
    if(lane==0)red[wid]=s;
    __syncthreads();
    float mu=(red[0]+red[1]+red[2]+red[3])*(1.0f/512.0f);
    __syncthreads();
    float dx=v.x-mu,dy=v.y-mu,dz=v.z-mu,dw=v.w-mu;
    float s2=dx*dx+dy*dy+dz*dz+dw*dw;
    #pragma unroll
    for(int o=16;o;o>>=1)s2+=__shfl_xor_sync(0xffffffffu,s2,o);
    if(lane==0)red[wid]=s2;
    __syncthreads();
    float var=(red[0]+red[1]+red[2]+red[3])*(1.0f/512.0f);
    float inv=rsqrtf(var+1e-12f);
    float4 gv=*(const float4*)&g[tid*4];
    float4 bv=*(const float4*)&bt[tid*4];
    float4 o;
    o.x=dx*inv*gv.x+bv.x; o.y=dy*inv*gv.y+bv.y;
    o.z=dz*inv*gv.z+bv.z; o.w=dw*inv*gv.w+bv.w;
    *(float4*)&out[row*Dd+tid*4]=o;
    ((uint32_t*)(oh+row*Dd+tid*4))[0]=pack2(o.x,o.y);
    ((uint32_t*)(oh+row*Dd+tid*4))[1]=pack2(o.z,o.w);
}

__global__ void split_k(const float* __restrict__ s,hf* __restrict__ hi,int n4){
    int i=blockIdx.x*256+threadIdx.x;
    if(i>=n4)return;
    float4 v=((const float4*)s)[i];
    ((uint32_t*)hi)[i*2+0]=pack2(v.x,v.y);
    ((uint32_t*)hi)[i*2+1]=pack2(v.z,v.w);
}

__global__ void wprep_k(const float* __restrict__ Wq,const float* __restrict__ Wk,
                        const float* __restrict__ Wv,const float* __restrict__ Wo,
                        const float* __restrict__ Wi,const float* __restrict__ Wf,
                        hf* __restrict__ wh){
    __shared__ float t[32][33];
    int tile=blockIdx.x;
    int l=tile/3072, r=tile%3072;
    const float* src; size_t off; int K,N;
    if(r<1024){
        int m=r>>8; r&=255;
        src=(m==0?Wq:m==1?Wk:m==2?Wv:Wo)+(size_t)l*Dd*Dd;
        off=(size_t)m*Dd*Dd; K=Dd; N=Dd;
    }else if(r<2048){
        r-=1024; src=Wi+(size_t)l*Dd*Ff; off=4*Dd*Dd; K=Dd; N=Ff;
    }else{
        r-=2048; src=Wf+(size_t)l*Ff*Dd; off=4*Dd*Dd+(size_t)Dd*Ff; K=Ff; N=Dd;
    }
    hf* dh=wh+(size_t)l*LWc+off;
    int ntk=K>>5;
    int n0=(r/ntk)*32, k0=(r%ntk)*32;
    int x=threadIdx.x, y0=threadIdx.y;
    for(int j=y0;j<32;j+=8) t[j][x]=src[(size_t)(k0+j)*N+n0+x];
    __syncthreads();
    for(int j=y0;j<32;j+=8)
        dh[(size_t)(n0+j)*K+k0+x]=__float2half_rn(t[x][j]);
}

__global__ void catb_k(const float* bq,const float* bk,const float* bv,float* o,
                       const float* pb,hf* pbh){
    int i=blockIdx.x*256+threadIdx.x;
    if(i<Ll*3*Dd){
        int l=i/(3*Dd), r=i%(3*Dd);
        o[i]= r<Dd ? bq[l*Dd+r] : (r<2*Dd ? bk[l*Dd+r-Dd] : bv[l*Dd+r-2*Dd]);
    }
    int n4=(int)((size_t)Hh*Ss*Ss/4);
    for(int j=i;j<n4;j+=gridDim.x*256){
        float4 v=((const float4*)pb)[j];
        ((uint32_t*)pbh)[j*2+0]=pack2(v.x,v.y);
        ((uint32_t*)pbh)[j*2+1]=pack2(v.z,v.w);
    }
}

extern "C" void kernel_launch(void* const* d_in, const int* in_sizes, int n_in,
                              void* d_out, int out_size){
    const float* hidden=(const float*)d_in[0];
    const float* pbias=(const float*)d_in[1];
    const long long* ts=(const long long*)d_in[2];
    const float* Wq=(const float*)d_in[3];  const float* bq=(const float*)d_in[4];
    const float* Wk=(const float*)d_in[5];  const float* bk=(const float*)d_in[6];
    const float* Wv=(const float*)d_in[7];  const float* bv=(const float*)d_in[8];
    const float* Wo=(const float*)d_in[9];  const float* bo=(const float*)d_in[10];
    const float* l1g=(const float*)d_in[11];const float* l1b=(const float*)d_in[12];
    const float* Wi=(const float*)d_in[13]; const float* bi=(const float*)d_in[14];
    const float* Wf=(const float*)d_in[15]; const float* bfp=(const float*)d_in[16];
    const float* l2g=(const float*)d_in[17];const float* l2b=(const float*)d_in[18];

    float *px,*pattn,*pcatb;
    cudaGetSymbolAddress((void**)&px,g_x);     cudaGetSymbolAddress((void**)&pattn,g_attn);
    cudaGetSymbolAddress((void**)&pcatb,g_catb);
    hf *xh,*qkh,*ch,*ah,*fh,*wh,*pbh,*tmph;
    cudaGetSymbolAddress((void**)&xh,g_xh);
    cudaGetSymbolAddress((void**)&qkh,g_qkvh);
    cudaGetSymbolAddress((void**)&ch,g_ch);
    cudaGetSymbolAddress((void**)&ah,g_ah);
    cudaGetSymbolAddress((void**)&fh,g_fh);
    cudaGetSymbolAddress((void**)&wh,g_wh);
    cudaGetSymbolAddress((void**)&pbh,g_pbh);
    cudaGetSymbolAddress((void**)&tmph,g_tmph);

    cudaFuncSetAttribute(gemm_mma<0,false,2,512>, cudaFuncAttributeMaxDynamicSharedMemorySize,GSMEM);
    cudaFuncSetAttribute(gemm_mma<0,true,2,512>,  cudaFuncAttributeMaxDynamicSharedMemorySize,GSMEM);
    cudaFuncSetAttribute(gemm_mma<1,false,2,512>, cudaFuncAttributeMaxDynamicSharedMemorySize,GSMEM);
    cudaFuncSetAttribute(gemm_mma<0,true,2,2048>, cudaFuncAttributeMaxDynamicSharedMemorySize,GSMEM);
    cudaFuncSetAttribute(flash_k,cudaFuncAttributeMaxDynamicSharedMemorySize,FLSM);

    wprep_k<<<Ll*3072,dim3(32,8)>>>(Wq,Wk,Wv,Wo,Wi,Wf,wh);
    catb_k<<<512,256>>>(bq,bk,bv,pcatb,pbias,pbh);
    const int nD4=Mrows*Dd/4;
    split_k<<<(nD4+255)/256,256>>>(hidden,xh,nD4);

    const dim3 gDD(Dd/128,Mrows/128), gQKV(3*Dd/128,Mrows/128), gDF(Ff/128,Mrows/128);
    const float* X=hidden;
    for(int l=0;l<Ll;l++){
        hf* bh_=wh+(size_t)l*LWc;
        hf* wih=bh_+4*Dd*Dd;
        hf* wfh=wih+(size_t)Dd*Ff;
        float* xout=(l==Ll-1)? (float*)d_out : px;

        gemm_mma<0,false,2,512><<<gQKV,256,GSMEM>>>(xh,bh_,pcatb+l*3*Dd,nullptr,nullptr,qkh,3*Dd);
        flash_k<<<dim3(4,Bb*Hh),256,FLSM>>>(qkh,pbh,ts,ch);

        gemm_mma<0,true,2,512><<<gDD,256,GSMEM>>>(ch,bh_+3*Dd*Dd,bo+l*Dd,X,nullptr,tmph,Dd);
        ln_k<<<Mrows,128>>>(tmph,l1g+l*Dd,l1b+l*Dd,pattn,ah);

        gemm_mma<1,false,2,512><<<gDF,256,GSMEM>>>(ah,wih,bi+l*Ff,nullptr,nullptr,fh,Ff);
        gemm_mma<0,true,2,2048><<<gDD,256,GSMEM>>>(fh,wfh,bfp+l*Dd,pattn,nullptr,tmph,Dd);
        ln_k<<<Mrows,128>>>(tmph,l2g+l*Dd,l2b+l*Dd,xout,xh);
        X=xout;
    }
}